// round 3
// baseline (speedup 1.0000x reference)
#include <cuda_runtime.h>
#include <cstdint>

// Problem constants (fixed by reference_code)
#define NMAX 50000
#define EMAX 800000
#define F    256
#define NCLS 40

// ---------------- scratch (static device globals; no runtime allocation) ----
__device__ int   g_is64;                 // 1 if edge_index is int64, 0 if int32
__device__ int   g_deg[NMAX];
__device__ int   g_cursor[NMAX];
__device__ int   g_rowptr[NMAX + 1];
__device__ int   g_col[EMAX];
__device__ float g_invdeg[NMAX];
__device__ __align__(16) float g_agg[(size_t)NMAX * F];  // agg scratch (both layers)
__device__ __align__(16) float g_h[(size_t)NMAX * F];    // relu(layer1 output)

// ---------------- edge dtype detection -------------------------------------
// int64 little-endian values < 2^31  =>  odd int32 slots are all zero.
// int32 random values in [0, 50000)  =>  essentially impossible that 256
// consecutive odd slots are all zero.
__global__ void detect_kernel(const int* __restrict__ v) {
    __shared__ int any_nonzero;
    if (threadIdx.x == 0) any_nonzero = 0;
    __syncthreads();
    int idx = 2 * threadIdx.x + 1;          // odd slots 1,3,...,511
    if (v[idx] != 0) atomicOr(&any_nonzero, 1);
    __syncthreads();
    if (threadIdx.x == 0) g_is64 = (any_nonzero == 0) ? 1 : 0;
}

__device__ __forceinline__ int edge_at(const void* edges, size_t idx) {
    if (g_is64) return (int)((const long long*)edges)[idx];
    return ((const int*)edges)[idx];
}

// ---------------- CSR build ------------------------------------------------
__global__ void zero_counts_kernel(int n) {
    int i = blockIdx.x * blockDim.x + threadIdx.x;
    if (i < n) { g_deg[i] = 0; g_cursor[i] = 0; }
}

__global__ void degree_kernel(const void* __restrict__ edges, int E) {
    int e = blockIdx.x * blockDim.x + threadIdx.x;
    if (e < E) {
        int d = edge_at(edges, (size_t)E + e);   // dst row
        atomicAdd(&g_deg[d], 1);
    }
}

// single-block exclusive prefix sum over g_deg -> g_rowptr, plus 1/max(deg,1)
__global__ void scan_kernel(int n) {
    __shared__ int psum[1024];
    int tid = threadIdx.x;
    int chunk = (n + 1023) / 1024;
    int start = tid * chunk;
    int end = start + chunk; if (end > n) end = n; if (start > n) start = n;
    int s = 0;
    for (int i = start; i < end; i++) s += g_deg[i];
    psum[tid] = s;
    __syncthreads();
    for (int off = 1; off < 1024; off <<= 1) {
        int v = (tid >= off) ? psum[tid - off] : 0;
        __syncthreads();
        psum[tid] += v;
        __syncthreads();
    }
    int run = (tid > 0) ? psum[tid - 1] : 0;
    for (int i = start; i < end; i++) {
        g_rowptr[i] = run;
        int d = g_deg[i];
        run += d;
        g_invdeg[i] = 1.0f / (float)(d > 0 ? d : 1);
    }
    if (tid == 1023) g_rowptr[n] = run;   // == E
}

__global__ void scatter_kernel(const void* __restrict__ edges, int E) {
    int e = blockIdx.x * blockDim.x + threadIdx.x;
    if (e < E) {
        int srcv = edge_at(edges, e);
        int d    = edge_at(edges, (size_t)E + e);
        int p = atomicAdd(&g_cursor[d], 1);
        g_col[g_rowptr[d] + p] = srcv;
    }
}

// ---------------- mean aggregation: g_agg[i] = inv_deg[i] * sum_{j in N(i)} feat[j]
// FROM_H=false: feat = x param. FROM_H=true: feat = g_h (device symbol).
// blockDim = (32, 8): one warp per node, lanes cover 256 feats as 2x float4
template <bool FROM_H>
__global__ void aggregate_kernel(const float* __restrict__ feat_in, int n) {
    int node = blockIdx.x * blockDim.y + threadIdx.y;
    if (node >= n) return;
    int lane = threadIdx.x;
    const float* feat = FROM_H ? (const float*)g_h : feat_in;
    int beg = g_rowptr[node], end = g_rowptr[node + 1];
    float4 acc0 = make_float4(0.f, 0.f, 0.f, 0.f);
    float4 acc1 = make_float4(0.f, 0.f, 0.f, 0.f);
    for (int e = beg; e < end; e++) {
        const float4* r = (const float4*)&feat[(size_t)g_col[e] * F];
        float4 a = r[lane];
        float4 b = r[lane + 32];
        acc0.x += a.x; acc0.y += a.y; acc0.z += a.z; acc0.w += a.w;
        acc1.x += b.x; acc1.y += b.y; acc1.z += b.z; acc1.w += b.w;
    }
    float s = g_invdeg[node];
    float4* o = (float4*)&g_agg[(size_t)node * F];
    o[lane]      = make_float4(acc0.x * s, acc0.y * s, acc0.z * s, acc0.w * s);
    o[lane + 32] = make_float4(acc1.x * s, acc1.y * s, acc1.z * s, acc1.w * s);
}

// ---------------- GEMM1: g_h = relu(g_agg*B0^T + x*B1^T + bias0 + bias1)
// A0 = g_agg, A1 = x (param): [M,256]; B0,B1: [256,256] row-major (out x in)
// Tiles: BM=128, BN=64, BK=16; 256 threads; 8x4 per-thread microtile.
__global__ void gemm_fused_relu_kernel(const float* __restrict__ A1,
                                       const float* __restrict__ B0,
                                       const float* __restrict__ B1,
                                       const float* __restrict__ bias0,
                                       const float* __restrict__ bias1,
                                       int M) {
    const int BM = 128, BN = 64, BK = 16, TM = 8, TN = 4;
    __shared__ __align__(16) float As[BK][BM];
    __shared__ __align__(16) float Bs[BK][BN];
    int bm = blockIdx.x * BM;
    int bn = blockIdx.y * BN;
    int tid = threadIdx.x;
    int ty = tid >> 4;      // 0..15 -> M
    int tx = tid & 15;      // 0..15 -> N

    float acc[TM][TN];
#pragma unroll
    for (int i = 0; i < TM; i++)
#pragma unroll
        for (int j = 0; j < TN; j++) acc[i][j] = 0.f;

#pragma unroll 1
    for (int s = 0; s < 2; s++) {
        const float* A = s ? A1 : (const float*)g_agg;
        const float* B = s ? B1 : B0;
#pragma unroll 1
        for (int k0 = 0; k0 < F; k0 += BK) {
            // A tile: 128x16 = 512 float4, 2 per thread (transposed store)
#pragma unroll
            for (int it = 0; it < 2; it++) {
                int idx = tid + it * 256;
                int r = idx >> 2;
                int c4 = idx & 3;
                int grow = bm + r;
                float4 v = make_float4(0.f, 0.f, 0.f, 0.f);
                if (grow < M) v = *(const float4*)&A[(size_t)grow * F + k0 + c4 * 4];
                As[c4 * 4 + 0][r] = v.x;
                As[c4 * 4 + 1][r] = v.y;
                As[c4 * 4 + 2][r] = v.z;
                As[c4 * 4 + 3][r] = v.w;
            }
            // B tile: 64x16 = 256 float4, 1 per thread (transposed store)
            {
                int r = tid >> 2;
                int c4 = tid & 3;
                float4 v = *(const float4*)&B[(size_t)(bn + r) * F + k0 + c4 * 4];
                Bs[c4 * 4 + 0][r] = v.x;
                Bs[c4 * 4 + 1][r] = v.y;
                Bs[c4 * 4 + 2][r] = v.z;
                Bs[c4 * 4 + 3][r] = v.w;
            }
            __syncthreads();
#pragma unroll
            for (int k = 0; k < BK; k++) {
                float4 a0 = *(const float4*)&As[k][ty * TM];
                float4 a1 = *(const float4*)&As[k][ty * TM + 4];
                float4 bv = *(const float4*)&Bs[k][tx * TN];
                float a[TM] = {a0.x, a0.y, a0.z, a0.w, a1.x, a1.y, a1.z, a1.w};
                float b[TN] = {bv.x, bv.y, bv.z, bv.w};
#pragma unroll
                for (int i = 0; i < TM; i++)
#pragma unroll
                    for (int j = 0; j < TN; j++) acc[i][j] += a[i] * b[j];
            }
            __syncthreads();
        }
    }
    // epilogue: bias + relu -> g_h
#pragma unroll
    for (int j = 0; j < TN; j++) {
        int gc = bn + tx * TN + j;
        float bb = bias0[gc] + bias1[gc];
#pragma unroll
        for (int i = 0; i < TM; i++) {
            int gr = bm + ty * TM + i;
            if (gr < M) {
                float v = acc[i][j] + bb;
                g_h[(size_t)gr * F + gc] = fmaxf(v, 0.f);
            }
        }
    }
}

// ---------------- GEMM2: out = g_agg*B0^T + g_h*B1^T + bias0 + bias1  (N=40)
// BM=128, BN=40, BK=32; 256 threads; per-thread 4x5 microtile.
__global__ void gemm_out_kernel(const float* __restrict__ B0,
                                const float* __restrict__ B1,
                                const float* __restrict__ bias0,
                                const float* __restrict__ bias1,
                                float* __restrict__ C, int M) {
    const int BM = 128, BK = 32, TM = 4, TN = 5;
    __shared__ __align__(16) float As[BK][BM];
    __shared__ __align__(16) float Bs[BK][NCLS];
    int bm = blockIdx.x * BM;
    int tid = threadIdx.x;
    int ty = tid >> 3;      // 0..31 -> M
    int tx = tid & 7;       // 0..7  -> N (8*5 = 40)

    float acc[TM][TN];
#pragma unroll
    for (int i = 0; i < TM; i++)
#pragma unroll
        for (int j = 0; j < TN; j++) acc[i][j] = 0.f;

#pragma unroll 1
    for (int s = 0; s < 2; s++) {
        const float* A = s ? (const float*)g_h : (const float*)g_agg;
        const float* B = s ? B1 : B0;
#pragma unroll 1
        for (int k0 = 0; k0 < F; k0 += BK) {
            // A tile: 128x32 = 1024 float4, 4 per thread
#pragma unroll
            for (int it = 0; it < 4; it++) {
                int idx = tid + it * 256;
                int r = idx >> 3;
                int c4 = idx & 7;
                int grow = bm + r;
                float4 v = make_float4(0.f, 0.f, 0.f, 0.f);
                if (grow < M) v = *(const float4*)&A[(size_t)grow * F + k0 + c4 * 4];
                As[c4 * 4 + 0][r] = v.x;
                As[c4 * 4 + 1][r] = v.y;
                As[c4 * 4 + 2][r] = v.z;
                As[c4 * 4 + 3][r] = v.w;
            }
            // B tile: 40x32 = 320 float4
            for (int idx = tid; idx < NCLS * BK / 4; idx += 256) {
                int r = idx >> 3;     // 0..39
                int c4 = idx & 7;
                float4 v = *(const float4*)&B[(size_t)r * F + k0 + c4 * 4];
                Bs[c4 * 4 + 0][r] = v.x;
                Bs[c4 * 4 + 1][r] = v.y;
                Bs[c4 * 4 + 2][r] = v.z;
                Bs[c4 * 4 + 3][r] = v.w;
            }
            __syncthreads();
#pragma unroll
            for (int k = 0; k < BK; k++) {
                float4 av4 = *(const float4*)&As[k][ty * TM];
                float a[TM] = {av4.x, av4.y, av4.z, av4.w};
                float b[TN];
#pragma unroll
                for (int j = 0; j < TN; j++) b[j] = Bs[k][tx * TN + j];
#pragma unroll
                for (int i = 0; i < TM; i++)
#pragma unroll
                    for (int j = 0; j < TN; j++) acc[i][j] += a[i] * b[j];
            }
            __syncthreads();
        }
    }
#pragma unroll
    for (int j = 0; j < TN; j++) {
        int gc = tx * TN + j;
        float bb = bias0[gc] + bias1[gc];
#pragma unroll
        for (int i = 0; i < TM; i++) {
            int gr = bm + ty * TM + i;
            if (gr < M) C[(size_t)gr * NCLS + gc] = acc[i][j] + bb;
        }
    }
}

// ---------------- launch --------------------------------------------------
extern "C" void kernel_launch(void* const* d_in, const int* in_sizes, int n_in,
                              void* d_out, int out_size) {
    const float* x     = (const float*)d_in[0];
    const void*  edges = (const void*)d_in[1];
    const float* w1_l = (const float*)d_in[2];
    const float* b1_l = (const float*)d_in[3];
    const float* w1_r = (const float*)d_in[4];
    const float* b1_r = (const float*)d_in[5];
    const float* w2_l = (const float*)d_in[6];
    const float* b2_l = (const float*)d_in[7];
    const float* w2_r = (const float*)d_in[8];
    const float* b2_r = (const float*)d_in[9];
    float* out = (float*)d_out;

    int N = in_sizes[0] / F;
    int E = in_sizes[1] / 2;

    // dtype probe + CSR build
    detect_kernel<<<1, 256>>>((const int*)edges);
    zero_counts_kernel<<<(N + 255) / 256, 256>>>(N);
    degree_kernel<<<(E + 255) / 256, 256>>>(edges, E);
    scan_kernel<<<1, 1024>>>(N);
    scatter_kernel<<<(E + 255) / 256, 256>>>(edges, E);

    dim3 aggBlock(32, 8);
    int aggGrid = (N + 7) / 8;

    // Layer 1
    aggregate_kernel<false><<<aggGrid, aggBlock>>>(x, N);
    {
        dim3 grid((N + 127) / 128, F / 64);
        gemm_fused_relu_kernel<<<grid, 256>>>(x, w1_l, w1_r, b1_l, b1_r, N);
    }

    // Layer 2
    aggregate_kernel<true><<<aggGrid, aggBlock>>>(nullptr, N);
    gemm_out_kernel<<<(N + 127) / 128, 256>>>(w2_l, w2_r, b2_l, b2_r, out, N);
}

// round 4
// speedup vs baseline: 1.1173x; 1.1173x over previous
#include <cuda_runtime.h>
#include <cstdint>

// Problem constants (fixed by reference_code)
#define NMAX 50000
#define EMAX 800000
#define F    256
#define NCLS 40
#define SCAN_TILE 1024
#define NBLK_MAX  64          // ceil(NMAX/SCAN_TILE) = 49 <= 64

// ---------------- scratch (static device globals; no runtime allocation) ----
__device__ int   g_is64;                 // 1 if edge_index is int64, 0 if int32
__device__ int   g_deg[NMAX];
__device__ int   g_cursor[NMAX];
__device__ int   g_rowptr[NMAX + 1];
__device__ int   g_col[EMAX];
__device__ int   g_excl[NMAX];           // within-block exclusive prefix
__device__ int   g_blocksum[NBLK_MAX];   // per-block degree totals
__device__ int   g_blockoff[NBLK_MAX];   // exclusive scan of block totals
__device__ float g_invdeg[NMAX];
__device__ __align__(16) float g_agg[(size_t)NMAX * F];  // agg scratch (both layers)
__device__ __align__(16) float g_h[(size_t)NMAX * F];    // relu(layer1 output)

// ---------------- edge dtype detection -------------------------------------
// int64 little-endian values < 2^31  =>  odd int32 slots are all zero.
__global__ void detect_kernel(const int* __restrict__ v) {
    __shared__ int any_nonzero;
    if (threadIdx.x == 0) any_nonzero = 0;
    __syncthreads();
    int idx = 2 * threadIdx.x + 1;          // odd slots 1,3,...,511
    if (v[idx] != 0) atomicOr(&any_nonzero, 1);
    __syncthreads();
    if (threadIdx.x == 0) g_is64 = (any_nonzero == 0) ? 1 : 0;
}

__device__ __forceinline__ int edge_at(const void* edges, size_t idx) {
    if (g_is64) return (int)((const long long*)edges)[idx];
    return ((const int*)edges)[idx];
}

// ---------------- CSR build ------------------------------------------------
__global__ void zero_counts_kernel(int n) {
    int i = blockIdx.x * blockDim.x + threadIdx.x;
    if (i < n) { g_deg[i] = 0; g_cursor[i] = 0; }
}

__global__ void degree_kernel(const void* __restrict__ edges, int E) {
    int e = blockIdx.x * blockDim.x + threadIdx.x;
    if (e < E) {
        int d = edge_at(edges, (size_t)E + e);   // dst row
        atomicAdd(&g_deg[d], 1);
    }
}

// Block-wide inclusive scan of one value per thread; returns inclusive prefix.
// Also leaves the block total in *total (valid for all threads).
__device__ __forceinline__ int block_incl_scan(int d, int* total) {
    __shared__ int wsum[32];
    int lane = threadIdx.x & 31, wid = threadIdx.x >> 5;
    int v = d;
#pragma unroll
    for (int o = 1; o < 32; o <<= 1) {
        int t = __shfl_up_sync(0xffffffffu, v, o);
        if (lane >= o) v += t;
    }
    if (lane == 31) wsum[wid] = v;
    __syncthreads();
    if (wid == 0) {
        int w = wsum[lane];
#pragma unroll
        for (int o = 1; o < 32; o <<= 1) {
            int t = __shfl_up_sync(0xffffffffu, w, o);
            if (lane >= o) w += t;
        }
        wsum[lane] = w;
    }
    __syncthreads();
    int incl = v + (wid > 0 ? wsum[wid - 1] : 0);
    *total = wsum[31];
    __syncthreads();   // protect wsum reuse across calls
    return incl;
}

// Phase 1: per-tile scan of g_deg (coalesced), store exclusive prefix + block sum
__global__ void scan_partial_kernel(int n) {
    int i = blockIdx.x * SCAN_TILE + threadIdx.x;
    int d = (i < n) ? g_deg[i] : 0;
    int total;
    int incl = block_incl_scan(d, &total);
    if (i < n) g_excl[i] = incl - d;
    if (threadIdx.x == 0) g_blocksum[blockIdx.x] = total;
}

// Phase 2: scan the block sums (nb <= 64, single block)
__global__ void scan_blocks_kernel(int nb) {
    int d = (threadIdx.x < nb) ? g_blocksum[threadIdx.x] : 0;
    int total;
    int incl = block_incl_scan(d, &total);
    if (threadIdx.x < nb) g_blockoff[threadIdx.x] = incl - d;
}

// Phase 3: emit rowptr + invdeg
__global__ void scan_emit_kernel(int n, int E) {
    int i = blockIdx.x * SCAN_TILE + threadIdx.x;
    if (i < n) {
        int rp = g_blockoff[blockIdx.x] + g_excl[i];
        g_rowptr[i] = rp;
        int d = g_deg[i];
        g_invdeg[i] = 1.0f / (float)(d > 0 ? d : 1);
        if (i == n - 1) g_rowptr[n] = E;
    }
}

__global__ void scatter_kernel(const void* __restrict__ edges, int E) {
    int e = blockIdx.x * blockDim.x + threadIdx.x;
    if (e < E) {
        int srcv = edge_at(edges, e);
        int d    = edge_at(edges, (size_t)E + e);
        int p = atomicAdd(&g_cursor[d], 1);
        g_col[g_rowptr[d] + p] = srcv;
    }
}

// ---------------- mean aggregation: g_agg[i] = inv_deg[i] * sum_{j in N(i)} feat[j]
// FROM_H=false: feat = x param. FROM_H=true: feat = g_h (device symbol).
// blockDim = (32, 8): one warp per node, lanes cover 256 feats as 2x float4
template <bool FROM_H>
__global__ void aggregate_kernel(const float* __restrict__ feat_in, int n) {
    int node = blockIdx.x * blockDim.y + threadIdx.y;
    if (node >= n) return;
    int lane = threadIdx.x;
    const float* feat = FROM_H ? (const float*)g_h : feat_in;
    int beg = g_rowptr[node], end = g_rowptr[node + 1];
    float4 acc0 = make_float4(0.f, 0.f, 0.f, 0.f);
    float4 acc1 = make_float4(0.f, 0.f, 0.f, 0.f);
    for (int e = beg; e < end; e++) {
        const float4* r = (const float4*)&feat[(size_t)g_col[e] * F];
        float4 a = r[lane];
        float4 b = r[lane + 32];
        acc0.x += a.x; acc0.y += a.y; acc0.z += a.z; acc0.w += a.w;
        acc1.x += b.x; acc1.y += b.y; acc1.z += b.z; acc1.w += b.w;
    }
    float s = g_invdeg[node];
    float4* o = (float4*)&g_agg[(size_t)node * F];
    o[lane]      = make_float4(acc0.x * s, acc0.y * s, acc0.z * s, acc0.w * s);
    o[lane + 32] = make_float4(acc1.x * s, acc1.y * s, acc1.z * s, acc1.w * s);
}

// ---------------- GEMM1: g_h = relu(g_agg*B0^T + x*B1^T + bias0 + bias1)
// Tiles: BM=128, BN=64, BK=16; 256 threads; 8x4 per-thread microtile.
__global__ void gemm_fused_relu_kernel(const float* __restrict__ A1,
                                       const float* __restrict__ B0,
                                       const float* __restrict__ B1,
                                       const float* __restrict__ bias0,
                                       const float* __restrict__ bias1,
                                       int M) {
    const int BM = 128, BN = 64, BK = 16, TM = 8, TN = 4;
    __shared__ __align__(16) float As[BK][BM];
    __shared__ __align__(16) float Bs[BK][BN];
    int bm = blockIdx.x * BM;
    int bn = blockIdx.y * BN;
    int tid = threadIdx.x;
    int ty = tid >> 4;      // 0..15 -> M
    int tx = tid & 15;      // 0..15 -> N

    float acc[TM][TN];
#pragma unroll
    for (int i = 0; i < TM; i++)
#pragma unroll
        for (int j = 0; j < TN; j++) acc[i][j] = 0.f;

#pragma unroll 1
    for (int s = 0; s < 2; s++) {
        const float* A = s ? A1 : (const float*)g_agg;
        const float* B = s ? B1 : B0;
#pragma unroll 1
        for (int k0 = 0; k0 < F; k0 += BK) {
#pragma unroll
            for (int it = 0; it < 2; it++) {
                int idx = tid + it * 256;
                int r = idx >> 2;
                int c4 = idx & 3;
                int grow = bm + r;
                float4 v = make_float4(0.f, 0.f, 0.f, 0.f);
                if (grow < M) v = *(const float4*)&A[(size_t)grow * F + k0 + c4 * 4];
                As[c4 * 4 + 0][r] = v.x;
                As[c4 * 4 + 1][r] = v.y;
                As[c4 * 4 + 2][r] = v.z;
                As[c4 * 4 + 3][r] = v.w;
            }
            {
                int r = tid >> 2;
                int c4 = tid & 3;
                float4 v = *(const float4*)&B[(size_t)(bn + r) * F + k0 + c4 * 4];
                Bs[c4 * 4 + 0][r] = v.x;
                Bs[c4 * 4 + 1][r] = v.y;
                Bs[c4 * 4 + 2][r] = v.z;
                Bs[c4 * 4 + 3][r] = v.w;
            }
            __syncthreads();
#pragma unroll
            for (int k = 0; k < BK; k++) {
                float4 a0 = *(const float4*)&As[k][ty * TM];
                float4 a1 = *(const float4*)&As[k][ty * TM + 4];
                float4 bv = *(const float4*)&Bs[k][tx * TN];
                float a[TM] = {a0.x, a0.y, a0.z, a0.w, a1.x, a1.y, a1.z, a1.w};
                float b[TN] = {bv.x, bv.y, bv.z, bv.w};
#pragma unroll
                for (int i = 0; i < TM; i++)
#pragma unroll
                    for (int j = 0; j < TN; j++) acc[i][j] += a[i] * b[j];
            }
            __syncthreads();
        }
    }
#pragma unroll
    for (int j = 0; j < TN; j++) {
        int gc = bn + tx * TN + j;
        float bb = bias0[gc] + bias1[gc];
#pragma unroll
        for (int i = 0; i < TM; i++) {
            int gr = bm + ty * TM + i;
            if (gr < M) {
                float v = acc[i][j] + bb;
                g_h[(size_t)gr * F + gc] = fmaxf(v, 0.f);
            }
        }
    }
}

// ---------------- GEMM2: out = g_agg*B0^T + g_h*B1^T + bias0 + bias1  (N=40)
__global__ void gemm_out_kernel(const float* __restrict__ B0,
                                const float* __restrict__ B1,
                                const float* __restrict__ bias0,
                                const float* __restrict__ bias1,
                                float* __restrict__ C, int M) {
    const int BM = 128, BK = 32, TM = 4, TN = 5;
    __shared__ __align__(16) float As[BK][BM];
    __shared__ __align__(16) float Bs[BK][NCLS];
    int bm = blockIdx.x * BM;
    int tid = threadIdx.x;
    int ty = tid >> 3;      // 0..31 -> M
    int tx = tid & 7;       // 0..7  -> N (8*5 = 40)

    float acc[TM][TN];
#pragma unroll
    for (int i = 0; i < TM; i++)
#pragma unroll
        for (int j = 0; j < TN; j++) acc[i][j] = 0.f;

#pragma unroll 1
    for (int s = 0; s < 2; s++) {
        const float* A = s ? (const float*)g_h : (const float*)g_agg;
        const float* B = s ? B1 : B0;
#pragma unroll 1
        for (int k0 = 0; k0 < F; k0 += BK) {
#pragma unroll
            for (int it = 0; it < 4; it++) {
                int idx = tid + it * 256;
                int r = idx >> 3;
                int c4 = idx & 7;
                int grow = bm + r;
                float4 v = make_float4(0.f, 0.f, 0.f, 0.f);
                if (grow < M) v = *(const float4*)&A[(size_t)grow * F + k0 + c4 * 4];
                As[c4 * 4 + 0][r] = v.x;
                As[c4 * 4 + 1][r] = v.y;
                As[c4 * 4 + 2][r] = v.z;
                As[c4 * 4 + 3][r] = v.w;
            }
            for (int idx = tid; idx < NCLS * BK / 4; idx += 256) {
                int r = idx >> 3;     // 0..39
                int c4 = idx & 7;
                float4 v = *(const float4*)&B[(size_t)r * F + k0 + c4 * 4];
                Bs[c4 * 4 + 0][r] = v.x;
                Bs[c4 * 4 + 1][r] = v.y;
                Bs[c4 * 4 + 2][r] = v.z;
                Bs[c4 * 4 + 3][r] = v.w;
            }
            __syncthreads();
#pragma unroll
            for (int k = 0; k < BK; k++) {
                float4 av4 = *(const float4*)&As[k][ty * TM];
                float a[TM] = {av4.x, av4.y, av4.z, av4.w};
                float b[TN];
#pragma unroll
                for (int j = 0; j < TN; j++) b[j] = Bs[k][tx * TN + j];
#pragma unroll
                for (int i = 0; i < TM; i++)
#pragma unroll
                    for (int j = 0; j < TN; j++) acc[i][j] += a[i] * b[j];
            }
            __syncthreads();
        }
    }
#pragma unroll
    for (int j = 0; j < TN; j++) {
        int gc = tx * TN + j;
        float bb = bias0[gc] + bias1[gc];
#pragma unroll
        for (int i = 0; i < TM; i++) {
            int gr = bm + ty * TM + i;
            if (gr < M) C[(size_t)gr * NCLS + gc] = acc[i][j] + bb;
        }
    }
}

// ---------------- launch --------------------------------------------------
extern "C" void kernel_launch(void* const* d_in, const int* in_sizes, int n_in,
                              void* d_out, int out_size) {
    const float* x     = (const float*)d_in[0];
    const void*  edges = (const void*)d_in[1];
    const float* w1_l = (const float*)d_in[2];
    const float* b1_l = (const float*)d_in[3];
    const float* w1_r = (const float*)d_in[4];
    const float* b1_r = (const float*)d_in[5];
    const float* w2_l = (const float*)d_in[6];
    const float* b2_l = (const float*)d_in[7];
    const float* w2_r = (const float*)d_in[8];
    const float* b2_r = (const float*)d_in[9];
    float* out = (float*)d_out;

    int N = in_sizes[0] / F;
    int E = in_sizes[1] / 2;
    int nb = (N + SCAN_TILE - 1) / SCAN_TILE;   // 49 for N=50000

    // dtype probe + CSR build
    detect_kernel<<<1, 256>>>((const int*)edges);
    zero_counts_kernel<<<(N + 255) / 256, 256>>>(N);
    degree_kernel<<<(E + 255) / 256, 256>>>(edges, E);
    scan_partial_kernel<<<nb, SCAN_TILE>>>(N);
    scan_blocks_kernel<<<1, SCAN_TILE>>>(nb);
    scan_emit_kernel<<<nb, SCAN_TILE>>>(N, E);
    scatter_kernel<<<(E + 255) / 256, 256>>>(edges, E);

    dim3 aggBlock(32, 8);
    int aggGrid = (N + 7) / 8;

    // Layer 1
    aggregate_kernel<false><<<aggGrid, aggBlock>>>(x, N);
    {
        dim3 grid((N + 127) / 128, F / 64);
        gemm_fused_relu_kernel<<<grid, 256>>>(x, w1_l, w1_r, b1_l, b1_r, N);
    }

    // Layer 2
    aggregate_kernel<true><<<aggGrid, aggBlock>>>(nullptr, N);
    gemm_out_kernel<<<(N + 127) / 128, 256>>>(w2_l, w2_r, b2_l, b2_r, out, N);
}

// round 6
// speedup vs baseline: 1.1688x; 1.0461x over previous
#include <cuda_runtime.h>
#include <cstdint>

// Problem constants (fixed by reference_code)
#define NMAX 50000
#define EMAX 800000
#define F    256
#define NCLS 40
#define SCAN_TILE 1024
#define NBLK_MAX  64          // ceil(NMAX/SCAN_TILE) = 49 <= 64

// ---------------- scratch (static device globals; no runtime allocation) ----
__device__ int   g_is64;                 // 1 if edge_index is int64, 0 if int32
__device__ int   g_deg[NMAX];
__device__ int   g_cursor[NMAX];
__device__ int   g_rowptr[NMAX + 1];
__device__ int   g_col[EMAX];
__device__ int   g_excl[NMAX];           // within-block exclusive prefix
__device__ int   g_blocksum[NBLK_MAX];   // per-block degree totals
__device__ int   g_blockoff[NBLK_MAX];   // exclusive scan of block totals
__device__ float g_invdeg[NMAX];
__device__ __align__(16) float g_agg[(size_t)NMAX * F];   // layer-1 agg scratch
__device__ __align__(16) float g_h[(size_t)NMAX * F];     // relu(layer1 output)
__device__ __align__(16) float g_t[(size_t)NMAX * NCLS];  // h @ w2_l^T
__device__ __align__(16) float g_aggt[(size_t)NMAX * NCLS];

// ---------------- edge dtype detection -------------------------------------
// int64 little-endian values < 2^31  =>  odd int32 slots are all zero.
__global__ void detect_kernel(const int* __restrict__ v) {
    __shared__ int any_nonzero;
    if (threadIdx.x == 0) any_nonzero = 0;
    __syncthreads();
    int idx = 2 * threadIdx.x + 1;          // odd slots 1,3,...,511
    if (v[idx] != 0) atomicOr(&any_nonzero, 1);
    __syncthreads();
    if (threadIdx.x == 0) g_is64 = (any_nonzero == 0) ? 1 : 0;
}

__device__ __forceinline__ int edge_at(const void* edges, size_t idx) {
    if (g_is64) return (int)((const long long*)edges)[idx];
    return ((const int*)edges)[idx];
}

// ---------------- CSR build ------------------------------------------------
__global__ void zero_counts_kernel(int n) {
    int i = blockIdx.x * blockDim.x + threadIdx.x;
    if (i < n) { g_deg[i] = 0; g_cursor[i] = 0; }
}

__global__ void degree_kernel(const void* __restrict__ edges, int E) {
    int e = blockIdx.x * blockDim.x + threadIdx.x;
    if (e < E) {
        int d = edge_at(edges, (size_t)E + e);   // dst row
        atomicAdd(&g_deg[d], 1);
    }
}

// Block-wide inclusive scan; returns inclusive prefix, total in *total.
__device__ __forceinline__ int block_incl_scan(int d, int* total) {
    __shared__ int wsum[32];
    int lane = threadIdx.x & 31, wid = threadIdx.x >> 5;
    int v = d;
#pragma unroll
    for (int o = 1; o < 32; o <<= 1) {
        int t = __shfl_up_sync(0xffffffffu, v, o);
        if (lane >= o) v += t;
    }
    if (lane == 31) wsum[wid] = v;
    __syncthreads();
    if (wid == 0) {
        int w = wsum[lane];
#pragma unroll
        for (int o = 1; o < 32; o <<= 1) {
            int t = __shfl_up_sync(0xffffffffu, w, o);
            if (lane >= o) w += t;
        }
        wsum[lane] = w;
    }
    __syncthreads();
    int incl = v + (wid > 0 ? wsum[wid - 1] : 0);
    *total = wsum[31];
    __syncthreads();
    return incl;
}

__global__ void scan_partial_kernel(int n) {
    int i = blockIdx.x * SCAN_TILE + threadIdx.x;
    int d = (i < n) ? g_deg[i] : 0;
    int total;
    int incl = block_incl_scan(d, &total);
    if (i < n) g_excl[i] = incl - d;
    if (threadIdx.x == 0) g_blocksum[blockIdx.x] = total;
}

__global__ void scan_blocks_kernel(int nb) {
    int d = (threadIdx.x < nb) ? g_blocksum[threadIdx.x] : 0;
    int total;
    int incl = block_incl_scan(d, &total);
    if (threadIdx.x < nb) g_blockoff[threadIdx.x] = incl - d;
}

__global__ void scan_emit_kernel(int n, int E) {
    int i = blockIdx.x * SCAN_TILE + threadIdx.x;
    if (i < n) {
        g_rowptr[i] = g_blockoff[blockIdx.x] + g_excl[i];
        int d = g_deg[i];
        g_invdeg[i] = 1.0f / (float)(d > 0 ? d : 1);
        if (i == n - 1) g_rowptr[n] = E;
    }
}

__global__ void scatter_kernel(const void* __restrict__ edges, int E) {
    int e = blockIdx.x * blockDim.x + threadIdx.x;
    if (e < E) {
        int srcv = edge_at(edges, e);
        int d    = edge_at(edges, (size_t)E + e);
        int p = atomicAdd(&g_cursor[d], 1);
        g_col[g_rowptr[d] + p] = srcv;
    }
}

// ---------------- mean aggregation (256-dim): g_agg[i] = invdeg * sum feat[nbr]
// blockDim = (32, 8): one warp per node, lanes cover 256 feats as 2x float4
__global__ void aggregate_kernel(const float* __restrict__ feat, int n) {
    int node = blockIdx.x * blockDim.y + threadIdx.y;
    if (node >= n) return;
    int lane = threadIdx.x;
    int beg = g_rowptr[node], end = g_rowptr[node + 1];
    float4 acc0 = make_float4(0.f, 0.f, 0.f, 0.f);
    float4 acc1 = make_float4(0.f, 0.f, 0.f, 0.f);
    for (int e = beg; e < end; e++) {
        const float4* r = (const float4*)&feat[(size_t)g_col[e] * F];
        float4 a = r[lane];
        float4 b = r[lane + 32];
        acc0.x += a.x; acc0.y += a.y; acc0.z += a.z; acc0.w += a.w;
        acc1.x += b.x; acc1.y += b.y; acc1.z += b.z; acc1.w += b.w;
    }
    float s = g_invdeg[node];
    float4* o = (float4*)&g_agg[(size_t)node * F];
    o[lane]      = make_float4(acc0.x * s, acc0.y * s, acc0.z * s, acc0.w * s);
    o[lane + 32] = make_float4(acc1.x * s, acc1.y * s, acc1.z * s, acc1.w * s);
}

// ---------------- mean aggregation (40-dim): g_aggt[i] = invdeg * sum g_t[nbr]
// 10 threads per node, each owns one float4 of the 40-float row.
// blockDim = 320 -> 32 nodes per block.
__global__ void aggregate40_kernel(int n) {
    int tid = threadIdx.x;
    int node = blockIdx.x * 32 + tid / 10;
    int c4 = tid % 10;
    if (node >= n) return;
    int beg = g_rowptr[node], end = g_rowptr[node + 1];
    float4 acc = make_float4(0.f, 0.f, 0.f, 0.f);
    for (int e = beg; e < end; e++) {
        float4 v = *(const float4*)&g_t[(size_t)g_col[e] * NCLS + c4 * 4];
        acc.x += v.x; acc.y += v.y; acc.z += v.z; acc.w += v.w;
    }
    float s = g_invdeg[node];
    *(float4*)&g_aggt[(size_t)node * NCLS + c4 * 4] =
        make_float4(acc.x * s, acc.y * s, acc.z * s, acc.w * s);
}

// ---------------- GEMM1: g_h = relu(g_agg*B0^T + x*B1^T + bias0 + bias1)
// Tiles: BM=128, BN=64, BK=16; 256 threads; 8x4 per-thread microtile.
__global__ void gemm_fused_relu_kernel(const float* __restrict__ A1,
                                       const float* __restrict__ B0,
                                       const float* __restrict__ B1,
                                       const float* __restrict__ bias0,
                                       const float* __restrict__ bias1,
                                       int M) {
    const int BM = 128, BN = 64, BK = 16, TM = 8, TN = 4;
    __shared__ __align__(16) float As[BK][BM];
    __shared__ __align__(16) float Bs[BK][BN];
    int bm = blockIdx.x * BM;
    int bn = blockIdx.y * BN;
    int tid = threadIdx.x;
    int ty = tid >> 4;
    int tx = tid & 15;

    float acc[TM][TN];
#pragma unroll
    for (int i = 0; i < TM; i++)
#pragma unroll
        for (int j = 0; j < TN; j++) acc[i][j] = 0.f;

#pragma unroll 1
    for (int s = 0; s < 2; s++) {
        const float* A = s ? A1 : (const float*)g_agg;
        const float* B = s ? B1 : B0;
#pragma unroll 1
        for (int k0 = 0; k0 < F; k0 += BK) {
#pragma unroll
            for (int it = 0; it < 2; it++) {
                int idx = tid + it * 256;
                int r = idx >> 2;
                int c4 = idx & 3;
                int grow = bm + r;
                float4 v = make_float4(0.f, 0.f, 0.f, 0.f);
                if (grow < M) v = *(const float4*)&A[(size_t)grow * F + k0 + c4 * 4];
                As[c4 * 4 + 0][r] = v.x;
                As[c4 * 4 + 1][r] = v.y;
                As[c4 * 4 + 2][r] = v.z;
                As[c4 * 4 + 3][r] = v.w;
            }
            {
                int r = tid >> 2;
                int c4 = tid & 3;
                float4 v = *(const float4*)&B[(size_t)(bn + r) * F + k0 + c4 * 4];
                Bs[c4 * 4 + 0][r] = v.x;
                Bs[c4 * 4 + 1][r] = v.y;
                Bs[c4 * 4 + 2][r] = v.z;
                Bs[c4 * 4 + 3][r] = v.w;
            }
            __syncthreads();
#pragma unroll
            for (int k = 0; k < BK; k++) {
                float4 a0 = *(const float4*)&As[k][ty * TM];
                float4 a1 = *(const float4*)&As[k][ty * TM + 4];
                float4 bv = *(const float4*)&Bs[k][tx * TN];
                float a[TM] = {a0.x, a0.y, a0.z, a0.w, a1.x, a1.y, a1.z, a1.w};
                float b[TN] = {bv.x, bv.y, bv.z, bv.w};
#pragma unroll
                for (int i = 0; i < TM; i++)
#pragma unroll
                    for (int j = 0; j < TN; j++) acc[i][j] += a[i] * b[j];
            }
            __syncthreads();
        }
    }
#pragma unroll
    for (int j = 0; j < TN; j++) {
        int gc = bn + tx * TN + j;
        float bb = bias0[gc] + bias1[gc];
#pragma unroll
        for (int i = 0; i < TM; i++) {
            int gr = bm + ty * TM + i;
            if (gr < M) {
                float v = acc[i][j] + bb;
                g_h[(size_t)gr * F + gc] = fmaxf(v, 0.f);
            }
        }
    }
}

// ---------------- 40-wide GEMM on A = g_h, K=256.
// FINAL=false: g_t = h @ B^T
// FINAL=true:  C   = g_aggt + h @ B^T + bias0 + bias1
// BM=128, BK=32; 256 threads; per-thread 4x5 microtile.
template <bool FINAL>
__global__ void gemm40_kernel(const float* __restrict__ B,
                              const float* __restrict__ bias0,
                              const float* __restrict__ bias1,
                              float* __restrict__ C, int M) {
    const int BM = 128, BK = 32, TM = 4, TN = 5;
    __shared__ __align__(16) float As[BK][BM];
    __shared__ __align__(16) float Bs[BK][NCLS];
    int bm = blockIdx.x * BM;
    int tid = threadIdx.x;
    int ty = tid >> 3;      // 0..31 -> M
    int tx = tid & 7;       // 0..7  -> N (8*5 = 40)

    float acc[TM][TN];
#pragma unroll
    for (int i = 0; i < TM; i++)
#pragma unroll
        for (int j = 0; j < TN; j++) acc[i][j] = 0.f;

#pragma unroll 1
    for (int k0 = 0; k0 < F; k0 += BK) {
#pragma unroll
        for (int it = 0; it < 4; it++) {
            int idx = tid + it * 256;
            int r = idx >> 3;
            int c4 = idx & 7;
            int grow = bm + r;
            float4 v = make_float4(0.f, 0.f, 0.f, 0.f);
            if (grow < M) v = *(const float4*)&g_h[(size_t)grow * F + k0 + c4 * 4];
            As[c4 * 4 + 0][r] = v.x;
            As[c4 * 4 + 1][r] = v.y;
            As[c4 * 4 + 2][r] = v.z;
            As[c4 * 4 + 3][r] = v.w;
        }
        for (int idx = tid; idx < NCLS * BK / 4; idx += 256) {
            int r = idx >> 3;     // 0..39
            int c4 = idx & 7;
            float4 v = *(const float4*)&B[(size_t)r * F + k0 + c4 * 4];
            Bs[c4 * 4 + 0][r] = v.x;
            Bs[c4 * 4 + 1][r] = v.y;
            Bs[c4 * 4 + 2][r] = v.z;
            Bs[c4 * 4 + 3][r] = v.w;
        }
        __syncthreads();
#pragma unroll
        for (int k = 0; k < BK; k++) {
            float4 av4 = *(const float4*)&As[k][ty * TM];
            float a[TM] = {av4.x, av4.y, av4.z, av4.w};
            float b[TN];
#pragma unroll
            for (int j = 0; j < TN; j++) b[j] = Bs[k][tx * TN + j];
#pragma unroll
            for (int i = 0; i < TM; i++)
#pragma unroll
                for (int j = 0; j < TN; j++) acc[i][j] += a[i] * b[j];
        }
        __syncthreads();
    }
#pragma unroll
    for (int j = 0; j < TN; j++) {
        int gc = tx * TN + j;
        float bb = FINAL ? (bias0[gc] + bias1[gc]) : 0.f;
#pragma unroll
        for (int i = 0; i < TM; i++) {
            int gr = bm + ty * TM + i;
            if (gr < M) {
                if (FINAL) {
                    C[(size_t)gr * NCLS + gc] =
                        acc[i][j] + bb + g_aggt[(size_t)gr * NCLS + gc];
                } else {
                    g_t[(size_t)gr * NCLS + gc] = acc[i][j];
                }
            }
        }
    }
}

// ---------------- launch --------------------------------------------------
extern "C" void kernel_launch(void* const* d_in, const int* in_sizes, int n_in,
                              void* d_out, int out_size) {
    const float* x     = (const float*)d_in[0];
    const void*  edges = (const void*)d_in[1];
    const float* w1_l = (const float*)d_in[2];
    const float* b1_l = (const float*)d_in[3];
    const float* w1_r = (const float*)d_in[4];
    const float* b1_r = (const float*)d_in[5];
    const float* w2_l = (const float*)d_in[6];
    const float* b2_l = (const float*)d_in[7];
    const float* w2_r = (const float*)d_in[8];
    const float* b2_r = (const float*)d_in[9];
    float* out = (float*)d_out;

    int N = in_sizes[0] / F;
    int E = in_sizes[1] / 2;
    int nb = (N + SCAN_TILE - 1) / SCAN_TILE;

    // dtype probe + CSR build
    detect_kernel<<<1, 256>>>((const int*)edges);
    zero_counts_kernel<<<(N + 255) / 256, 256>>>(N);
    degree_kernel<<<(E + 255) / 256, 256>>>(edges, E);
    scan_partial_kernel<<<nb, SCAN_TILE>>>(N);
    scan_blocks_kernel<<<1, SCAN_TILE>>>(nb);
    scan_emit_kernel<<<nb, SCAN_TILE>>>(N, E);
    scatter_kernel<<<(E + 255) / 256, 256>>>(edges, E);

    // Layer 1: agg(x) -> GEMM(+relu)
    dim3 aggBlock(32, 8);
    aggregate_kernel<<<(N + 7) / 8, aggBlock>>>(x, N);
    {
        dim3 grid((N + 127) / 128, F / 64);
        gemm_fused_relu_kernel<<<grid, 256>>>(x, w1_l, w1_r, b1_l, b1_r, N);
    }

    // Layer 2 (aggregate-after-projection): t = h@w2_l^T; agg(t); out = agg_t + h@w2_r^T + b
    gemm40_kernel<false><<<(N + 127) / 128, 256>>>(w2_l, nullptr, nullptr, nullptr, N);
    aggregate40_kernel<<<(N + 31) / 32, 320>>>(N);
    gemm40_kernel<true><<<(N + 127) / 128, 256>>>(w2_r, b2_l, b2_r, out, N);
}

// round 7
// speedup vs baseline: 1.8114x; 1.5497x over previous
#include <cuda_runtime.h>
#include <cuda_bf16.h>
#include <cstdint>

// Problem constants (fixed by reference_code)
#define NMAX 50000
#define EMAX 800000
#define F    256
#define AK   512          // concat K for layer-1 GEMM (agg | x)
#define NCLS 40
#define SCAN_TILE 1024
#define NBLK_MAX  64

// ---------------- scratch (static device globals; no runtime allocation) ----
__device__ int   g_is64;
__device__ int   g_deg[NMAX];
__device__ int   g_cursor[NMAX];
__device__ int   g_rowptr[NMAX + 1];
__device__ int   g_col[EMAX];
__device__ int   g_excl[NMAX];
__device__ int   g_blocksum[NBLK_MAX];
__device__ int   g_blockoff[NBLK_MAX];
__device__ float g_invdeg[NMAX];
__device__ __align__(16) __nv_bfloat16 g_Ahi[(size_t)NMAX * AK];  // [agg|x] hi
__device__ __align__(16) __nv_bfloat16 g_Alo[(size_t)NMAX * AK];  // [agg|x] lo
__device__ __align__(16) __nv_bfloat16 g_Bhi[(size_t)F * AK];     // [w1_l|w1_r] hi
__device__ __align__(16) __nv_bfloat16 g_Blo[(size_t)F * AK];     // lo
__device__ __align__(16) float g_h[(size_t)NMAX * F];             // relu(layer1)
__device__ __align__(16) float g_t[(size_t)NMAX * NCLS];          // h @ w2_l^T
__device__ __align__(16) float g_u[(size_t)NMAX * NCLS];          // h @ w2_r^T
__device__ __align__(16) float g_aggt[(size_t)NMAX * NCLS];

// ---------------- small PTX helpers ----------------------------------------
__device__ __forceinline__ void ldsm_x4(uint32_t& r0, uint32_t& r1,
                                        uint32_t& r2, uint32_t& r3, uint32_t addr) {
    asm volatile("ldmatrix.sync.aligned.m8n8.x4.shared.b16 {%0,%1,%2,%3},[%4];"
                 : "=r"(r0), "=r"(r1), "=r"(r2), "=r"(r3) : "r"(addr));
}
__device__ __forceinline__ void mma_bf16(float* c, const uint32_t* a, const uint32_t* b) {
    asm volatile("mma.sync.aligned.m16n8k16.row.col.f32.bf16.bf16.f32 "
                 "{%0,%1,%2,%3},{%4,%5,%6,%7},{%8,%9},{%0,%1,%2,%3};"
                 : "+f"(c[0]), "+f"(c[1]), "+f"(c[2]), "+f"(c[3])
                 : "r"(a[0]), "r"(a[1]), "r"(a[2]), "r"(a[3]), "r"(b[0]), "r"(b[1]));
}
__device__ __forceinline__ void cp16(uint32_t saddr, const void* gaddr, int sz) {
    asm volatile("cp.async.cg.shared.global [%0],[%1],16,%2;"
                 :: "r"(saddr), "l"(gaddr), "r"(sz));
}
__device__ __forceinline__ void cp_wait_all() {
    asm volatile("cp.async.commit_group;");
    asm volatile("cp.async.wait_group 0;");
}

// hi/lo bf16 split of 4 floats, stored at hi[0..3], lo[0..3] (8B aligned)
__device__ __forceinline__ void split4(__nv_bfloat16* hi, __nv_bfloat16* lo, float4 v) {
    __nv_bfloat162 h0 = __floats2bfloat162_rn(v.x, v.y);
    __nv_bfloat162 h1 = __floats2bfloat162_rn(v.z, v.w);
    float lx = v.x - __bfloat162float(h0.x);
    float ly = v.y - __bfloat162float(h0.y);
    float lz = v.z - __bfloat162float(h1.x);
    float lw = v.w - __bfloat162float(h1.y);
    *reinterpret_cast<__nv_bfloat162*>(hi)     = h0;
    *reinterpret_cast<__nv_bfloat162*>(hi + 2) = h1;
    *reinterpret_cast<__nv_bfloat162*>(lo)     = __floats2bfloat162_rn(lx, ly);
    *reinterpret_cast<__nv_bfloat162*>(lo + 2) = __floats2bfloat162_rn(lz, lw);
}

// ---------------- edge dtype detection -------------------------------------
__global__ void detect_kernel(const int* __restrict__ v) {
    __shared__ int any_nonzero;
    if (threadIdx.x == 0) any_nonzero = 0;
    __syncthreads();
    if (v[2 * threadIdx.x + 1] != 0) atomicOr(&any_nonzero, 1);
    __syncthreads();
    if (threadIdx.x == 0) g_is64 = (any_nonzero == 0) ? 1 : 0;
}
__device__ __forceinline__ int edge_at(const void* edges, size_t idx) {
    if (g_is64) return (int)((const long long*)edges)[idx];
    return ((const int*)edges)[idx];
}

// ---------------- CSR build ------------------------------------------------
__global__ void zero_counts_kernel(int n) {
    int i = blockIdx.x * blockDim.x + threadIdx.x;
    if (i < n) { g_deg[i] = 0; g_cursor[i] = 0; }
}
__global__ void degree_kernel(const void* __restrict__ edges, int E) {
    int e = blockIdx.x * blockDim.x + threadIdx.x;
    if (e < E) atomicAdd(&g_deg[edge_at(edges, (size_t)E + e)], 1);
}
__device__ __forceinline__ int block_incl_scan(int d, int* total) {
    __shared__ int wsum[32];
    int lane = threadIdx.x & 31, wid = threadIdx.x >> 5;
    int v = d;
#pragma unroll
    for (int o = 1; o < 32; o <<= 1) {
        int t = __shfl_up_sync(0xffffffffu, v, o);
        if (lane >= o) v += t;
    }
    if (lane == 31) wsum[wid] = v;
    __syncthreads();
    if (wid == 0) {
        int w = wsum[lane];
#pragma unroll
        for (int o = 1; o < 32; o <<= 1) {
            int t = __shfl_up_sync(0xffffffffu, w, o);
            if (lane >= o) w += t;
        }
        wsum[lane] = w;
    }
    __syncthreads();
    int incl = v + (wid > 0 ? wsum[wid - 1] : 0);
    *total = wsum[31];
    __syncthreads();
    return incl;
}
__global__ void scan_partial_kernel(int n) {
    int i = blockIdx.x * SCAN_TILE + threadIdx.x;
    int d = (i < n) ? g_deg[i] : 0;
    int total;
    int incl = block_incl_scan(d, &total);
    if (i < n) g_excl[i] = incl - d;
    if (threadIdx.x == 0) g_blocksum[blockIdx.x] = total;
}
__global__ void scan_blocks_kernel(int nb) {
    int d = (threadIdx.x < nb) ? g_blocksum[threadIdx.x] : 0;
    int total;
    int incl = block_incl_scan(d, &total);
    if (threadIdx.x < nb) g_blockoff[threadIdx.x] = incl - d;
}
__global__ void scan_emit_kernel(int n, int E) {
    int i = blockIdx.x * SCAN_TILE + threadIdx.x;
    if (i < n) {
        g_rowptr[i] = g_blockoff[blockIdx.x] + g_excl[i];
        int d = g_deg[i];
        g_invdeg[i] = 1.0f / (float)(d > 0 ? d : 1);
        if (i == n - 1) g_rowptr[n] = E;
    }
}
__global__ void scatter_kernel(const void* __restrict__ edges, int E) {
    int e = blockIdx.x * blockDim.x + threadIdx.x;
    if (e < E) {
        int srcv = edge_at(edges, e);
        int d    = edge_at(edges, (size_t)E + e);
        int p = atomicAdd(&g_cursor[d], 1);
        g_col[g_rowptr[d] + p] = srcv;
    }
}

// ---------------- conversions ----------------------------------------------
// x -> bf16 hi/lo into columns [256, 512) of g_Ahi/g_Alo
__global__ void convert_x_kernel(const float* __restrict__ x, int n) {
    int idx = blockIdx.x * blockDim.x + threadIdx.x;   // over n*64 float4s
    if (idx >= n * (F / 4)) return;
    int row = idx / (F / 4), c4 = idx % (F / 4);
    float4 v = *(const float4*)&x[(size_t)row * F + c4 * 4];
    size_t o = (size_t)row * AK + F + c4 * 4;
    split4(&g_Ahi[o], &g_Alo[o], v);
}
// w1_l -> cols [0,256), w1_r -> cols [256,512) of g_Bhi/g_Blo  (256 rows)
__global__ void convert_w_kernel(const float* __restrict__ w1_l,
                                 const float* __restrict__ w1_r) {
    int idx = blockIdx.x * blockDim.x + threadIdx.x;   // over 256*64
    if (idx >= F * (F / 4)) return;
    int row = idx / (F / 4), c4 = idx % (F / 4);
    float4 vl = *(const float4*)&w1_l[(size_t)row * F + c4 * 4];
    float4 vr = *(const float4*)&w1_r[(size_t)row * F + c4 * 4];
    size_t ol = (size_t)row * AK + c4 * 4;
    size_t orr = ol + F;
    split4(&g_Bhi[ol], &g_Blo[ol], vl);
    split4(&g_Bhi[orr], &g_Blo[orr], vr);
}

// ---------------- mean aggregation (256-dim) -> bf16 hi/lo cols [0,256) -----
__global__ void aggregate_kernel(const float* __restrict__ feat, int n) {
    int node = blockIdx.x * blockDim.y + threadIdx.y;
    if (node >= n) return;
    int lane = threadIdx.x;
    int beg = g_rowptr[node], end = g_rowptr[node + 1];
    float4 acc0 = make_float4(0.f, 0.f, 0.f, 0.f);
    float4 acc1 = make_float4(0.f, 0.f, 0.f, 0.f);
    for (int e = beg; e < end; e++) {
        const float4* r = (const float4*)&feat[(size_t)g_col[e] * F];
        float4 a = r[lane];
        float4 b = r[lane + 32];
        acc0.x += a.x; acc0.y += a.y; acc0.z += a.z; acc0.w += a.w;
        acc1.x += b.x; acc1.y += b.y; acc1.z += b.z; acc1.w += b.w;
    }
    float s = g_invdeg[node];
    acc0.x *= s; acc0.y *= s; acc0.z *= s; acc0.w *= s;
    acc1.x *= s; acc1.y *= s; acc1.z *= s; acc1.w *= s;
    size_t o0 = (size_t)node * AK + lane * 4;
    size_t o1 = (size_t)node * AK + 128 + lane * 4;
    split4(&g_Ahi[o0], &g_Alo[o0], acc0);
    split4(&g_Ahi[o1], &g_Alo[o1], acc1);
}

// ---------------- GEMM1 (tensor cores, bf16 split-3) ------------------------
// g_h = relu( A*B^T + bias ),  A=[M,512] bf16 hi/lo, B=[256,512] bf16 hi/lo
// C = Ahi*Bhi^T + Ahi*Blo^T + Alo*Bhi^T   (fp32 accum)
// BM=128, BN=128, BK=32; 8 warps in 2(m)x4(n); warp = 64x32; mma m16n8k16.
#define SMSTRIDE 40     // bf16 elems per smem row (80B: 16B-aligned, conflict-free ldsm)
__global__ __launch_bounds__(256) void gemm1_tc_kernel(const float* __restrict__ bias0,
                                                       const float* __restrict__ bias1,
                                                       int M) {
    __shared__ __align__(16) __nv_bfloat16 As[128 * SMSTRIDE];
    __shared__ __align__(16) __nv_bfloat16 Bs[128 * SMSTRIDE];
    const uint32_t asb = (uint32_t)__cvta_generic_to_shared(As);
    const uint32_t bsb = (uint32_t)__cvta_generic_to_shared(Bs);
    int bm = blockIdx.x * 128, bn = blockIdx.y * 128;
    int tid = threadIdx.x, wid = tid >> 5, lane = tid & 31;
    int wm = (wid >> 2) * 64, wn = (wid & 3) * 32;

    float acc[4][4][4];
#pragma unroll
    for (int mf = 0; mf < 4; mf++)
#pragma unroll
        for (int nf = 0; nf < 4; nf++)
#pragma unroll
            for (int r = 0; r < 4; r++) acc[mf][nf][r] = 0.f;

#pragma unroll 1
    for (int pass = 0; pass < 3; pass++) {
        const __nv_bfloat16* Ag = (pass == 2) ? (const __nv_bfloat16*)g_Alo
                                              : (const __nv_bfloat16*)g_Ahi;
        const __nv_bfloat16* Bg = (pass == 1) ? (const __nv_bfloat16*)g_Blo
                                              : (const __nv_bfloat16*)g_Bhi;
#pragma unroll 1
        for (int k0 = 0; k0 < AK; k0 += 32) {
            // A tile: 128 rows x 4 chunks(16B); 512 cp, 2 per thread
#pragma unroll
            for (int i = 0; i < 2; i++) {
                int idx = tid + i * 256;
                int row = idx >> 2, ch = idx & 3;
                int grow = bm + row;
                int gr = grow < M ? grow : (M - 1);
                cp16(asb + row * 80 + ch * 16,
                     Ag + (size_t)gr * AK + k0 + ch * 8, grow < M ? 16 : 0);
            }
#pragma unroll
            for (int i = 0; i < 2; i++) {
                int idx = tid + i * 256;
                int row = idx >> 2, ch = idx & 3;
                cp16(bsb + row * 80 + ch * 16,
                     Bg + (size_t)(bn + row) * AK + k0 + ch * 8, 16);
            }
            cp_wait_all();
            __syncthreads();
#pragma unroll
            for (int ks = 0; ks < 32; ks += 16) {
                uint32_t a[4][4], b[4][2];
#pragma unroll
                for (int mf = 0; mf < 4; mf++) {
                    int row = wm + mf * 16 + (lane & 15);
                    int kb = (ks + ((lane >> 4) << 3)) * 2;
                    ldsm_x4(a[mf][0], a[mf][1], a[mf][2], a[mf][3],
                            asb + row * 80 + kb);
                }
#pragma unroll
                for (int nf2 = 0; nf2 < 2; nf2++) {
                    int row = wn + nf2 * 16 + ((lane >> 4) << 3) + (lane & 7);
                    int kb = (ks + (((lane >> 3) & 1) << 3)) * 2;
                    uint32_t r0, r1, r2, r3;
                    ldsm_x4(r0, r1, r2, r3, bsb + row * 80 + kb);
                    b[nf2 * 2][0] = r0; b[nf2 * 2][1] = r1;
                    b[nf2 * 2 + 1][0] = r2; b[nf2 * 2 + 1][1] = r3;
                }
#pragma unroll
                for (int mf = 0; mf < 4; mf++)
#pragma unroll
                    for (int nf = 0; nf < 4; nf++)
                        mma_bf16(acc[mf][nf], a[mf], b[nf]);
            }
            __syncthreads();
        }
    }
    // epilogue: bias + relu -> g_h fp32
#pragma unroll
    for (int nf = 0; nf < 4; nf++) {
        int c = bn + wn + nf * 8 + 2 * (lane & 3);
        float bb0 = bias0[c] + bias1[c];
        float bb1 = bias0[c + 1] + bias1[c + 1];
#pragma unroll
        for (int mf = 0; mf < 4; mf++) {
            int r0 = bm + wm + mf * 16 + (lane >> 2);
            int r1 = r0 + 8;
            if (r0 < M) {
                g_h[(size_t)r0 * F + c]     = fmaxf(acc[mf][nf][0] + bb0, 0.f);
                g_h[(size_t)r0 * F + c + 1] = fmaxf(acc[mf][nf][1] + bb1, 0.f);
            }
            if (r1 < M) {
                g_h[(size_t)r1 * F + c]     = fmaxf(acc[mf][nf][2] + bb0, 0.f);
                g_h[(size_t)r1 * F + c + 1] = fmaxf(acc[mf][nf][3] + bb1, 0.f);
            }
        }
    }
}

// ---------------- dual 40-wide GEMM: g_t = h@w2_l^T, g_u = h@w2_r^T ---------
__global__ void gemm40_dual_kernel(const float* __restrict__ B0,
                                   const float* __restrict__ B1, int M) {
    const int BM = 128, BK = 32, TM = 4, TN = 5;
    __shared__ __align__(16) float As[BK][BM];
    __shared__ __align__(16) float Bs[BK][2 * NCLS];
    int bm = blockIdx.x * BM;
    int tid = threadIdx.x;
    int ty = tid >> 3;      // 0..31 -> M
    int tx = tid & 7;       // 0..7  -> N

    float accl[TM][TN], accu[TM][TN];
#pragma unroll
    for (int i = 0; i < TM; i++)
#pragma unroll
        for (int j = 0; j < TN; j++) { accl[i][j] = 0.f; accu[i][j] = 0.f; }

#pragma unroll 1
    for (int k0 = 0; k0 < F; k0 += BK) {
#pragma unroll
        for (int it = 0; it < 4; it++) {
            int idx = tid + it * 256;
            int r = idx >> 3;
            int c4 = idx & 7;
            int grow = bm + r;
            float4 v = make_float4(0.f, 0.f, 0.f, 0.f);
            if (grow < M) v = *(const float4*)&g_h[(size_t)grow * F + k0 + c4 * 4];
            As[c4 * 4 + 0][r] = v.x;
            As[c4 * 4 + 1][r] = v.y;
            As[c4 * 4 + 2][r] = v.z;
            As[c4 * 4 + 3][r] = v.w;
        }
        for (int idx = tid; idx < 2 * NCLS * BK / 4; idx += 256) {
            int r = idx >> 3;     // 0..79
            int c4 = idx & 7;
            const float* src = (r < NCLS) ? &B0[(size_t)r * F + k0 + c4 * 4]
                                          : &B1[(size_t)(r - NCLS) * F + k0 + c4 * 4];
            float4 v = *(const float4*)src;
            Bs[c4 * 4 + 0][r] = v.x;
            Bs[c4 * 4 + 1][r] = v.y;
            Bs[c4 * 4 + 2][r] = v.z;
            Bs[c4 * 4 + 3][r] = v.w;
        }
        __syncthreads();
#pragma unroll
        for (int k = 0; k < BK; k++) {
            float4 av4 = *(const float4*)&As[k][ty * TM];
            float a[TM] = {av4.x, av4.y, av4.z, av4.w};
            float bl[TN], bu[TN];
#pragma unroll
            for (int j = 0; j < TN; j++) {
                bl[j] = Bs[k][tx * TN + j];
                bu[j] = Bs[k][NCLS + tx * TN + j];
            }
#pragma unroll
            for (int i = 0; i < TM; i++)
#pragma unroll
                for (int j = 0; j < TN; j++) {
                    accl[i][j] += a[i] * bl[j];
                    accu[i][j] += a[i] * bu[j];
                }
        }
        __syncthreads();
    }
#pragma unroll
    for (int j = 0; j < TN; j++) {
        int gc = tx * TN + j;
#pragma unroll
        for (int i = 0; i < TM; i++) {
            int gr = bm + ty * TM + i;
            if (gr < M) {
                g_t[(size_t)gr * NCLS + gc] = accl[i][j];
                g_u[(size_t)gr * NCLS + gc] = accu[i][j];
            }
        }
    }
}

// ---------------- mean aggregation (40-dim) on g_t -> g_aggt ----------------
__global__ void aggregate40_kernel(int n) {
    int tid = threadIdx.x;
    int node = blockIdx.x * 32 + tid / 10;
    int c4 = tid % 10;
    if (node >= n) return;
    int beg = g_rowptr[node], end = g_rowptr[node + 1];
    float4 acc = make_float4(0.f, 0.f, 0.f, 0.f);
    for (int e = beg; e < end; e++) {
        float4 v = *(const float4*)&g_t[(size_t)g_col[e] * NCLS + c4 * 4];
        acc.x += v.x; acc.y += v.y; acc.z += v.z; acc.w += v.w;
    }
    float s = g_invdeg[node];
    *(float4*)&g_aggt[(size_t)node * NCLS + c4 * 4] =
        make_float4(acc.x * s, acc.y * s, acc.z * s, acc.w * s);
}

// ---------------- final: out = g_aggt + g_u + b2_l + b2_r -------------------
__global__ void final_add_kernel(const float* __restrict__ b0,
                                 const float* __restrict__ b1,
                                 float* __restrict__ out, int n) {
    int i = blockIdx.x * blockDim.x + threadIdx.x;
    if (i < n * NCLS) {
        int c = i % NCLS;
        out[i] = g_aggt[i] + g_u[i] + b0[c] + b1[c];
    }
}

// ---------------- launch --------------------------------------------------
extern "C" void kernel_launch(void* const* d_in, const int* in_sizes, int n_in,
                              void* d_out, int out_size) {
    const float* x     = (const float*)d_in[0];
    const void*  edges = (const void*)d_in[1];
    const float* w1_l = (const float*)d_in[2];
    const float* b1_l = (const float*)d_in[3];
    const float* w1_r = (const float*)d_in[4];
    const float* b1_r = (const float*)d_in[5];
    const float* w2_l = (const float*)d_in[6];
    const float* b2_l = (const float*)d_in[7];
    const float* w2_r = (const float*)d_in[8];
    const float* b2_r = (const float*)d_in[9];
    float* out = (float*)d_out;

    int N = in_sizes[0] / F;
    int E = in_sizes[1] / 2;
    int nb = (N + SCAN_TILE - 1) / SCAN_TILE;

    // dtype probe + CSR build
    detect_kernel<<<1, 256>>>((const int*)edges);
    zero_counts_kernel<<<(N + 255) / 256, 256>>>(N);
    degree_kernel<<<(E + 255) / 256, 256>>>(edges, E);
    scan_partial_kernel<<<nb, SCAN_TILE>>>(N);
    scan_blocks_kernel<<<1, SCAN_TILE>>>(nb);
    scan_emit_kernel<<<nb, SCAN_TILE>>>(N, E);
    scatter_kernel<<<(E + 255) / 256, 256>>>(edges, E);

    // bf16 conversions (independent of CSR)
    convert_x_kernel<<<(N * (F / 4) + 255) / 256, 256>>>(x, N);
    convert_w_kernel<<<(F * (F / 4) + 255) / 256, 256>>>(w1_l, w1_r);

    // Layer 1: agg(x) -> bf16 split; tensor-core GEMM + bias + relu
    dim3 aggBlock(32, 8);
    aggregate_kernel<<<(N + 7) / 8, aggBlock>>>(x, N);
    {
        dim3 grid((N + 127) / 128, F / 128);
        gemm1_tc_kernel<<<grid, 256>>>(b1_l, b1_r, N);
    }

    // Layer 2: dual projection, aggregate small, final add
    gemm40_dual_kernel<<<(N + 127) / 128, 256>>>(w2_l, w2_r, N);
    aggregate40_kernel<<<(N + 31) / 32, 320>>>(N);
    final_add_kernel<<<(N * NCLS + 255) / 256, 256>>>(b2_l, b2_r, out, N);
}

// round 9
// speedup vs baseline: 2.0114x; 1.1105x over previous
#include <cuda_runtime.h>
#include <cuda_bf16.h>
#include <cstdint>

// Problem constants (fixed by reference_code)
#define NMAX 50000
#define EMAX 800000
#define F    256
#define AK   512          // concat K for layer-1 GEMM (agg | x)
#define NCLS 40
#define SCAN_TILE 1024
#define NBLK_MAX  64

// ---------------- scratch (static device globals; no runtime allocation) ----
__device__ int   g_is64;
__device__ int   g_deg[NMAX];
__device__ int   g_cursor[NMAX];
__device__ int   g_rowptr[NMAX + 1];
__device__ int   g_col[EMAX];
__device__ int   g_excl[NMAX];
__device__ int   g_blocksum[NBLK_MAX];
__device__ int   g_blockoff[NBLK_MAX];
__device__ float g_invdeg[NMAX];
__device__ __align__(16) __nv_bfloat16 g_Ahi[(size_t)NMAX * AK];  // [agg|x] hi
__device__ __align__(16) __nv_bfloat16 g_Alo[(size_t)NMAX * AK];  // [agg|x] lo
__device__ __align__(16) __nv_bfloat16 g_Bhi[(size_t)F * AK];     // [w1_l|w1_r] hi
__device__ __align__(16) __nv_bfloat16 g_Blo[(size_t)F * AK];     // lo
__device__ __align__(16) float g_h[(size_t)NMAX * F];             // relu(layer1)
__device__ __align__(16) float g_t[(size_t)NMAX * NCLS];          // h @ w2_l^T
__device__ __align__(16) float g_u[(size_t)NMAX * NCLS];          // h @ w2_r^T
__device__ __align__(16) float g_aggt[(size_t)NMAX * NCLS];

// ---------------- PTX helpers ----------------------------------------------
__device__ __forceinline__ void ldsm_x4(uint32_t& r0, uint32_t& r1,
                                        uint32_t& r2, uint32_t& r3, uint32_t addr) {
    asm volatile("ldmatrix.sync.aligned.m8n8.x4.shared.b16 {%0,%1,%2,%3},[%4];"
                 : "=r"(r0), "=r"(r1), "=r"(r2), "=r"(r3) : "r"(addr));
}
__device__ __forceinline__ void mma_bf16(float* c, const uint32_t* a, const uint32_t* b) {
    asm volatile("mma.sync.aligned.m16n8k16.row.col.f32.bf16.bf16.f32 "
                 "{%0,%1,%2,%3},{%4,%5,%6,%7},{%8,%9},{%0,%1,%2,%3};"
                 : "+f"(c[0]), "+f"(c[1]), "+f"(c[2]), "+f"(c[3])
                 : "r"(a[0]), "r"(a[1]), "r"(a[2]), "r"(a[3]), "r"(b[0]), "r"(b[1]));
}
__device__ __forceinline__ void cp16(uint32_t saddr, const void* gaddr, int sz) {
    asm volatile("cp.async.cg.shared.global [%0],[%1],16,%2;"
                 :: "r"(saddr), "l"(gaddr), "r"(sz));
}
__device__ __forceinline__ void cp_wait_all() {
    asm volatile("cp.async.commit_group;");
    asm volatile("cp.async.wait_group 0;");
}

// hi/lo bf16 split of 4 floats
__device__ __forceinline__ void split4(__nv_bfloat16* hi, __nv_bfloat16* lo, float4 v) {
    __nv_bfloat162 h0 = __floats2bfloat162_rn(v.x, v.y);
    __nv_bfloat162 h1 = __floats2bfloat162_rn(v.z, v.w);
    float lx = v.x - __bfloat162float(h0.x);
    float ly = v.y - __bfloat162float(h0.y);
    float lz = v.z - __bfloat162float(h1.x);
    float lw = v.w - __bfloat162float(h1.y);
    *reinterpret_cast<__nv_bfloat162*>(hi)     = h0;
    *reinterpret_cast<__nv_bfloat162*>(hi + 2) = h1;
    *reinterpret_cast<__nv_bfloat162*>(lo)     = __floats2bfloat162_rn(lx, ly);
    *reinterpret_cast<__nv_bfloat162*>(lo + 2) = __floats2bfloat162_rn(lz, lw);
}

// ---------------- edge dtype detection -------------------------------------
__global__ void detect_kernel(const int* __restrict__ v) {
    __shared__ int any_nonzero;
    if (threadIdx.x == 0) any_nonzero = 0;
    __syncthreads();
    if (v[2 * threadIdx.x + 1] != 0) atomicOr(&any_nonzero, 1);
    __syncthreads();
    if (threadIdx.x == 0) g_is64 = (any_nonzero == 0) ? 1 : 0;
}
__device__ __forceinline__ int edge_at(const void* edges, size_t idx) {
    if (g_is64) return (int)((const long long*)edges)[idx];
    return ((const int*)edges)[idx];
}

// ---------------- CSR build ------------------------------------------------
__global__ void zero_counts_kernel(int n) {
    int i = blockIdx.x * blockDim.x + threadIdx.x;
    if (i < n) { g_deg[i] = 0; g_cursor[i] = 0; }
}
__global__ void degree_kernel(const void* __restrict__ edges, int E) {
    int e = blockIdx.x * blockDim.x + threadIdx.x;
    if (e < E) atomicAdd(&g_deg[edge_at(edges, (size_t)E + e)], 1);
}
__device__ __forceinline__ int block_incl_scan(int d, int* total) {
    __shared__ int wsum[32];
    int lane = threadIdx.x & 31, wid = threadIdx.x >> 5;
    int v = d;
#pragma unroll
    for (int o = 1; o < 32; o <<= 1) {
        int t = __shfl_up_sync(0xffffffffu, v, o);
        if (lane >= o) v += t;
    }
    if (lane == 31) wsum[wid] = v;
    __syncthreads();
    if (wid == 0) {
        int w = wsum[lane];
#pragma unroll
        for (int o = 1; o < 32; o <<= 1) {
            int t = __shfl_up_sync(0xffffffffu, w, o);
            if (lane >= o) w += t;
        }
        wsum[lane] = w;
    }
    __syncthreads();
    int incl = v + (wid > 0 ? wsum[wid - 1] : 0);
    *total = wsum[31];
    __syncthreads();
    return incl;
}
__global__ void scan_partial_kernel(int n) {
    int i = blockIdx.x * SCAN_TILE + threadIdx.x;
    int d = (i < n) ? g_deg[i] : 0;
    int total;
    int incl = block_incl_scan(d, &total);
    if (i < n) g_excl[i] = incl - d;
    if (threadIdx.x == 0) g_blocksum[blockIdx.x] = total;
}
__global__ void scan_blocks_kernel(int nb) {
    int d = (threadIdx.x < nb) ? g_blocksum[threadIdx.x] : 0;
    int total;
    int incl = block_incl_scan(d, &total);
    if (threadIdx.x < nb) g_blockoff[threadIdx.x] = incl - d;
}
__global__ void scan_emit_kernel(int n, int E) {
    int i = blockIdx.x * SCAN_TILE + threadIdx.x;
    if (i < n) {
        g_rowptr[i] = g_blockoff[blockIdx.x] + g_excl[i];
        int d = g_deg[i];
        g_invdeg[i] = 1.0f / (float)(d > 0 ? d : 1);
        if (i == n - 1) g_rowptr[n] = E;
    }
}
__global__ void scatter_kernel(const void* __restrict__ edges, int E) {
    int e = blockIdx.x * blockDim.x + threadIdx.x;
    if (e < E) {
        int srcv = edge_at(edges, e);
        int d    = edge_at(edges, (size_t)E + e);
        int p = atomicAdd(&g_cursor[d], 1);
        g_col[g_rowptr[d] + p] = srcv;
    }
}

// ---------------- conversions ----------------------------------------------
__global__ void convert_x_kernel(const float* __restrict__ x, int n) {
    int idx = blockIdx.x * blockDim.x + threadIdx.x;
    if (idx >= n * (F / 4)) return;
    int row = idx / (F / 4), c4 = idx % (F / 4);
    float4 v = *(const float4*)&x[(size_t)row * F + c4 * 4];
    size_t o = (size_t)row * AK + F + c4 * 4;
    split4(&g_Ahi[o], &g_Alo[o], v);
}
__global__ void convert_w_kernel(const float* __restrict__ w1_l,
                                 const float* __restrict__ w1_r) {
    int idx = blockIdx.x * blockDim.x + threadIdx.x;
    if (idx >= F * (F / 4)) return;
    int row = idx / (F / 4), c4 = idx % (F / 4);
    float4 vl = *(const float4*)&w1_l[(size_t)row * F + c4 * 4];
    float4 vr = *(const float4*)&w1_r[(size_t)row * F + c4 * 4];
    size_t ol = (size_t)row * AK + c4 * 4;
    size_t orr = ol + F;
    split4(&g_Bhi[ol], &g_Blo[ol], vl);
    split4(&g_Bhi[orr], &g_Blo[orr], vr);
}

// ---------------- mean aggregation (256-dim) -> bf16 hi/lo cols [0,256) -----
__global__ void aggregate_kernel(const float* __restrict__ feat, int n) {
    int node = blockIdx.x * blockDim.y + threadIdx.y;
    if (node >= n) return;
    int lane = threadIdx.x;
    int beg = g_rowptr[node], end = g_rowptr[node + 1];
    float4 acc0 = make_float4(0.f, 0.f, 0.f, 0.f);
    float4 acc1 = make_float4(0.f, 0.f, 0.f, 0.f);
    for (int e = beg; e < end; e++) {
        const float4* r = (const float4*)&feat[(size_t)g_col[e] * F];
        float4 a = r[lane];
        float4 b = r[lane + 32];
        acc0.x += a.x; acc0.y += a.y; acc0.z += a.z; acc0.w += a.w;
        acc1.x += b.x; acc1.y += b.y; acc1.z += b.z; acc1.w += b.w;
    }
    float s = g_invdeg[node];
    acc0.x *= s; acc0.y *= s; acc0.z *= s; acc0.w *= s;
    acc1.x *= s; acc1.y *= s; acc1.z *= s; acc1.w *= s;
    size_t o0 = (size_t)node * AK + lane * 4;
    size_t o1 = (size_t)node * AK + 128 + lane * 4;
    split4(&g_Ahi[o0], &g_Alo[o0], acc0);
    split4(&g_Ahi[o1], &g_Alo[o1], acc1);
}

// ---------------- GEMM1 (tensor cores, fused split-3, single K sweep) -------
// g_h = relu(A*B^T + bias); C = Ahi*Bhi^T + Ahi*Blo^T + Alo*Bhi^T (fp32 accum)
// BM=128, BN=128, BK=32; 8 warps 2(m)x4(n); warp=64x32; 16 K-chunks.
// Per chunk: load 4 tiles (Ahi,Alo,Bhi,Blo), issue 96 mma/warp.
#define TSTRIDE 40      // bf16 per smem row (80B) -> conflict-free ldsm
#define TILE_B  (128 * TSTRIDE * 2)   // bytes per tile = 10240
__global__ __launch_bounds__(256) void gemm1_tc_kernel(const float* __restrict__ bias0,
                                                       const float* __restrict__ bias1,
                                                       int M) {
    __shared__ __align__(16) __nv_bfloat16 smem[4 * 128 * TSTRIDE];
    const uint32_t sb = (uint32_t)__cvta_generic_to_shared(smem);
    int bm = blockIdx.x * 128, bn = blockIdx.y * 128;
    int tid = threadIdx.x, wid = tid >> 5, lane = tid & 31;
    int wm = (wid >> 2) * 64, wn = (wid & 3) * 32;

    float acc[4][4][4];
#pragma unroll
    for (int mf = 0; mf < 4; mf++)
#pragma unroll
        for (int nf = 0; nf < 4; nf++)
#pragma unroll
            for (int r = 0; r < 4; r++) acc[mf][nf][r] = 0.f;

#pragma unroll 1
    for (int k0 = 0; k0 < AK; k0 += 32) {
        // 2048 cp16 ops (4 tiles x 128 rows x 4 chunks), 8 per thread
#pragma unroll
        for (int i = 0; i < 8; i++) {
            int idx = tid + i * 256;
            int t   = idx >> 9;          // tile 0..3
            int rem = idx & 511;
            int row = rem >> 2, ch = rem & 3;
            uint32_t sa = sb + t * TILE_B + row * 80 + ch * 16;
            if (t < 2) {                 // A tiles: clamp rows >= M
                const __nv_bfloat16* Ag = t ? (const __nv_bfloat16*)g_Alo
                                            : (const __nv_bfloat16*)g_Ahi;
                int grow = bm + row;
                int gr = grow < M ? grow : (M - 1);
                cp16(sa, Ag + (size_t)gr * AK + k0 + ch * 8, grow < M ? 16 : 0);
            } else {                     // B tiles: rows always valid (256)
                const __nv_bfloat16* Bg = (t == 3) ? (const __nv_bfloat16*)g_Blo
                                                   : (const __nv_bfloat16*)g_Bhi;
                cp16(sa, Bg + (size_t)(bn + row) * AK + k0 + ch * 8, 16);
            }
        }
        cp_wait_all();
        __syncthreads();
#pragma unroll
        for (int ks = 0; ks < 32; ks += 16) {
            uint32_t ah[4][4], al[4][4], bh[4][2], bl[4][2];
            int akb = (ks + ((lane >> 4) << 3)) * 2;
#pragma unroll
            for (int mf = 0; mf < 4; mf++) {
                int row = wm + mf * 16 + (lane & 15);
                ldsm_x4(ah[mf][0], ah[mf][1], ah[mf][2], ah[mf][3],
                        sb + 0 * TILE_B + row * 80 + akb);
                ldsm_x4(al[mf][0], al[mf][1], al[mf][2], al[mf][3],
                        sb + 1 * TILE_B + row * 80 + akb);
            }
            int brow0 = wn + ((lane >> 4) << 3) + (lane & 7);
            int bkb = (ks + (((lane >> 3) & 1) << 3)) * 2;
#pragma unroll
            for (int nf2 = 0; nf2 < 2; nf2++) {
                int row = brow0 + nf2 * 16;
                uint32_t r0, r1, r2, r3;
                ldsm_x4(r0, r1, r2, r3, sb + 2 * TILE_B + row * 80 + bkb);
                bh[nf2 * 2][0] = r0; bh[nf2 * 2][1] = r1;
                bh[nf2 * 2 + 1][0] = r2; bh[nf2 * 2 + 1][1] = r3;
                ldsm_x4(r0, r1, r2, r3, sb + 3 * TILE_B + row * 80 + bkb);
                bl[nf2 * 2][0] = r0; bl[nf2 * 2][1] = r1;
                bl[nf2 * 2 + 1][0] = r2; bl[nf2 * 2 + 1][1] = r3;
            }
#pragma unroll
            for (int mf = 0; mf < 4; mf++)
#pragma unroll
                for (int nf = 0; nf < 4; nf++) {
                    mma_bf16(acc[mf][nf], ah[mf], bh[nf]);
                    mma_bf16(acc[mf][nf], ah[mf], bl[nf]);
                    mma_bf16(acc[mf][nf], al[mf], bh[nf]);
                }
        }
        __syncthreads();
    }
    // epilogue: bias + relu -> g_h fp32
#pragma unroll
    for (int nf = 0; nf < 4; nf++) {
        int c = bn + wn + nf * 8 + 2 * (lane & 3);
        float bb0 = bias0[c] + bias1[c];
        float bb1 = bias0[c + 1] + bias1[c + 1];
#pragma unroll
        for (int mf = 0; mf < 4; mf++) {
            int r0 = bm + wm + mf * 16 + (lane >> 2);
            int r1 = r0 + 8;
            if (r0 < M) {
                g_h[(size_t)r0 * F + c]     = fmaxf(acc[mf][nf][0] + bb0, 0.f);
                g_h[(size_t)r0 * F + c + 1] = fmaxf(acc[mf][nf][1] + bb1, 0.f);
            }
            if (r1 < M) {
                g_h[(size_t)r1 * F + c]     = fmaxf(acc[mf][nf][2] + bb0, 0.f);
                g_h[(size_t)r1 * F + c + 1] = fmaxf(acc[mf][nf][3] + bb1, 0.f);
            }
        }
    }
}

// ---------------- dual 40-wide GEMM: g_t = h@w2_l^T, g_u = h@w2_r^T ---------
__global__ void gemm40_dual_kernel(const float* __restrict__ B0,
                                   const float* __restrict__ B1, int M) {
    const int BM = 128, BK = 32, TM = 4, TN = 5;
    __shared__ __align__(16) float As[BK][BM];
    __shared__ __align__(16) float Bs[BK][2 * NCLS];
    int bm = blockIdx.x * BM;
    int tid = threadIdx.x;
    int ty = tid >> 3;
    int tx = tid & 7;

    float accl[TM][TN], accu[TM][TN];
#pragma unroll
    for (int i = 0; i < TM; i++)
#pragma unroll
        for (int j = 0; j < TN; j++) { accl[i][j] = 0.f; accu[i][j] = 0.f; }

#pragma unroll 1
    for (int k0 = 0; k0 < F; k0 += BK) {
#pragma unroll
        for (int it = 0; it < 4; it++) {
            int idx = tid + it * 256;
            int r = idx >> 3;
            int c4 = idx & 7;
            int grow = bm + r;
            float4 v = make_float4(0.f, 0.f, 0.f, 0.f);
            if (grow < M) v = *(const float4*)&g_h[(size_t)grow * F + k0 + c4 * 4];
            As[c4 * 4 + 0][r] = v.x;
            As[c4 * 4 + 1][r] = v.y;
            As[c4 * 4 + 2][r] = v.z;
            As[c4 * 4 + 3][r] = v.w;
        }
        for (int idx = tid; idx < 2 * NCLS * BK / 4; idx += 256) {
            int r = idx >> 3;
            int c4 = idx & 7;
            const float* src = (r < NCLS) ? &B0[(size_t)r * F + k0 + c4 * 4]
                                          : &B1[(size_t)(r - NCLS) * F + k0 + c4 * 4];
            float4 v = *(const float4*)src;
            Bs[c4 * 4 + 0][r] = v.x;
            Bs[c4 * 4 + 1][r] = v.y;
            Bs[c4 * 4 + 2][r] = v.z;
            Bs[c4 * 4 + 3][r] = v.w;
        }
        __syncthreads();
#pragma unroll
        for (int k = 0; k < BK; k++) {
            float4 av4 = *(const float4*)&As[k][ty * TM];
            float a[TM] = {av4.x, av4.y, av4.z, av4.w};
            float bl[TN], bu[TN];
#pragma unroll
            for (int j = 0; j < TN; j++) {
                bl[j] = Bs[k][tx * TN + j];
                bu[j] = Bs[k][NCLS + tx * TN + j];
            }
#pragma unroll
            for (int i = 0; i < TM; i++)
#pragma unroll
                for (int j = 0; j < TN; j++) {
                    accl[i][j] += a[i] * bl[j];
                    accu[i][j] += a[i] * bu[j];
                }
        }
        __syncthreads();
    }
#pragma unroll
    for (int j = 0; j < TN; j++) {
        int gc = tx * TN + j;
#pragma unroll
        for (int i = 0; i < TM; i++) {
            int gr = bm + ty * TM + i;
            if (gr < M) {
                g_t[(size_t)gr * NCLS + gc] = accl[i][j];
                g_u[(size_t)gr * NCLS + gc] = accu[i][j];
            }
        }
    }
}

// ---------------- mean aggregation (40-dim) on g_t -> g_aggt ----------------
__global__ void aggregate40_kernel(int n) {
    int tid = threadIdx.x;
    int node = blockIdx.x * 32 + tid / 10;
    int c4 = tid % 10;
    if (node >= n) return;
    int beg = g_rowptr[node], end = g_rowptr[node + 1];
    float4 acc = make_float4(0.f, 0.f, 0.f, 0.f);
    for (int e = beg; e < end; e++) {
        float4 v = *(const float4*)&g_t[(size_t)g_col[e] * NCLS + c4 * 4];
        acc.x += v.x; acc.y += v.y; acc.z += v.z; acc.w += v.w;
    }
    float s = g_invdeg[node];
    *(float4*)&g_aggt[(size_t)node * NCLS + c4 * 4] =
        make_float4(acc.x * s, acc.y * s, acc.z * s, acc.w * s);
}

// ---------------- final: out = g_aggt + g_u + b2_l + b2_r -------------------
__global__ void final_add_kernel(const float* __restrict__ b0,
                                 const float* __restrict__ b1,
                                 float* __restrict__ out, int n) {
    int i = blockIdx.x * blockDim.x + threadIdx.x;
    if (i < n * NCLS) {
        int c = i % NCLS;
        out[i] = g_aggt[i] + g_u[i] + b0[c] + b1[c];
    }
}

// ---------------- launch --------------------------------------------------
extern "C" void kernel_launch(void* const* d_in, const int* in_sizes, int n_in,
                              void* d_out, int out_size) {
    const float* x     = (const float*)d_in[0];
    const void*  edges = (const void*)d_in[1];
    const float* w1_l = (const float*)d_in[2];
    const float* b1_l = (const float*)d_in[3];
    const float* w1_r = (const float*)d_in[4];
    const float* b1_r = (const float*)d_in[5];
    const float* w2_l = (const float*)d_in[6];
    const float* b2_l = (const float*)d_in[7];
    const float* w2_r = (const float*)d_in[8];
    const float* b2_r = (const float*)d_in[9];
    float* out = (float*)d_out;

    int N = in_sizes[0] / F;
    int E = in_sizes[1] / 2;
    int nb = (N + SCAN_TILE - 1) / SCAN_TILE;

    // dtype probe + CSR build
    detect_kernel<<<1, 256>>>((const int*)edges);
    zero_counts_kernel<<<(N + 255) / 256, 256>>>(N);
    degree_kernel<<<(E + 255) / 256, 256>>>(edges, E);
    scan_partial_kernel<<<nb, SCAN_TILE>>>(N);
    scan_blocks_kernel<<<1, SCAN_TILE>>>(nb);
    scan_emit_kernel<<<nb, SCAN_TILE>>>(N, E);
    scatter_kernel<<<(E + 255) / 256, 256>>>(edges, E);

    // bf16 conversions (independent of CSR)
    convert_x_kernel<<<(N * (F / 4) + 255) / 256, 256>>>(x, N);
    convert_w_kernel<<<(F * (F / 4) + 255) / 256, 256>>>(w1_l, w1_r);

    // Layer 1: agg(x) -> bf16 split; tensor-core GEMM + bias + relu
    dim3 aggBlock(32, 8);
    aggregate_kernel<<<(N + 7) / 8, aggBlock>>>(x, N);
    {
        dim3 grid((N + 127) / 128, F / 128);
        gemm1_tc_kernel<<<grid, 256>>>(b1_l, b1_r, N);
    }

    // Layer 2: dual projection, aggregate small, final add
    gemm40_dual_kernel<<<(N + 127) / 128, 256>>>(w2_l, w2_r, N);
    aggregate40_kernel<<<(N + 31) / 32, 320>>>(N);
    final_add_kernel<<<(N * NCLS + 255) / 256, 256>>>(b2_l, b2_r, out, N);
}

// round 10
// speedup vs baseline: 2.0160x; 1.0023x over previous
#include <cuda_runtime.h>
#include <cuda_bf16.h>
#include <cstdint>

// Problem constants (fixed by reference_code)
#define NMAX 50000
#define EMAX 800000
#define F    256
#define AK   512          // concat K for layer-1 GEMM (agg | x)
#define NCLS 40
#define SCAN_TILE 1024
#define NBLK_MAX  64

// ---------------- scratch (static device globals; no runtime allocation) ----
__device__ int   g_is64;
__device__ int   g_deg[NMAX];
__device__ int   g_cursor[NMAX];
__device__ int   g_rowptr[NMAX + 1];
__device__ int   g_col[EMAX];
__device__ int   g_excl[NMAX];
__device__ int   g_blocksum[NBLK_MAX];
__device__ int   g_blockoff[NBLK_MAX];
__device__ float g_invdeg[NMAX];
__device__ __align__(16) __nv_bfloat16 g_Ahi[(size_t)NMAX * AK];  // [agg|x] hi
__device__ __align__(16) __nv_bfloat16 g_Alo[(size_t)NMAX * AK];  // [agg|x] lo
__device__ __align__(16) __nv_bfloat16 g_Bhi[(size_t)F * AK];     // [w1_l|w1_r] hi
__device__ __align__(16) __nv_bfloat16 g_Blo[(size_t)F * AK];     // lo
__device__ __align__(16) float g_h[(size_t)NMAX * F];             // relu(layer1)
__device__ __align__(16) float g_t[(size_t)NMAX * NCLS];          // h @ w2_l^T
__device__ __align__(16) float g_u[(size_t)NMAX * NCLS];          // h @ w2_r^T
__device__ __align__(16) float g_aggt[(size_t)NMAX * NCLS];

// ---------------- PTX helpers ----------------------------------------------
__device__ __forceinline__ void ldsm_x4(uint32_t& r0, uint32_t& r1,
                                        uint32_t& r2, uint32_t& r3, uint32_t addr) {
    asm volatile("ldmatrix.sync.aligned.m8n8.x4.shared.b16 {%0,%1,%2,%3},[%4];"
                 : "=r"(r0), "=r"(r1), "=r"(r2), "=r"(r3) : "r"(addr));
}
__device__ __forceinline__ void mma_bf16(float* c, const uint32_t* a, const uint32_t* b) {
    asm volatile("mma.sync.aligned.m16n8k16.row.col.f32.bf16.bf16.f32 "
                 "{%0,%1,%2,%3},{%4,%5,%6,%7},{%8,%9},{%0,%1,%2,%3};"
                 : "+f"(c[0]), "+f"(c[1]), "+f"(c[2]), "+f"(c[3])
                 : "r"(a[0]), "r"(a[1]), "r"(a[2]), "r"(a[3]), "r"(b[0]), "r"(b[1]));
}
__device__ __forceinline__ void cp16(uint32_t saddr, const void* gaddr, int sz) {
    asm volatile("cp.async.cg.shared.global [%0],[%1],16,%2;"
                 :: "r"(saddr), "l"(gaddr), "r"(sz));
}
__device__ __forceinline__ void cp_commit() {
    asm volatile("cp.async.commit_group;");
}
template <int N>
__device__ __forceinline__ void cp_wait() {
    asm volatile("cp.async.wait_group %0;" :: "n"(N));
}
__device__ __forceinline__ void cp_wait_all() {
    asm volatile("cp.async.commit_group;");
    asm volatile("cp.async.wait_group 0;");
}

// hi/lo bf16 split of 4 floats
__device__ __forceinline__ void split4(__nv_bfloat16* hi, __nv_bfloat16* lo, float4 v) {
    __nv_bfloat162 h0 = __floats2bfloat162_rn(v.x, v.y);
    __nv_bfloat162 h1 = __floats2bfloat162_rn(v.z, v.w);
    float lx = v.x - __bfloat162float(h0.x);
    float ly = v.y - __bfloat162float(h0.y);
    float lz = v.z - __bfloat162float(h1.x);
    float lw = v.w - __bfloat162float(h1.y);
    *reinterpret_cast<__nv_bfloat162*>(hi)     = h0;
    *reinterpret_cast<__nv_bfloat162*>(hi + 2) = h1;
    *reinterpret_cast<__nv_bfloat162*>(lo)     = __floats2bfloat162_rn(lx, ly);
    *reinterpret_cast<__nv_bfloat162*>(lo + 2) = __floats2bfloat162_rn(lz, lw);
}

// ---------------- edge dtype detection -------------------------------------
__global__ void detect_kernel(const int* __restrict__ v) {
    __shared__ int any_nonzero;
    if (threadIdx.x == 0) any_nonzero = 0;
    __syncthreads();
    if (v[2 * threadIdx.x + 1] != 0) atomicOr(&any_nonzero, 1);
    __syncthreads();
    if (threadIdx.x == 0) g_is64 = (any_nonzero == 0) ? 1 : 0;
}
__device__ __forceinline__ int edge_at(const void* edges, size_t idx) {
    if (g_is64) return (int)((const long long*)edges)[idx];
    return ((const int*)edges)[idx];
}

// ---------------- CSR build ------------------------------------------------
__global__ void zero_counts_kernel(int n) {
    int i = blockIdx.x * blockDim.x + threadIdx.x;
    if (i < n) { g_deg[i] = 0; g_cursor[i] = 0; }
}
__global__ void degree_kernel(const void* __restrict__ edges, int E) {
    int e = blockIdx.x * blockDim.x + threadIdx.x;
    if (e < E) atomicAdd(&g_deg[edge_at(edges, (size_t)E + e)], 1);
}
__device__ __forceinline__ int block_incl_scan(int d, int* total) {
    __shared__ int wsum[32];
    int lane = threadIdx.x & 31, wid = threadIdx.x >> 5;
    int v = d;
#pragma unroll
    for (int o = 1; o < 32; o <<= 1) {
        int t = __shfl_up_sync(0xffffffffu, v, o);
        if (lane >= o) v += t;
    }
    if (lane == 31) wsum[wid] = v;
    __syncthreads();
    if (wid == 0) {
        int w = wsum[lane];
#pragma unroll
        for (int o = 1; o < 32; o <<= 1) {
            int t = __shfl_up_sync(0xffffffffu, w, o);
            if (lane >= o) w += t;
        }
        wsum[lane] = w;
    }
    __syncthreads();
    int incl = v + (wid > 0 ? wsum[wid - 1] : 0);
    *total = wsum[31];
    __syncthreads();
    return incl;
}
__global__ void scan_partial_kernel(int n) {
    int i = blockIdx.x * SCAN_TILE + threadIdx.x;
    int d = (i < n) ? g_deg[i] : 0;
    int total;
    int incl = block_incl_scan(d, &total);
    if (i < n) g_excl[i] = incl - d;
    if (threadIdx.x == 0) g_blocksum[blockIdx.x] = total;
}
__global__ void scan_blocks_kernel(int nb) {
    int d = (threadIdx.x < nb) ? g_blocksum[threadIdx.x] : 0;
    int total;
    int incl = block_incl_scan(d, &total);
    if (threadIdx.x < nb) g_blockoff[threadIdx.x] = incl - d;
}
__global__ void scan_emit_kernel(int n, int E) {
    int i = blockIdx.x * SCAN_TILE + threadIdx.x;
    if (i < n) {
        g_rowptr[i] = g_blockoff[blockIdx.x] + g_excl[i];
        int d = g_deg[i];
        g_invdeg[i] = 1.0f / (float)(d > 0 ? d : 1);
        if (i == n - 1) g_rowptr[n] = E;
    }
}
__global__ void scatter_kernel(const void* __restrict__ edges, int E) {
    int e = blockIdx.x * blockDim.x + threadIdx.x;
    if (e < E) {
        int srcv = edge_at(edges, e);
        int d    = edge_at(edges, (size_t)E + e);
        int p = atomicAdd(&g_cursor[d], 1);
        g_col[g_rowptr[d] + p] = srcv;
    }
}

// ---------------- conversions ----------------------------------------------
__global__ void convert_x_kernel(const float* __restrict__ x, int n) {
    int idx = blockIdx.x * blockDim.x + threadIdx.x;
    if (idx >= n * (F / 4)) return;
    int row = idx / (F / 4), c4 = idx % (F / 4);
    float4 v = *(const float4*)&x[(size_t)row * F + c4 * 4];
    size_t o = (size_t)row * AK + F + c4 * 4;
    split4(&g_Ahi[o], &g_Alo[o], v);
}
__global__ void convert_w_kernel(const float* __restrict__ w1_l,
                                 const float* __restrict__ w1_r) {
    int idx = blockIdx.x * blockDim.x + threadIdx.x;
    if (idx >= F * (F / 4)) return;
    int row = idx / (F / 4), c4 = idx % (F / 4);
    float4 vl = *(const float4*)&w1_l[(size_t)row * F + c4 * 4];
    float4 vr = *(const float4*)&w1_r[(size_t)row * F + c4 * 4];
    size_t ol = (size_t)row * AK + c4 * 4;
    size_t orr = ol + F;
    split4(&g_Bhi[ol], &g_Blo[ol], vl);
    split4(&g_Bhi[orr], &g_Blo[orr], vr);
}

// ---------------- mean aggregation (256-dim) -> bf16 hi/lo cols [0,256) -----
__global__ void aggregate_kernel(const float* __restrict__ feat, int n) {
    int node = blockIdx.x * blockDim.y + threadIdx.y;
    if (node >= n) return;
    int lane = threadIdx.x;
    int beg = g_rowptr[node], end = g_rowptr[node + 1];
    float4 acc0 = make_float4(0.f, 0.f, 0.f, 0.f);
    float4 acc1 = make_float4(0.f, 0.f, 0.f, 0.f);
    for (int e = beg; e < end; e++) {
        const float4* r = (const float4*)&feat[(size_t)g_col[e] * F];
        float4 a = r[lane];
        float4 b = r[lane + 32];
        acc0.x += a.x; acc0.y += a.y; acc0.z += a.z; acc0.w += a.w;
        acc1.x += b.x; acc1.y += b.y; acc1.z += b.z; acc1.w += b.w;
    }
    float s = g_invdeg[node];
    acc0.x *= s; acc0.y *= s; acc0.z *= s; acc0.w *= s;
    acc1.x *= s; acc1.y *= s; acc1.z *= s; acc1.w *= s;
    size_t o0 = (size_t)node * AK + lane * 4;
    size_t o1 = (size_t)node * AK + 128 + lane * 4;
    split4(&g_Ahi[o0], &g_Alo[o0], acc0);
    split4(&g_Ahi[o1], &g_Alo[o1], acc1);
}

// ---------------- GEMM1 (tensor cores, fused split-3, 2-stage pipeline) -----
// g_h = relu(A*B^T + bias); C = Ahi*Bhi^T + Ahi*Blo^T + Alo*Bhi^T (fp32 accum)
// BM=128, BN=128, BK=32; 8 warps 2(m)x4(n); warp=64x32; 16 K-chunks.
// Double-buffered: chunk k+1 loads overlap chunk k's 96 mma/warp.
#define TSTRIDE 40      // bf16 per smem row (80B) -> conflict-free ldsm
#define TILE_B  (128 * TSTRIDE * 2)   // bytes per tile = 10240
#define STAGE_B (4 * TILE_B)          // 4 tiles per stage = 40960
extern __shared__ __align__(16) __nv_bfloat16 g1_smem[];
__global__ __launch_bounds__(256) void gemm1_tc_kernel(const float* __restrict__ bias0,
                                                       const float* __restrict__ bias1,
                                                       int M) {
    const uint32_t sb0 = (uint32_t)__cvta_generic_to_shared(g1_smem);
    int bm = blockIdx.x * 128, bn = blockIdx.y * 128;
    int tid = threadIdx.x, wid = tid >> 5, lane = tid & 31;
    int wm = (wid >> 2) * 64, wn = (wid & 3) * 32;

    float acc[4][4][4];
#pragma unroll
    for (int mf = 0; mf < 4; mf++)
#pragma unroll
        for (int nf = 0; nf < 4; nf++)
#pragma unroll
            for (int r = 0; r < 4; r++) acc[mf][nf][r] = 0.f;

    // load K-chunk kc into stage buffer (8 cp16 per thread), then commit
    auto load_chunk = [&](int kc, int stage) {
        int k0 = kc * 32;
        uint32_t sbase = sb0 + stage * STAGE_B;
#pragma unroll
        for (int i = 0; i < 8; i++) {
            int idx = tid + i * 256;
            int t   = idx >> 9;          // tile 0..3
            int rem = idx & 511;
            int row = rem >> 2, ch = rem & 3;
            uint32_t sa = sbase + t * TILE_B + row * 80 + ch * 16;
            if (t < 2) {                 // A tiles: clamp rows >= M
                const __nv_bfloat16* Ag = t ? (const __nv_bfloat16*)g_Alo
                                            : (const __nv_bfloat16*)g_Ahi;
                int grow = bm + row;
                int gr = grow < M ? grow : (M - 1);
                cp16(sa, Ag + (size_t)gr * AK + k0 + ch * 8, grow < M ? 16 : 0);
            } else {                     // B tiles: rows always valid (256)
                const __nv_bfloat16* Bg = (t == 3) ? (const __nv_bfloat16*)g_Blo
                                                   : (const __nv_bfloat16*)g_Bhi;
                cp16(sa, Bg + (size_t)(bn + row) * AK + k0 + ch * 8, 16);
            }
        }
        cp_commit();
    };

    load_chunk(0, 0);
#pragma unroll 1
    for (int kc = 0; kc < 16; kc++) {
        int stage = kc & 1;
        if (kc + 1 < 16) {
            load_chunk(kc + 1, stage ^ 1);
            cp_wait<1>();               // stage `stage` is ready
        } else {
            cp_wait<0>();
        }
        __syncthreads();
        uint32_t sb = sb0 + stage * STAGE_B;
#pragma unroll
        for (int ks = 0; ks < 32; ks += 16) {
            uint32_t ah[4][4], al[4][4], bh[4][2], bl[4][2];
            int akb = (ks + ((lane >> 4) << 3)) * 2;
#pragma unroll
            for (int mf = 0; mf < 4; mf++) {
                int row = wm + mf * 16 + (lane & 15);
                ldsm_x4(ah[mf][0], ah[mf][1], ah[mf][2], ah[mf][3],
                        sb + 0 * TILE_B + row * 80 + akb);
                ldsm_x4(al[mf][0], al[mf][1], al[mf][2], al[mf][3],
                        sb + 1 * TILE_B + row * 80 + akb);
            }
            int brow0 = wn + ((lane >> 4) << 3) + (lane & 7);
            int bkb = (ks + (((lane >> 3) & 1) << 3)) * 2;
#pragma unroll
            for (int nf2 = 0; nf2 < 2; nf2++) {
                int row = brow0 + nf2 * 16;
                uint32_t r0, r1, r2, r3;
                ldsm_x4(r0, r1, r2, r3, sb + 2 * TILE_B + row * 80 + bkb);
                bh[nf2 * 2][0] = r0; bh[nf2 * 2][1] = r1;
                bh[nf2 * 2 + 1][0] = r2; bh[nf2 * 2 + 1][1] = r3;
                ldsm_x4(r0, r1, r2, r3, sb + 3 * TILE_B + row * 80 + bkb);
                bl[nf2 * 2][0] = r0; bl[nf2 * 2][1] = r1;
                bl[nf2 * 2 + 1][0] = r2; bl[nf2 * 2 + 1][1] = r3;
            }
#pragma unroll
            for (int mf = 0; mf < 4; mf++)
#pragma unroll
                for (int nf = 0; nf < 4; nf++) {
                    mma_bf16(acc[mf][nf], ah[mf], bh[nf]);
                    mma_bf16(acc[mf][nf], ah[mf], bl[nf]);
                    mma_bf16(acc[mf][nf], al[mf], bh[nf]);
                }
        }
        __syncthreads();   // compute(kc) done before next-next load overwrites stage
    }
    // epilogue: bias + relu -> g_h fp32
#pragma unroll
    for (int nf = 0; nf < 4; nf++) {
        int c = bn + wn + nf * 8 + 2 * (lane & 3);
        float bb0 = bias0[c] + bias1[c];
        float bb1 = bias0[c + 1] + bias1[c + 1];
#pragma unroll
        for (int mf = 0; mf < 4; mf++) {
            int r0 = bm + wm + mf * 16 + (lane >> 2);
            int r1 = r0 + 8;
            if (r0 < M) {
                g_h[(size_t)r0 * F + c]     = fmaxf(acc[mf][nf][0] + bb0, 0.f);
                g_h[(size_t)r0 * F + c + 1] = fmaxf(acc[mf][nf][1] + bb1, 0.f);
            }
            if (r1 < M) {
                g_h[(size_t)r1 * F + c]     = fmaxf(acc[mf][nf][2] + bb0, 0.f);
                g_h[(size_t)r1 * F + c + 1] = fmaxf(acc[mf][nf][3] + bb1, 0.f);
            }
        }
    }
}

// ---------------- dual 40-wide GEMM: g_t = h@w2_l^T, g_u = h@w2_r^T ---------
__global__ void gemm40_dual_kernel(const float* __restrict__ B0,
                                   const float* __restrict__ B1, int M) {
    const int BM = 128, BK = 32, TM = 4, TN = 5;
    __shared__ __align__(16) float As[BK][BM];
    __shared__ __align__(16) float Bs[BK][2 * NCLS];
    int bm = blockIdx.x * BM;
    int tid = threadIdx.x;
    int ty = tid >> 3;
    int tx = tid & 7;

    float accl[TM][TN], accu[TM][TN];
#pragma unroll
    for (int i = 0; i < TM; i++)
#pragma unroll
        for (int j = 0; j < TN; j++) { accl[i][j] = 0.f; accu[i][j] = 0.f; }

#pragma unroll 1
    for (int k0 = 0; k0 < F; k0 += BK) {
#pragma unroll
        for (int it = 0; it < 4; it++) {
            int idx = tid + it * 256;
            int r = idx >> 3;
            int c4 = idx & 7;
            int grow = bm + r;
            float4 v = make_float4(0.f, 0.f, 0.f, 0.f);
            if (grow < M) v = *(const float4*)&g_h[(size_t)grow * F + k0 + c4 * 4];
            As[c4 * 4 + 0][r] = v.x;
            As[c4 * 4 + 1][r] = v.y;
            As[c4 * 4 + 2][r] = v.z;
            As[c4 * 4 + 3][r] = v.w;
        }
        for (int idx = tid; idx < 2 * NCLS * BK / 4; idx += 256) {
            int r = idx >> 3;
            int c4 = idx & 7;
            const float* src = (r < NCLS) ? &B0[(size_t)r * F + k0 + c4 * 4]
                                          : &B1[(size_t)(r - NCLS) * F + k0 + c4 * 4];
            float4 v = *(const float4*)src;
            Bs[c4 * 4 + 0][r] = v.x;
            Bs[c4 * 4 + 1][r] = v.y;
            Bs[c4 * 4 + 2][r] = v.z;
            Bs[c4 * 4 + 3][r] = v.w;
        }
        __syncthreads();
#pragma unroll
        for (int k = 0; k < BK; k++) {
            float4 av4 = *(const float4*)&As[k][ty * TM];
            float a[TM] = {av4.x, av4.y, av4.z, av4.w};
            float bl[TN], bu[TN];
#pragma unroll
            for (int j = 0; j < TN; j++) {
                bl[j] = Bs[k][tx * TN + j];
                bu[j] = Bs[k][NCLS + tx * TN + j];
            }
#pragma unroll
            for (int i = 0; i < TM; i++)
#pragma unroll
                for (int j = 0; j < TN; j++) {
                    accl[i][j] += a[i] * bl[j];
                    accu[i][j] += a[i] * bu[j];
                }
        }
        __syncthreads();
    }
#pragma unroll
    for (int j = 0; j < TN; j++) {
        int gc = tx * TN + j;
#pragma unroll
        for (int i = 0; i < TM; i++) {
            int gr = bm + ty * TM + i;
            if (gr < M) {
                g_t[(size_t)gr * NCLS + gc] = accl[i][j];
                g_u[(size_t)gr * NCLS + gc] = accu[i][j];
            }
        }
    }
}

// ---------------- mean aggregation (40-dim) on g_t -> g_aggt ----------------
__global__ void aggregate40_kernel(int n) {
    int tid = threadIdx.x;
    int node = blockIdx.x * 32 + tid / 10;
    int c4 = tid % 10;
    if (node >= n) return;
    int beg = g_rowptr[node], end = g_rowptr[node + 1];
    float4 acc = make_float4(0.f, 0.f, 0.f, 0.f);
    for (int e = beg; e < end; e++) {
        float4 v = *(const float4*)&g_t[(size_t)g_col[e] * NCLS + c4 * 4];
        acc.x += v.x; acc.y += v.y; acc.z += v.z; acc.w += v.w;
    }
    float s = g_invdeg[node];
    *(float4*)&g_aggt[(size_t)node * NCLS + c4 * 4] =
        make_float4(acc.x * s, acc.y * s, acc.z * s, acc.w * s);
}

// ---------------- final: out = g_aggt + g_u + b2_l + b2_r -------------------
__global__ void final_add_kernel(const float* __restrict__ b0,
                                 const float* __restrict__ b1,
                                 float* __restrict__ out, int n) {
    int i = blockIdx.x * blockDim.x + threadIdx.x;
    if (i < n * NCLS) {
        int c = i % NCLS;
        out[i] = g_aggt[i] + g_u[i] + b0[c] + b1[c];
    }
}

// ---------------- launch --------------------------------------------------
extern "C" void kernel_launch(void* const* d_in, const int* in_sizes, int n_in,
                              void* d_out, int out_size) {
    const float* x     = (const float*)d_in[0];
    const void*  edges = (const void*)d_in[1];
    const float* w1_l = (const float*)d_in[2];
    const float* b1_l = (const float*)d_in[3];
    const float* w1_r = (const float*)d_in[4];
    const float* b1_r = (const float*)d_in[5];
    const float* w2_l = (const float*)d_in[6];
    const float* b2_l = (const float*)d_in[7];
    const float* w2_r = (const float*)d_in[8];
    const float* b2_r = (const float*)d_in[9];
    float* out = (float*)d_out;

    int N = in_sizes[0] / F;
    int E = in_sizes[1] / 2;
    int nb = (N + SCAN_TILE - 1) / SCAN_TILE;

    // dtype probe + CSR build
    detect_kernel<<<1, 256>>>((const int*)edges);
    zero_counts_kernel<<<(N + 255) / 256, 256>>>(N);
    degree_kernel<<<(E + 255) / 256, 256>>>(edges, E);
    scan_partial_kernel<<<nb, SCAN_TILE>>>(N);
    scan_blocks_kernel<<<1, SCAN_TILE>>>(nb);
    scan_emit_kernel<<<nb, SCAN_TILE>>>(N, E);
    scatter_kernel<<<(E + 255) / 256, 256>>>(edges, E);

    // bf16 conversions (independent of CSR)
    convert_x_kernel<<<(N * (F / 4) + 255) / 256, 256>>>(x, N);
    convert_w_kernel<<<(F * (F / 4) + 255) / 256, 256>>>(w1_l, w1_r);

    // Layer 1: agg(x) -> bf16 split; tensor-core GEMM + bias + relu
    dim3 aggBlock(32, 8);
    aggregate_kernel<<<(N + 7) / 8, aggBlock>>>(x, N);
    {
        static int smem_set = 0;
        if (!smem_set) {
            cudaFuncSetAttribute(gemm1_tc_kernel,
                                 cudaFuncAttributeMaxDynamicSharedMemorySize,
                                 2 * STAGE_B);
            smem_set = 1;
        }
        dim3 grid((N + 127) / 128, F / 128);
        gemm1_tc_kernel<<<grid, 256, 2 * STAGE_B>>>(b1_l, b1_r, N);
    }

    // Layer 2: dual projection, aggregate small, final add
    gemm40_dual_kernel<<<(N + 127) / 128, 256>>>(w2_l, w2_r, N);
    aggregate40_kernel<<<(N + 31) / 32, 320>>>(N);
    final_add_kernel<<<(N * NCLS + 255) / 256, 256>>>(b2_l, b2_r, out, N);
}

// round 11
// speedup vs baseline: 2.4712x; 1.2258x over previous
#include <cuda_runtime.h>
#include <cuda_bf16.h>
#include <cstdint>

// Problem constants (fixed by reference_code)
#define NMAX 50000
#define EMAX 800000
#define F    256
#define AK   512          // concat K for layer-1 GEMM (agg | x)
#define NCLS 40
#define N2   80           // combined layer-2 output width [w2_l | w2_r]
#define SCAN_TILE 1024
#define NBLK_MAX  64

// ---------------- scratch (static device globals; no runtime allocation) ----
__device__ int   g_is64;
__device__ int   g_deg[NMAX];
__device__ int   g_cursor[NMAX];
__device__ int   g_rowptr[NMAX + 1];
__device__ int   g_col[EMAX];
__device__ int   g_excl[NMAX];
__device__ int   g_blocksum[NBLK_MAX];
__device__ int   g_blockoff[NBLK_MAX];
__device__ float g_invdeg[NMAX];
__device__ __align__(16) __nv_bfloat16 g_Ahi[(size_t)NMAX * AK];  // [agg|x] hi
__device__ __align__(16) __nv_bfloat16 g_Alo[(size_t)NMAX * AK];  // [agg|x] lo
__device__ __align__(16) __nv_bfloat16 g_Bhi[(size_t)F * AK];     // [w1_l|w1_r] hi
__device__ __align__(16) __nv_bfloat16 g_Blo[(size_t)F * AK];     // lo
__device__ __align__(16) __nv_bfloat16 g_Hhi[(size_t)NMAX * F];   // relu(h) hi
__device__ __align__(16) __nv_bfloat16 g_Hlo[(size_t)NMAX * F];   // relu(h) lo
__device__ __align__(16) __nv_bfloat16 g_B2hi[(size_t)N2 * F];    // [w2_l|w2_r] hi
__device__ __align__(16) __nv_bfloat16 g_B2lo[(size_t)N2 * F];    // lo
__device__ __align__(16) float g_t[(size_t)NMAX * NCLS];          // h @ w2_l^T
__device__ __align__(16) float g_u[(size_t)NMAX * NCLS];          // h @ w2_r^T

// ---------------- PTX helpers ----------------------------------------------
__device__ __forceinline__ void ldsm_x4(uint32_t& r0, uint32_t& r1,
                                        uint32_t& r2, uint32_t& r3, uint32_t addr) {
    asm volatile("ldmatrix.sync.aligned.m8n8.x4.shared.b16 {%0,%1,%2,%3},[%4];"
                 : "=r"(r0), "=r"(r1), "=r"(r2), "=r"(r3) : "r"(addr));
}
__device__ __forceinline__ void ldsm_x2(uint32_t& r0, uint32_t& r1, uint32_t addr) {
    asm volatile("ldmatrix.sync.aligned.m8n8.x2.shared.b16 {%0,%1},[%2];"
                 : "=r"(r0), "=r"(r1) : "r"(addr));
}
__device__ __forceinline__ void mma_bf16(float* c, const uint32_t* a, const uint32_t* b) {
    asm volatile("mma.sync.aligned.m16n8k16.row.col.f32.bf16.bf16.f32 "
                 "{%0,%1,%2,%3},{%4,%5,%6,%7},{%8,%9},{%0,%1,%2,%3};"
                 : "+f"(c[0]), "+f"(c[1]), "+f"(c[2]), "+f"(c[3])
                 : "r"(a[0]), "r"(a[1]), "r"(a[2]), "r"(a[3]), "r"(b[0]), "r"(b[1]));
}
__device__ __forceinline__ void cp16(uint32_t saddr, const void* gaddr, int sz) {
    asm volatile("cp.async.cg.shared.global [%0],[%1],16,%2;"
                 :: "r"(saddr), "l"(gaddr), "r"(sz));
}
__device__ __forceinline__ void cp_commit() {
    asm volatile("cp.async.commit_group;");
}
template <int N>
__device__ __forceinline__ void cp_wait() {
    asm volatile("cp.async.wait_group %0;" :: "n"(N));
}
__device__ __forceinline__ void cp_wait_all() {
    asm volatile("cp.async.commit_group;");
    asm volatile("cp.async.wait_group 0;");
}

// hi/lo bf16 split of 4 floats
__device__ __forceinline__ void split4(__nv_bfloat16* hi, __nv_bfloat16* lo, float4 v) {
    __nv_bfloat162 h0 = __floats2bfloat162_rn(v.x, v.y);
    __nv_bfloat162 h1 = __floats2bfloat162_rn(v.z, v.w);
    float lx = v.x - __bfloat162float(h0.x);
    float ly = v.y - __bfloat162float(h0.y);
    float lz = v.z - __bfloat162float(h1.x);
    float lw = v.w - __bfloat162float(h1.y);
    *reinterpret_cast<__nv_bfloat162*>(hi)     = h0;
    *reinterpret_cast<__nv_bfloat162*>(hi + 2) = h1;
    *reinterpret_cast<__nv_bfloat162*>(lo)     = __floats2bfloat162_rn(lx, ly);
    *reinterpret_cast<__nv_bfloat162*>(lo + 2) = __floats2bfloat162_rn(lz, lw);
}

__device__ __forceinline__ int edge_at(const void* edges, size_t idx) {
    if (g_is64) return (int)((const long long*)edges)[idx];
    return ((const int*)edges)[idx];
}

// ---------------- init: zero counters + (block 0) edge-dtype probe ----------
__global__ void init_kernel(const int* __restrict__ v, int n) {
    int i = blockIdx.x * blockDim.x + threadIdx.x;
    if (i < n) { g_deg[i] = 0; g_cursor[i] = 0; }
    if (blockIdx.x == 0) {
        __shared__ int any_nonzero;
        if (threadIdx.x == 0) any_nonzero = 0;
        __syncthreads();
        if (v[2 * threadIdx.x + 1] != 0) atomicOr(&any_nonzero, 1);
        __syncthreads();
        if (threadIdx.x == 0) g_is64 = (any_nonzero == 0) ? 1 : 0;
    }
}

// ---------------- CSR build ------------------------------------------------
__global__ void degree_kernel(const void* __restrict__ edges, int E) {
    int e = blockIdx.x * blockDim.x + threadIdx.x;
    if (e < E) atomicAdd(&g_deg[edge_at(edges, (size_t)E + e)], 1);
}
__device__ __forceinline__ int block_incl_scan(int d, int* total) {
    __shared__ int wsum[32];
    int lane = threadIdx.x & 31, wid = threadIdx.x >> 5;
    int v = d;
#pragma unroll
    for (int o = 1; o < 32; o <<= 1) {
        int t = __shfl_up_sync(0xffffffffu, v, o);
        if (lane >= o) v += t;
    }
    if (lane == 31) wsum[wid] = v;
    __syncthreads();
    if (wid == 0) {
        int w = wsum[lane];
#pragma unroll
        for (int o = 1; o < 32; o <<= 1) {
            int t = __shfl_up_sync(0xffffffffu, w, o);
            if (lane >= o) w += t;
        }
        wsum[lane] = w;
    }
    __syncthreads();
    int incl = v + (wid > 0 ? wsum[wid - 1] : 0);
    *total = wsum[31];
    __syncthreads();
    return incl;
}
__global__ void scan_partial_kernel(int n) {
    int i = blockIdx.x * SCAN_TILE + threadIdx.x;
    int d = (i < n) ? g_deg[i] : 0;
    int total;
    int incl = block_incl_scan(d, &total);
    if (i < n) g_excl[i] = incl - d;
    if (threadIdx.x == 0) g_blocksum[blockIdx.x] = total;
}
__global__ void scan_blocks_kernel(int nb) {
    int d = (threadIdx.x < nb) ? g_blocksum[threadIdx.x] : 0;
    int total;
    int incl = block_incl_scan(d, &total);
    if (threadIdx.x < nb) g_blockoff[threadIdx.x] = incl - d;
}
__global__ void scan_emit_kernel(int n, int E) {
    int i = blockIdx.x * SCAN_TILE + threadIdx.x;
    if (i < n) {
        g_rowptr[i] = g_blockoff[blockIdx.x] + g_excl[i];
        int d = g_deg[i];
        g_invdeg[i] = 1.0f / (float)(d > 0 ? d : 1);
        if (i == n - 1) g_rowptr[n] = E;
    }
}
__global__ void scatter_kernel(const void* __restrict__ edges, int E) {
    int e = blockIdx.x * blockDim.x + threadIdx.x;
    if (e < E) {
        int srcv = edge_at(edges, e);
        int d    = edge_at(edges, (size_t)E + e);
        int p = atomicAdd(&g_cursor[d], 1);
        g_col[g_rowptr[d] + p] = srcv;
    }
}

// ---------------- weight conversions ----------------------------------------
__global__ void convert_w_kernel(const float* __restrict__ w1_l,
                                 const float* __restrict__ w1_r) {
    int idx = blockIdx.x * blockDim.x + threadIdx.x;
    if (idx >= F * (F / 4)) return;
    int row = idx / (F / 4), c4 = idx % (F / 4);
    float4 vl = *(const float4*)&w1_l[(size_t)row * F + c4 * 4];
    float4 vr = *(const float4*)&w1_r[(size_t)row * F + c4 * 4];
    size_t ol = (size_t)row * AK + c4 * 4;
    size_t orr = ol + F;
    split4(&g_Bhi[ol], &g_Blo[ol], vl);
    split4(&g_Bhi[orr], &g_Blo[orr], vr);
}
__global__ void convert_w2_kernel(const float* __restrict__ w2_l,
                                  const float* __restrict__ w2_r) {
    int idx = blockIdx.x * blockDim.x + threadIdx.x;
    if (idx >= N2 * (F / 4)) return;
    int row = idx / (F / 4), c4 = idx % (F / 4);
    const float* src = (row < NCLS) ? &w2_l[(size_t)row * F + c4 * 4]
                                    : &w2_r[(size_t)(row - NCLS) * F + c4 * 4];
    float4 v = *(const float4*)src;
    size_t o = (size_t)row * F + c4 * 4;
    split4(&g_B2hi[o], &g_B2lo[o], v);
}

// ---------------- mean aggregation (256-dim) + x self-split -----------------
// writes agg(x) hi/lo to cols [0,256) and x[node] hi/lo to cols [256,512)
__global__ void aggregate_kernel(const float* __restrict__ feat, int n) {
    int node = blockIdx.x * blockDim.y + threadIdx.y;
    if (node >= n) return;
    int lane = threadIdx.x;
    int beg = g_rowptr[node], end = g_rowptr[node + 1];
    float4 acc0 = make_float4(0.f, 0.f, 0.f, 0.f);
    float4 acc1 = make_float4(0.f, 0.f, 0.f, 0.f);
    for (int e = beg; e < end; e++) {
        const float4* r = (const float4*)&feat[(size_t)g_col[e] * F];
        float4 a = r[lane];
        float4 b = r[lane + 32];
        acc0.x += a.x; acc0.y += a.y; acc0.z += a.z; acc0.w += a.w;
        acc1.x += b.x; acc1.y += b.y; acc1.z += b.z; acc1.w += b.w;
    }
    float s = g_invdeg[node];
    acc0.x *= s; acc0.y *= s; acc0.z *= s; acc0.w *= s;
    acc1.x *= s; acc1.y *= s; acc1.z *= s; acc1.w *= s;
    size_t base = (size_t)node * AK;
    split4(&g_Ahi[base + lane * 4],       &g_Alo[base + lane * 4],       acc0);
    split4(&g_Ahi[base + 128 + lane * 4], &g_Alo[base + 128 + lane * 4], acc1);
    // self row of x -> cols [256,512)
    const float4* r = (const float4*)&feat[(size_t)node * F];
    float4 a = r[lane];
    float4 b = r[lane + 32];
    split4(&g_Ahi[base + F + lane * 4],       &g_Alo[base + F + lane * 4],       a);
    split4(&g_Ahi[base + F + 128 + lane * 4], &g_Alo[base + F + 128 + lane * 4], b);
}

// ---------------- GEMM1 (tensor cores, fused split-3, 2-stage pipeline) -----
// h = relu(A*B^T + bias); C = Ahi*Bhi^T + Ahi*Blo^T + Alo*Bhi^T (fp32 accum)
// Epilogue writes h as bf16 hi/lo (g_Hhi/g_Hlo).
#define TSTRIDE 40      // bf16 per smem row (80B) -> conflict-free ldsm
#define TILE_B  (128 * TSTRIDE * 2)   // bytes per tile = 10240
#define STAGE_B (4 * TILE_B)          // 4 tiles per stage = 40960
extern __shared__ __align__(16) __nv_bfloat16 g1_smem[];
__global__ __launch_bounds__(256) void gemm1_tc_kernel(const float* __restrict__ bias0,
                                                       const float* __restrict__ bias1,
                                                       int M) {
    const uint32_t sb0 = (uint32_t)__cvta_generic_to_shared(g1_smem);
    int bm = blockIdx.x * 128, bn = blockIdx.y * 128;
    int tid = threadIdx.x, wid = tid >> 5, lane = tid & 31;
    int wm = (wid >> 2) * 64, wn = (wid & 3) * 32;

    float acc[4][4][4];
#pragma unroll
    for (int mf = 0; mf < 4; mf++)
#pragma unroll
        for (int nf = 0; nf < 4; nf++)
#pragma unroll
            for (int r = 0; r < 4; r++) acc[mf][nf][r] = 0.f;

    auto load_chunk = [&](int kc, int stage) {
        int k0 = kc * 32;
        uint32_t sbase = sb0 + stage * STAGE_B;
#pragma unroll
        for (int i = 0; i < 8; i++) {
            int idx = tid + i * 256;
            int t   = idx >> 9;
            int rem = idx & 511;
            int row = rem >> 2, ch = rem & 3;
            uint32_t sa = sbase + t * TILE_B + row * 80 + ch * 16;
            if (t < 2) {
                const __nv_bfloat16* Ag = t ? (const __nv_bfloat16*)g_Alo
                                            : (const __nv_bfloat16*)g_Ahi;
                int grow = bm + row;
                int gr = grow < M ? grow : (M - 1);
                cp16(sa, Ag + (size_t)gr * AK + k0 + ch * 8, grow < M ? 16 : 0);
            } else {
                const __nv_bfloat16* Bg = (t == 3) ? (const __nv_bfloat16*)g_Blo
                                                   : (const __nv_bfloat16*)g_Bhi;
                cp16(sa, Bg + (size_t)(bn + row) * AK + k0 + ch * 8, 16);
            }
        }
        cp_commit();
    };

    load_chunk(0, 0);
#pragma unroll 1
    for (int kc = 0; kc < 16; kc++) {
        int stage = kc & 1;
        if (kc + 1 < 16) {
            load_chunk(kc + 1, stage ^ 1);
            cp_wait<1>();
        } else {
            cp_wait<0>();
        }
        __syncthreads();
        uint32_t sb = sb0 + stage * STAGE_B;
#pragma unroll
        for (int ks = 0; ks < 32; ks += 16) {
            uint32_t ah[4][4], al[4][4], bh[4][2], bl[4][2];
            int akb = (ks + ((lane >> 4) << 3)) * 2;
#pragma unroll
            for (int mf = 0; mf < 4; mf++) {
                int row = wm + mf * 16 + (lane & 15);
                ldsm_x4(ah[mf][0], ah[mf][1], ah[mf][2], ah[mf][3],
                        sb + 0 * TILE_B + row * 80 + akb);
                ldsm_x4(al[mf][0], al[mf][1], al[mf][2], al[mf][3],
                        sb + 1 * TILE_B + row * 80 + akb);
            }
            int brow0 = wn + ((lane >> 4) << 3) + (lane & 7);
            int bkb = (ks + (((lane >> 3) & 1) << 3)) * 2;
#pragma unroll
            for (int nf2 = 0; nf2 < 2; nf2++) {
                int row = brow0 + nf2 * 16;
                uint32_t r0, r1, r2, r3;
                ldsm_x4(r0, r1, r2, r3, sb + 2 * TILE_B + row * 80 + bkb);
                bh[nf2 * 2][0] = r0; bh[nf2 * 2][1] = r1;
                bh[nf2 * 2 + 1][0] = r2; bh[nf2 * 2 + 1][1] = r3;
                ldsm_x4(r0, r1, r2, r3, sb + 3 * TILE_B + row * 80 + bkb);
                bl[nf2 * 2][0] = r0; bl[nf2 * 2][1] = r1;
                bl[nf2 * 2 + 1][0] = r2; bl[nf2 * 2 + 1][1] = r3;
            }
#pragma unroll
            for (int mf = 0; mf < 4; mf++)
#pragma unroll
                for (int nf = 0; nf < 4; nf++) {
                    mma_bf16(acc[mf][nf], ah[mf], bh[nf]);
                    mma_bf16(acc[mf][nf], ah[mf], bl[nf]);
                    mma_bf16(acc[mf][nf], al[mf], bh[nf]);
                }
        }
        __syncthreads();
    }
    // epilogue: bias + relu -> h as bf16 hi/lo
#pragma unroll
    for (int nf = 0; nf < 4; nf++) {
        int c = bn + wn + nf * 8 + 2 * (lane & 3);
        float bb0 = bias0[c] + bias1[c];
        float bb1 = bias0[c + 1] + bias1[c + 1];
#pragma unroll
        for (int mf = 0; mf < 4; mf++) {
            int r0 = bm + wm + mf * 16 + (lane >> 2);
            int r1 = r0 + 8;
            if (r0 < M) {
                float v0 = fmaxf(acc[mf][nf][0] + bb0, 0.f);
                float v1 = fmaxf(acc[mf][nf][1] + bb1, 0.f);
                __nv_bfloat162 h = __floats2bfloat162_rn(v0, v1);
                *(__nv_bfloat162*)&g_Hhi[(size_t)r0 * F + c] = h;
                *(__nv_bfloat162*)&g_Hlo[(size_t)r0 * F + c] =
                    __floats2bfloat162_rn(v0 - __bfloat162float(h.x),
                                          v1 - __bfloat162float(h.y));
            }
            if (r1 < M) {
                float v0 = fmaxf(acc[mf][nf][2] + bb0, 0.f);
                float v1 = fmaxf(acc[mf][nf][3] + bb1, 0.f);
                __nv_bfloat162 h = __floats2bfloat162_rn(v0, v1);
                *(__nv_bfloat162*)&g_Hhi[(size_t)r1 * F + c] = h;
                *(__nv_bfloat162*)&g_Hlo[(size_t)r1 * F + c] =
                    __floats2bfloat162_rn(v0 - __bfloat162float(h.x),
                                          v1 - __bfloat162float(h.y));
            }
        }
    }
}

// ---------------- GEMM40 (tensor cores, split-3): g_t|g_u = h @ [w2_l|w2_r]^T
// M x 80, K=256. 8 warps: wqm=wid&3 (32 rows), wnh=wid>>2 (40 cols).
// smem: Hhi(128x32) Hlo B2hi(80x32) B2lo, row stride 80B.
#define A2_B (128 * 80)     // 10240 bytes per A tile
#define B2_B (80 * 80)      // 6400 bytes per B tile
__global__ __launch_bounds__(256) void gemm40_tc_kernel(int M) {
    __shared__ __align__(16) __nv_bfloat16 smem[(2 * A2_B + 2 * B2_B) / 2];
    const uint32_t sb = (uint32_t)__cvta_generic_to_shared(smem);
    int bm = blockIdx.x * 128;
    int tid = threadIdx.x, wid = tid >> 5, lane = tid & 31;
    int wm = (wid & 3) * 32, wn = (wid >> 2) * 40;

    float acc[2][5][4];
#pragma unroll
    for (int mf = 0; mf < 2; mf++)
#pragma unroll
        for (int nf = 0; nf < 5; nf++)
#pragma unroll
            for (int r = 0; r < 4; r++) acc[mf][nf][r] = 0.f;

#pragma unroll 1
    for (int kc = 0; kc < 8; kc++) {
        int k0 = kc * 32;
        // A: 2 tiles x 128 rows x 4 ch = 1024 cp16; B: 2 x 80 x 4 = 640
        for (int idx = tid; idx < 1664; idx += 256) {
            if (idx < 1024) {
                int t = idx >> 9, rem = idx & 511;
                int row = rem >> 2, ch = rem & 3;
                const __nv_bfloat16* Ag = t ? (const __nv_bfloat16*)g_Hlo
                                            : (const __nv_bfloat16*)g_Hhi;
                int grow = bm + row;
                int gr = grow < M ? grow : (M - 1);
                cp16(sb + t * A2_B + row * 80 + ch * 16,
                     Ag + (size_t)gr * F + k0 + ch * 8, grow < M ? 16 : 0);
            } else {
                int j = idx - 1024;
                int t = (j >= 320), r2 = j - t * 320;
                int row = r2 >> 2, ch = r2 & 3;
                const __nv_bfloat16* Bg = t ? (const __nv_bfloat16*)g_B2lo
                                            : (const __nv_bfloat16*)g_B2hi;
                cp16(sb + 2 * A2_B + t * B2_B + row * 80 + ch * 16,
                     Bg + (size_t)row * F + k0 + ch * 8, 16);
            }
        }
        cp_wait_all();
        __syncthreads();
#pragma unroll
        for (int ks = 0; ks < 32; ks += 16) {
            uint32_t ah[2][4], al[2][4], bh[5][2], bl[5][2];
            int akb = (ks + ((lane >> 4) << 3)) * 2;
#pragma unroll
            for (int mf = 0; mf < 2; mf++) {
                int row = wm + mf * 16 + (lane & 15);
                ldsm_x4(ah[mf][0], ah[mf][1], ah[mf][2], ah[mf][3],
                        sb + 0 * A2_B + row * 80 + akb);
                ldsm_x4(al[mf][0], al[mf][1], al[mf][2], al[mf][3],
                        sb + 1 * A2_B + row * 80 + akb);
            }
            int bkb = (ks + (((lane >> 3) & 1) << 3)) * 2;
            int brow0 = wn + ((lane >> 4) << 3) + (lane & 7);
#pragma unroll
            for (int nf2 = 0; nf2 < 2; nf2++) {
                int row = brow0 + nf2 * 16;
                uint32_t r0, r1, r2, r3;
                ldsm_x4(r0, r1, r2, r3, sb + 2 * A2_B + 0 * B2_B + row * 80 + bkb);
                bh[nf2 * 2][0] = r0; bh[nf2 * 2][1] = r1;
                bh[nf2 * 2 + 1][0] = r2; bh[nf2 * 2 + 1][1] = r3;
                ldsm_x4(r0, r1, r2, r3, sb + 2 * A2_B + 1 * B2_B + row * 80 + bkb);
                bl[nf2 * 2][0] = r0; bl[nf2 * 2][1] = r1;
                bl[nf2 * 2 + 1][0] = r2; bl[nf2 * 2 + 1][1] = r3;
            }
            {   // 5th n-frag (rows wn+32..39) via ldsm.x2
                int row = wn + 32 + (lane & 7);
                ldsm_x2(bh[4][0], bh[4][1], sb + 2 * A2_B + 0 * B2_B + row * 80 + bkb);
                ldsm_x2(bl[4][0], bl[4][1], sb + 2 * A2_B + 1 * B2_B + row * 80 + bkb);
            }
#pragma unroll
            for (int mf = 0; mf < 2; mf++)
#pragma unroll
                for (int nf = 0; nf < 5; nf++) {
                    mma_bf16(acc[mf][nf], ah[mf], bh[nf]);
                    mma_bf16(acc[mf][nf], ah[mf], bl[nf]);
                    mma_bf16(acc[mf][nf], al[mf], bh[nf]);
                }
        }
        __syncthreads();
    }
    // epilogue: n-half 0 -> g_t, n-half 1 -> g_u (each 40 cols)
    float* dst = (wid >> 2) ? (float*)g_u : (float*)g_t;
#pragma unroll
    for (int nf = 0; nf < 5; nf++) {
        int c = (wn % 40) + nf * 8 + 2 * (lane & 3);   // col within 40
#pragma unroll
        for (int mf = 0; mf < 2; mf++) {
            int r0 = bm + wm + mf * 16 + (lane >> 2);
            int r1 = r0 + 8;
            if (r0 < M) {
                dst[(size_t)r0 * NCLS + c]     = acc[mf][nf][0];
                dst[(size_t)r0 * NCLS + c + 1] = acc[mf][nf][1];
            }
            if (r1 < M) {
                dst[(size_t)r1 * NCLS + c]     = acc[mf][nf][2];
                dst[(size_t)r1 * NCLS + c + 1] = acc[mf][nf][3];
            }
        }
    }
}

// ---------------- mean aggregation (40-dim) on g_t, fused final -------------
// out[node] = invdeg * sum g_t[nbr] + g_u[node] + b2_l + b2_r
__global__ void aggregate40_final_kernel(const float* __restrict__ b0,
                                         const float* __restrict__ b1,
                                         float* __restrict__ out, int n) {
    int tid = threadIdx.x;
    int node = blockIdx.x * 32 + tid / 10;
    int c4 = tid % 10;
    if (node >= n) return;
    int beg = g_rowptr[node], end = g_rowptr[node + 1];
    float4 acc = make_float4(0.f, 0.f, 0.f, 0.f);
    for (int e = beg; e < end; e++) {
        float4 v = *(const float4*)&g_t[(size_t)g_col[e] * NCLS + c4 * 4];
        acc.x += v.x; acc.y += v.y; acc.z += v.z; acc.w += v.w;
    }
    float s = g_invdeg[node];
    float4 u  = *(const float4*)&g_u[(size_t)node * NCLS + c4 * 4];
    float4 v0 = *(const float4*)&b0[c4 * 4];
    float4 v1 = *(const float4*)&b1[c4 * 4];
    *(float4*)&out[(size_t)node * NCLS + c4 * 4] =
        make_float4(acc.x * s + u.x + v0.x + v1.x,
                    acc.y * s + u.y + v0.y + v1.y,
                    acc.z * s + u.z + v0.z + v1.z,
                    acc.w * s + u.w + v0.w + v1.w);
}

// ---------------- launch --------------------------------------------------
extern "C" void kernel_launch(void* const* d_in, const int* in_sizes, int n_in,
                              void* d_out, int out_size) {
    const float* x     = (const float*)d_in[0];
    const void*  edges = (const void*)d_in[1];
    const float* w1_l = (const float*)d_in[2];
    const float* b1_l = (const float*)d_in[3];
    const float* w1_r = (const float*)d_in[4];
    const float* b1_r = (const float*)d_in[5];
    const float* w2_l = (const float*)d_in[6];
    const float* b2_l = (const float*)d_in[7];
    const float* w2_r = (const float*)d_in[8];
    const float* b2_r = (const float*)d_in[9];
    float* out = (float*)d_out;

    int N = in_sizes[0] / F;
    int E = in_sizes[1] / 2;
    int nb = (N + SCAN_TILE - 1) / SCAN_TILE;

    // init (zero counters + dtype probe) + CSR build
    init_kernel<<<(N + 255) / 256, 256>>>((const int*)edges, N);
    degree_kernel<<<(E + 255) / 256, 256>>>(edges, E);
    scan_partial_kernel<<<nb, SCAN_TILE>>>(N);
    scan_blocks_kernel<<<1, SCAN_TILE>>>(nb);
    scan_emit_kernel<<<nb, SCAN_TILE>>>(N, E);
    scatter_kernel<<<(E + 255) / 256, 256>>>(edges, E);

    // weight conversions (independent of CSR)
    convert_w_kernel<<<(F * (F / 4) + 255) / 256, 256>>>(w1_l, w1_r);
    convert_w2_kernel<<<(N2 * (F / 4) + 255) / 256, 256>>>(w2_l, w2_r);

    // Layer 1: agg(x) + self-split -> tensor-core GEMM + bias + relu (h bf16)
    dim3 aggBlock(32, 8);
    aggregate_kernel<<<(N + 7) / 8, aggBlock>>>(x, N);
    {
        static int smem_set = 0;
        if (!smem_set) {
            cudaFuncSetAttribute(gemm1_tc_kernel,
                                 cudaFuncAttributeMaxDynamicSharedMemorySize,
                                 2 * STAGE_B);
            smem_set = 1;
        }
        dim3 grid((N + 127) / 128, F / 128);
        gemm1_tc_kernel<<<grid, 256, 2 * STAGE_B>>>(b1_l, b1_r, N);
    }

    // Layer 2: TC dual projection, fused aggregate+final
    gemm40_tc_kernel<<<(N + 127) / 128, 256>>>(N);
    aggregate40_final_kernel<<<(N + 31) / 32, 320>>>(b2_l, b2_r, out, N);
}

// round 12
// speedup vs baseline: 2.5036x; 1.0131x over previous
#include <cuda_runtime.h>
#include <cuda_bf16.h>
#include <cstdint>

// Problem constants (fixed by reference_code)
#define NMAX 50000
#define EMAX 800000
#define F    256
#define AK   512          // concat K for layer-1 GEMM (agg | x)
#define NCLS 40
#define N2   80           // combined layer-2 output width [w2_l | w2_r]
#define SCAN_TILE 1024
#define NBLK_MAX  64

// ---------------- scratch (static device globals; no runtime allocation) ----
__device__ int   g_is64;
__device__ int   g_deg[NMAX];
__device__ int   g_cursor[NMAX];
__device__ int   g_rowptr[NMAX + 1];
__device__ int   g_col[EMAX];
__device__ unsigned long long g_scan_state[NBLK_MAX];  // (flag<<62)|value
__device__ int   g_scan_ticket;
__device__ float g_invdeg[NMAX];
__device__ __align__(16) __nv_bfloat16 g_Ahi[(size_t)NMAX * AK];  // [agg|x] hi
__device__ __align__(16) __nv_bfloat16 g_Alo[(size_t)NMAX * AK];  // [agg|x] lo
__device__ __align__(16) __nv_bfloat16 g_Bhi[(size_t)F * AK];     // [w1_l|w1_r] hi
__device__ __align__(16) __nv_bfloat16 g_Blo[(size_t)F * AK];     // lo
__device__ __align__(16) __nv_bfloat16 g_Hhi[(size_t)NMAX * F];   // relu(h) hi
__device__ __align__(16) __nv_bfloat16 g_Hlo[(size_t)NMAX * F];   // relu(h) lo
__device__ __align__(16) __nv_bfloat16 g_B2hi[(size_t)N2 * F];    // [w2_l|w2_r] hi
__device__ __align__(16) __nv_bfloat16 g_B2lo[(size_t)N2 * F];    // lo
__device__ __align__(16) float g_t[(size_t)NMAX * NCLS];          // h @ w2_l^T
__device__ __align__(16) float g_u[(size_t)NMAX * NCLS];          // h @ w2_r^T

// ---------------- PTX helpers ----------------------------------------------
__device__ __forceinline__ void ldsm_x4(uint32_t& r0, uint32_t& r1,
                                        uint32_t& r2, uint32_t& r3, uint32_t addr) {
    asm volatile("ldmatrix.sync.aligned.m8n8.x4.shared.b16 {%0,%1,%2,%3},[%4];"
                 : "=r"(r0), "=r"(r1), "=r"(r2), "=r"(r3) : "r"(addr));
}
__device__ __forceinline__ void ldsm_x2(uint32_t& r0, uint32_t& r1, uint32_t addr) {
    asm volatile("ldmatrix.sync.aligned.m8n8.x2.shared.b16 {%0,%1},[%2];"
                 : "=r"(r0), "=r"(r1) : "r"(addr));
}
__device__ __forceinline__ void mma_bf16(float* c, const uint32_t* a, const uint32_t* b) {
    asm volatile("mma.sync.aligned.m16n8k16.row.col.f32.bf16.bf16.f32 "
                 "{%0,%1,%2,%3},{%4,%5,%6,%7},{%8,%9},{%0,%1,%2,%3};"
                 : "+f"(c[0]), "+f"(c[1]), "+f"(c[2]), "+f"(c[3])
                 : "r"(a[0]), "r"(a[1]), "r"(a[2]), "r"(a[3]), "r"(b[0]), "r"(b[1]));
}
__device__ __forceinline__ void cp16(uint32_t saddr, const void* gaddr, int sz) {
    asm volatile("cp.async.cg.shared.global [%0],[%1],16,%2;"
                 :: "r"(saddr), "l"(gaddr), "r"(sz));
}
__device__ __forceinline__ void cp_commit() {
    asm volatile("cp.async.commit_group;");
}
template <int N>
__device__ __forceinline__ void cp_wait() {
    asm volatile("cp.async.wait_group %0;" :: "n"(N));
}
__device__ __forceinline__ void cp_wait_all() {
    asm volatile("cp.async.commit_group;");
    asm volatile("cp.async.wait_group 0;");
}

// hi/lo bf16 split of 4 floats
__device__ __forceinline__ void split4(__nv_bfloat16* hi, __nv_bfloat16* lo, float4 v) {
    __nv_bfloat162 h0 = __floats2bfloat162_rn(v.x, v.y);
    __nv_bfloat162 h1 = __floats2bfloat162_rn(v.z, v.w);
    float lx = v.x - __bfloat162float(h0.x);
    float ly = v.y - __bfloat162float(h0.y);
    float lz = v.z - __bfloat162float(h1.x);
    float lw = v.w - __bfloat162float(h1.y);
    *reinterpret_cast<__nv_bfloat162*>(hi)     = h0;
    *reinterpret_cast<__nv_bfloat162*>(hi + 2) = h1;
    *reinterpret_cast<__nv_bfloat162*>(lo)     = __floats2bfloat162_rn(lx, ly);
    *reinterpret_cast<__nv_bfloat162*>(lo + 2) = __floats2bfloat162_rn(lz, lw);
}

__device__ __forceinline__ int edge_at(const void* edges, size_t idx) {
    if (g_is64) return (int)((const long long*)edges)[idx];
    return ((const int*)edges)[idx];
}

// ---------------- init: zero counters + scan state + dtype probe ------------
__global__ void init_kernel(const int* __restrict__ v, int n) {
    int i = blockIdx.x * blockDim.x + threadIdx.x;
    if (i < n) { g_deg[i] = 0; g_cursor[i] = 0; }
    if (blockIdx.x == 0) {
        if (threadIdx.x < NBLK_MAX) g_scan_state[threadIdx.x] = 0ULL;
        __shared__ int any_nonzero;
        if (threadIdx.x == 0) { any_nonzero = 0; g_scan_ticket = 0; }
        __syncthreads();
        if (v[2 * threadIdx.x + 1] != 0) atomicOr(&any_nonzero, 1);
        __syncthreads();
        if (threadIdx.x == 0) g_is64 = (any_nonzero == 0) ? 1 : 0;
    }
}

// ---------------- CSR build ------------------------------------------------
__global__ void degree_kernel(const void* __restrict__ edges, int E) {
    int e = blockIdx.x * blockDim.x + threadIdx.x;
    if (e < E) atomicAdd(&g_deg[edge_at(edges, (size_t)E + e)], 1);
}
__device__ __forceinline__ int block_incl_scan(int d, int* total) {
    __shared__ int wsum[32];
    int lane = threadIdx.x & 31, wid = threadIdx.x >> 5;
    int v = d;
#pragma unroll
    for (int o = 1; o < 32; o <<= 1) {
        int t = __shfl_up_sync(0xffffffffu, v, o);
        if (lane >= o) v += t;
    }
    if (lane == 31) wsum[wid] = v;
    __syncthreads();
    if (wid == 0) {
        int w = wsum[lane];
#pragma unroll
        for (int o = 1; o < 32; o <<= 1) {
            int t = __shfl_up_sync(0xffffffffu, w, o);
            if (lane >= o) w += t;
        }
        wsum[lane] = w;
    }
    __syncthreads();
    int incl = v + (wid > 0 ? wsum[wid - 1] : 0);
    *total = wsum[31];
    __syncthreads();
    return incl;
}

// single-pass decoupled-lookback scan: g_deg -> g_rowptr (+invdeg, rowptr[n])
__global__ void scan_lookback_kernel(int n, int E) {
    __shared__ int s_bid;
    __shared__ int s_prefix;
    if (threadIdx.x == 0) s_bid = atomicAdd(&g_scan_ticket, 1);
    __syncthreads();
    int bid = s_bid;
    int i = bid * SCAN_TILE + threadIdx.x;
    int d = (i < n) ? g_deg[i] : 0;
    int total;
    int incl = block_incl_scan(d, &total);
    if (threadIdx.x == 0) {
        if (bid == 0) {
            atomicExch(&g_scan_state[0], (2ULL << 62) | (unsigned)total);
            s_prefix = 0;
        } else {
            atomicExch(&g_scan_state[bid], (1ULL << 62) | (unsigned)total);
            int prefix = 0;
            int j = bid - 1;
            while (j >= 0) {
                unsigned long long st = atomicAdd(&g_scan_state[j], 0ULL);
                unsigned long long flag = st >> 62;
                if (flag == 2) { prefix += (int)(st & 0xFFFFFFFFu); break; }
                if (flag == 1) { prefix += (int)(st & 0xFFFFFFFFu); j--; }
            }
            atomicExch(&g_scan_state[bid], (2ULL << 62) | (unsigned)(prefix + total));
            s_prefix = prefix;
        }
    }
    __syncthreads();
    if (i < n) {
        g_rowptr[i] = s_prefix + incl - d;
        g_invdeg[i] = 1.0f / (float)(d > 0 ? d : 1);
        if (i == n - 1) g_rowptr[n] = E;
    }
}

__global__ void scatter_kernel(const void* __restrict__ edges, int E) {
    int e = blockIdx.x * blockDim.x + threadIdx.x;
    if (e < E) {
        int srcv = edge_at(edges, e);
        int d    = edge_at(edges, (size_t)E + e);
        int p = atomicAdd(&g_cursor[d], 1);
        g_col[g_rowptr[d] + p] = srcv;
    }
}

// ---------------- merged weight conversions ---------------------------------
#define W1_Q (F * (F / 4))          // 16384 float4s
#define W2_Q (N2 * (F / 4))         // 5120 float4s
__global__ void convert_weights_kernel(const float* __restrict__ w1_l,
                                       const float* __restrict__ w1_r,
                                       const float* __restrict__ w2_l,
                                       const float* __restrict__ w2_r) {
    int idx = blockIdx.x * blockDim.x + threadIdx.x;
    if (idx < W1_Q) {
        int row = idx / (F / 4), c4 = idx % (F / 4);
        float4 vl = *(const float4*)&w1_l[(size_t)row * F + c4 * 4];
        float4 vr = *(const float4*)&w1_r[(size_t)row * F + c4 * 4];
        size_t ol = (size_t)row * AK + c4 * 4;
        split4(&g_Bhi[ol], &g_Blo[ol], vl);
        split4(&g_Bhi[ol + F], &g_Blo[ol + F], vr);
    } else if (idx < W1_Q + W2_Q) {
        int j = idx - W1_Q;
        int row = j / (F / 4), c4 = j % (F / 4);
        const float* src = (row < NCLS) ? &w2_l[(size_t)row * F + c4 * 4]
                                        : &w2_r[(size_t)(row - NCLS) * F + c4 * 4];
        float4 v = *(const float4*)src;
        size_t o = (size_t)row * F + c4 * 4;
        split4(&g_B2hi[o], &g_B2lo[o], v);
    }
}

// ---------------- mean aggregation (256-dim) + x self-split, 2-way unrolled -
__global__ void aggregate_kernel(const float* __restrict__ feat, int n) {
    int node = blockIdx.x * blockDim.y + threadIdx.y;
    if (node >= n) return;
    int lane = threadIdx.x;
    int beg = g_rowptr[node], end = g_rowptr[node + 1];
    float4 acc0 = make_float4(0.f, 0.f, 0.f, 0.f);
    float4 acc1 = make_float4(0.f, 0.f, 0.f, 0.f);
    int e = beg;
    for (; e + 2 <= end; e += 2) {
        const float4* r0 = (const float4*)&feat[(size_t)g_col[e] * F];
        const float4* r1 = (const float4*)&feat[(size_t)g_col[e + 1] * F];
        float4 a0 = r0[lane], b0 = r0[lane + 32];
        float4 a1 = r1[lane], b1 = r1[lane + 32];
        acc0.x += a0.x + a1.x; acc0.y += a0.y + a1.y;
        acc0.z += a0.z + a1.z; acc0.w += a0.w + a1.w;
        acc1.x += b0.x + b1.x; acc1.y += b0.y + b1.y;
        acc1.z += b0.z + b1.z; acc1.w += b0.w + b1.w;
    }
    if (e < end) {
        const float4* r = (const float4*)&feat[(size_t)g_col[e] * F];
        float4 a = r[lane], b = r[lane + 32];
        acc0.x += a.x; acc0.y += a.y; acc0.z += a.z; acc0.w += a.w;
        acc1.x += b.x; acc1.y += b.y; acc1.z += b.z; acc1.w += b.w;
    }
    float s = g_invdeg[node];
    acc0.x *= s; acc0.y *= s; acc0.z *= s; acc0.w *= s;
    acc1.x *= s; acc1.y *= s; acc1.z *= s; acc1.w *= s;
    size_t base = (size_t)node * AK;
    split4(&g_Ahi[base + lane * 4],       &g_Alo[base + lane * 4],       acc0);
    split4(&g_Ahi[base + 128 + lane * 4], &g_Alo[base + 128 + lane * 4], acc1);
    const float4* r = (const float4*)&feat[(size_t)node * F];
    float4 a = r[lane];
    float4 b = r[lane + 32];
    split4(&g_Ahi[base + F + lane * 4],       &g_Alo[base + F + lane * 4],       a);
    split4(&g_Ahi[base + F + 128 + lane * 4], &g_Alo[base + F + 128 + lane * 4], b);
}

// ---------------- GEMM1 (tensor cores, fused split-3, 2-stage pipeline) -----
#define TSTRIDE 40
#define TILE_B  (128 * TSTRIDE * 2)
#define STAGE_B (4 * TILE_B)
extern __shared__ __align__(16) __nv_bfloat16 g1_smem[];
__global__ __launch_bounds__(256) void gemm1_tc_kernel(const float* __restrict__ bias0,
                                                       const float* __restrict__ bias1,
                                                       int M) {
    const uint32_t sb0 = (uint32_t)__cvta_generic_to_shared(g1_smem);
    int bm = blockIdx.x * 128, bn = blockIdx.y * 128;
    int tid = threadIdx.x, wid = tid >> 5, lane = tid & 31;
    int wm = (wid >> 2) * 64, wn = (wid & 3) * 32;

    float acc[4][4][4];
#pragma unroll
    for (int mf = 0; mf < 4; mf++)
#pragma unroll
        for (int nf = 0; nf < 4; nf++)
#pragma unroll
            for (int r = 0; r < 4; r++) acc[mf][nf][r] = 0.f;

    auto load_chunk = [&](int kc, int stage) {
        int k0 = kc * 32;
        uint32_t sbase = sb0 + stage * STAGE_B;
#pragma unroll
        for (int i = 0; i < 8; i++) {
            int idx = tid + i * 256;
            int t   = idx >> 9;
            int rem = idx & 511;
            int row = rem >> 2, ch = rem & 3;
            uint32_t sa = sbase + t * TILE_B + row * 80 + ch * 16;
            if (t < 2) {
                const __nv_bfloat16* Ag = t ? (const __nv_bfloat16*)g_Alo
                                            : (const __nv_bfloat16*)g_Ahi;
                int grow = bm + row;
                int gr = grow < M ? grow : (M - 1);
                cp16(sa, Ag + (size_t)gr * AK + k0 + ch * 8, grow < M ? 16 : 0);
            } else {
                const __nv_bfloat16* Bg = (t == 3) ? (const __nv_bfloat16*)g_Blo
                                                   : (const __nv_bfloat16*)g_Bhi;
                cp16(sa, Bg + (size_t)(bn + row) * AK + k0 + ch * 8, 16);
            }
        }
        cp_commit();
    };

    load_chunk(0, 0);
#pragma unroll 1
    for (int kc = 0; kc < 16; kc++) {
        int stage = kc & 1;
        if (kc + 1 < 16) {
            load_chunk(kc + 1, stage ^ 1);
            cp_wait<1>();
        } else {
            cp_wait<0>();
        }
        __syncthreads();
        uint32_t sb = sb0 + stage * STAGE_B;
#pragma unroll
        for (int ks = 0; ks < 32; ks += 16) {
            uint32_t ah[4][4], al[4][4], bh[4][2], bl[4][2];
            int akb = (ks + ((lane >> 4) << 3)) * 2;
#pragma unroll
            for (int mf = 0; mf < 4; mf++) {
                int row = wm + mf * 16 + (lane & 15);
                ldsm_x4(ah[mf][0], ah[mf][1], ah[mf][2], ah[mf][3],
                        sb + 0 * TILE_B + row * 80 + akb);
                ldsm_x4(al[mf][0], al[mf][1], al[mf][2], al[mf][3],
                        sb + 1 * TILE_B + row * 80 + akb);
            }
            int brow0 = wn + ((lane >> 4) << 3) + (lane & 7);
            int bkb = (ks + (((lane >> 3) & 1) << 3)) * 2;
#pragma unroll
            for (int nf2 = 0; nf2 < 2; nf2++) {
                int row = brow0 + nf2 * 16;
                uint32_t r0, r1, r2, r3;
                ldsm_x4(r0, r1, r2, r3, sb + 2 * TILE_B + row * 80 + bkb);
                bh[nf2 * 2][0] = r0; bh[nf2 * 2][1] = r1;
                bh[nf2 * 2 + 1][0] = r2; bh[nf2 * 2 + 1][1] = r3;
                ldsm_x4(r0, r1, r2, r3, sb + 3 * TILE_B + row * 80 + bkb);
                bl[nf2 * 2][0] = r0; bl[nf2 * 2][1] = r1;
                bl[nf2 * 2 + 1][0] = r2; bl[nf2 * 2 + 1][1] = r3;
            }
#pragma unroll
            for (int mf = 0; mf < 4; mf++)
#pragma unroll
                for (int nf = 0; nf < 4; nf++) {
                    mma_bf16(acc[mf][nf], ah[mf], bh[nf]);
                    mma_bf16(acc[mf][nf], ah[mf], bl[nf]);
                    mma_bf16(acc[mf][nf], al[mf], bh[nf]);
                }
        }
        __syncthreads();
    }
#pragma unroll
    for (int nf = 0; nf < 4; nf++) {
        int c = bn + wn + nf * 8 + 2 * (lane & 3);
        float bb0 = bias0[c] + bias1[c];
        float bb1 = bias0[c + 1] + bias1[c + 1];
#pragma unroll
        for (int mf = 0; mf < 4; mf++) {
            int r0 = bm + wm + mf * 16 + (lane >> 2);
            int r1 = r0 + 8;
            if (r0 < M) {
                float v0 = fmaxf(acc[mf][nf][0] + bb0, 0.f);
                float v1 = fmaxf(acc[mf][nf][1] + bb1, 0.f);
                __nv_bfloat162 h = __floats2bfloat162_rn(v0, v1);
                *(__nv_bfloat162*)&g_Hhi[(size_t)r0 * F + c] = h;
                *(__nv_bfloat162*)&g_Hlo[(size_t)r0 * F + c] =
                    __floats2bfloat162_rn(v0 - __bfloat162float(h.x),
                                          v1 - __bfloat162float(h.y));
            }
            if (r1 < M) {
                float v0 = fmaxf(acc[mf][nf][2] + bb0, 0.f);
                float v1 = fmaxf(acc[mf][nf][3] + bb1, 0.f);
                __nv_bfloat162 h = __floats2bfloat162_rn(v0, v1);
                *(__nv_bfloat162*)&g_Hhi[(size_t)r1 * F + c] = h;
                *(__nv_bfloat162*)&g_Hlo[(size_t)r1 * F + c] =
                    __floats2bfloat162_rn(v0 - __bfloat162float(h.x),
                                          v1 - __bfloat162float(h.y));
            }
        }
    }
}

// ---------------- GEMM40 (tensor cores, split-3): g_t|g_u = h @ [w2_l|w2_r]^T
#define A2_B (128 * 80)
#define B2_B (80 * 80)
__global__ __launch_bounds__(256) void gemm40_tc_kernel(int M) {
    __shared__ __align__(16) __nv_bfloat16 smem[(2 * A2_B + 2 * B2_B) / 2];
    const uint32_t sb = (uint32_t)__cvta_generic_to_shared(smem);
    int bm = blockIdx.x * 128;
    int tid = threadIdx.x, wid = tid >> 5, lane = tid & 31;
    int wm = (wid & 3) * 32, wn = (wid >> 2) * 40;

    float acc[2][5][4];
#pragma unroll
    for (int mf = 0; mf < 2; mf++)
#pragma unroll
        for (int nf = 0; nf < 5; nf++)
#pragma unroll
            for (int r = 0; r < 4; r++) acc[mf][nf][r] = 0.f;

#pragma unroll 1
    for (int kc = 0; kc < 8; kc++) {
        int k0 = kc * 32;
        for (int idx = tid; idx < 1664; idx += 256) {
            if (idx < 1024) {
                int t = idx >> 9, rem = idx & 511;
                int row = rem >> 2, ch = rem & 3;
                const __nv_bfloat16* Ag = t ? (const __nv_bfloat16*)g_Hlo
                                            : (const __nv_bfloat16*)g_Hhi;
                int grow = bm + row;
                int gr = grow < M ? grow : (M - 1);
                cp16(sb + t * A2_B + row * 80 + ch * 16,
                     Ag + (size_t)gr * F + k0 + ch * 8, grow < M ? 16 : 0);
            } else {
                int j = idx - 1024;
                int t = (j >= 320), r2 = j - t * 320;
                int row = r2 >> 2, ch = r2 & 3;
                const __nv_bfloat16* Bg = t ? (const __nv_bfloat16*)g_B2lo
                                            : (const __nv_bfloat16*)g_B2hi;
                cp16(sb + 2 * A2_B + t * B2_B + row * 80 + ch * 16,
                     Bg + (size_t)row * F + k0 + ch * 8, 16);
            }
        }
        cp_wait_all();
        __syncthreads();
#pragma unroll
        for (int ks = 0; ks < 32; ks += 16) {
            uint32_t ah[2][4], al[2][4], bh[5][2], bl[5][2];
            int akb = (ks + ((lane >> 4) << 3)) * 2;
#pragma unroll
            for (int mf = 0; mf < 2; mf++) {
                int row = wm + mf * 16 + (lane & 15);
                ldsm_x4(ah[mf][0], ah[mf][1], ah[mf][2], ah[mf][3],
                        sb + 0 * A2_B + row * 80 + akb);
                ldsm_x4(al[mf][0], al[mf][1], al[mf][2], al[mf][3],
                        sb + 1 * A2_B + row * 80 + akb);
            }
            int bkb = (ks + (((lane >> 3) & 1) << 3)) * 2;
            int brow0 = wn + ((lane >> 4) << 3) + (lane & 7);
#pragma unroll
            for (int nf2 = 0; nf2 < 2; nf2++) {
                int row = brow0 + nf2 * 16;
                uint32_t r0, r1, r2, r3;
                ldsm_x4(r0, r1, r2, r3, sb + 2 * A2_B + 0 * B2_B + row * 80 + bkb);
                bh[nf2 * 2][0] = r0; bh[nf2 * 2][1] = r1;
                bh[nf2 * 2 + 1][0] = r2; bh[nf2 * 2 + 1][1] = r3;
                ldsm_x4(r0, r1, r2, r3, sb + 2 * A2_B + 1 * B2_B + row * 80 + bkb);
                bl[nf2 * 2][0] = r0; bl[nf2 * 2][1] = r1;
                bl[nf2 * 2 + 1][0] = r2; bl[nf2 * 2 + 1][1] = r3;
            }
            {
                int row = wn + 32 + (lane & 7);
                ldsm_x2(bh[4][0], bh[4][1], sb + 2 * A2_B + 0 * B2_B + row * 80 + bkb);
                ldsm_x2(bl[4][0], bl[4][1], sb + 2 * A2_B + 1 * B2_B + row * 80 + bkb);
            }
#pragma unroll
            for (int mf = 0; mf < 2; mf++)
#pragma unroll
                for (int nf = 0; nf < 5; nf++) {
                    mma_bf16(acc[mf][nf], ah[mf], bh[nf]);
                    mma_bf16(acc[mf][nf], ah[mf], bl[nf]);
                    mma_bf16(acc[mf][nf], al[mf], bh[nf]);
                }
        }
        __syncthreads();
    }
    float* dst = (wid >> 2) ? (float*)g_u : (float*)g_t;
#pragma unroll
    for (int nf = 0; nf < 5; nf++) {
        int c = (wn % 40) + nf * 8 + 2 * (lane & 3);
#pragma unroll
        for (int mf = 0; mf < 2; mf++) {
            int r0 = bm + wm + mf * 16 + (lane >> 2);
            int r1 = r0 + 8;
            if (r0 < M) {
                dst[(size_t)r0 * NCLS + c]     = acc[mf][nf][0];
                dst[(size_t)r0 * NCLS + c + 1] = acc[mf][nf][1];
            }
            if (r1 < M) {
                dst[(size_t)r1 * NCLS + c]     = acc[mf][nf][2];
                dst[(size_t)r1 * NCLS + c + 1] = acc[mf][nf][3];
            }
        }
    }
}

// ---------------- mean aggregation (40-dim) on g_t, fused final, 4-unrolled -
__global__ void aggregate40_final_kernel(const float* __restrict__ b0,
                                         const float* __restrict__ b1,
                                         float* __restrict__ out, int n) {
    int tid = threadIdx.x;
    int node = blockIdx.x * 32 + tid / 10;
    int c4 = tid % 10;
    if (node >= n) return;
    int beg = g_rowptr[node], end = g_rowptr[node + 1];
    float4 acc = make_float4(0.f, 0.f, 0.f, 0.f);
    int e = beg;
    for (; e + 4 <= end; e += 4) {
        int c0 = g_col[e], c1 = g_col[e + 1], c2 = g_col[e + 2], c3 = g_col[e + 3];
        float4 v0 = *(const float4*)&g_t[(size_t)c0 * NCLS + c4 * 4];
        float4 v1 = *(const float4*)&g_t[(size_t)c1 * NCLS + c4 * 4];
        float4 v2 = *(const float4*)&g_t[(size_t)c2 * NCLS + c4 * 4];
        float4 v3 = *(const float4*)&g_t[(size_t)c3 * NCLS + c4 * 4];
        acc.x += (v0.x + v1.x) + (v2.x + v3.x);
        acc.y += (v0.y + v1.y) + (v2.y + v3.y);
        acc.z += (v0.z + v1.z) + (v2.z + v3.z);
        acc.w += (v0.w + v1.w) + (v2.w + v3.w);
    }
    for (; e < end; e++) {
        float4 v = *(const float4*)&g_t[(size_t)g_col[e] * NCLS + c4 * 4];
        acc.x += v.x; acc.y += v.y; acc.z += v.z; acc.w += v.w;
    }
    float s = g_invdeg[node];
    float4 u  = *(const float4*)&g_u[(size_t)node * NCLS + c4 * 4];
    float4 v0 = *(const float4*)&b0[c4 * 4];
    float4 v1 = *(const float4*)&b1[c4 * 4];
    *(float4*)&out[(size_t)node * NCLS + c4 * 4] =
        make_float4(acc.x * s + u.x + v0.x + v1.x,
                    acc.y * s + u.y + v0.y + v1.y,
                    acc.z * s + u.z + v0.z + v1.z,
                    acc.w * s + u.w + v0.w + v1.w);
}

// ---------------- launch --------------------------------------------------
extern "C" void kernel_launch(void* const* d_in, const int* in_sizes, int n_in,
                              void* d_out, int out_size) {
    const float* x     = (const float*)d_in[0];
    const void*  edges = (const void*)d_in[1];
    const float* w1_l = (const float*)d_in[2];
    const float* b1_l = (const float*)d_in[3];
    const float* w1_r = (const float*)d_in[4];
    const float* b1_r = (const float*)d_in[5];
    const float* w2_l = (const float*)d_in[6];
    const float* b2_l = (const float*)d_in[7];
    const float* w2_r = (const float*)d_in[8];
    const float* b2_r = (const float*)d_in[9];
    float* out = (float*)d_out;

    int N = in_sizes[0] / F;
    int E = in_sizes[1] / 2;
    int nb = (N + SCAN_TILE - 1) / SCAN_TILE;

    // init + CSR build (single-pass lookback scan)
    init_kernel<<<(N + 255) / 256, 256>>>((const int*)edges, N);
    degree_kernel<<<(E + 255) / 256, 256>>>(edges, E);
    scan_lookback_kernel<<<nb, SCAN_TILE>>>(N, E);
    scatter_kernel<<<(E + 255) / 256, 256>>>(edges, E);

    // merged weight conversions
    convert_weights_kernel<<<(W1_Q + W2_Q + 255) / 256, 256>>>(w1_l, w1_r, w2_l, w2_r);

    // Layer 1: agg(x) + self-split -> tensor-core GEMM + bias + relu (h bf16)
    dim3 aggBlock(32, 8);
    aggregate_kernel<<<(N + 7) / 8, aggBlock>>>(x, N);
    {
        static int smem_set = 0;
        if (!smem_set) {
            cudaFuncSetAttribute(gemm1_tc_kernel,
                                 cudaFuncAttributeMaxDynamicSharedMemorySize,
                                 2 * STAGE_B);
            smem_set = 1;
        }
        dim3 grid((N + 127) / 128, F / 128);
        gemm1_tc_kernel<<<grid, 256, 2 * STAGE_B>>>(b1_l, b1_r, N);
    }

    // Layer 2: TC dual projection, fused aggregate+final
    gemm40_tc_kernel<<<(N + 127) / 128, 256>>>(N);
    aggregate40_final_kernel<<<(N + 31) / 32, 320>>>(b2_l, b2_r, out, N);
}

// round 13
// speedup vs baseline: 2.5589x; 1.0221x over previous
#include <cuda_runtime.h>
#include <cuda_bf16.h>
#include <cuda_fp16.h>
#include <cstdint>

// Problem constants (fixed by reference_code)
#define NMAX 50000
#define EMAX 800000
#define F    256
#define AK   512          // concat K for layer-1 GEMM (agg | x)
#define NCLS 40
#define N2   80           // combined layer-2 output width [w2_l | w2_r]
#define SCAN_TILE 1024
#define NBLK_MAX  64

// ---------------- scratch (static device globals; no runtime allocation) ----
__device__ int   g_is64;
__device__ int   g_deg[NMAX];
__device__ int   g_cursor[NMAX];
__device__ int   g_rowptr[NMAX + 1];
__device__ int   g_col[EMAX];
__device__ unsigned long long g_scan_state[NBLK_MAX];  // (flag<<62)|value
__device__ int   g_scan_ticket;
__device__ float g_invdeg[NMAX];
__device__ __align__(16) __half g_Xh[(size_t)NMAX * F];           // fp16 copy of x
__device__ __align__(16) __nv_bfloat16 g_Ahi[(size_t)NMAX * AK];  // [agg|x] hi
__device__ __align__(16) __nv_bfloat16 g_Alo[(size_t)NMAX * AK];  // [agg|x] lo
__device__ __align__(16) __nv_bfloat16 g_Bhi[(size_t)F * AK];     // [w1_l|w1_r] hi
__device__ __align__(16) __nv_bfloat16 g_Blo[(size_t)F * AK];     // lo
__device__ __align__(16) __nv_bfloat16 g_Hhi[(size_t)NMAX * F];   // relu(h) hi
__device__ __align__(16) __nv_bfloat16 g_Hlo[(size_t)NMAX * F];   // relu(h) lo
__device__ __align__(16) __nv_bfloat16 g_B2hi[(size_t)N2 * F];    // [w2_l|w2_r] hi
__device__ __align__(16) __nv_bfloat16 g_B2lo[(size_t)N2 * F];    // lo
__device__ __align__(16) float g_t[(size_t)NMAX * NCLS];          // h @ w2_l^T
__device__ __align__(16) float g_u[(size_t)NMAX * NCLS];          // h @ w2_r^T

// ---------------- PTX helpers ----------------------------------------------
__device__ __forceinline__ void ldsm_x4(uint32_t& r0, uint32_t& r1,
                                        uint32_t& r2, uint32_t& r3, uint32_t addr) {
    asm volatile("ldmatrix.sync.aligned.m8n8.x4.shared.b16 {%0,%1,%2,%3},[%4];"
                 : "=r"(r0), "=r"(r1), "=r"(r2), "=r"(r3) : "r"(addr));
}
__device__ __forceinline__ void ldsm_x2(uint32_t& r0, uint32_t& r1, uint32_t addr) {
    asm volatile("ldmatrix.sync.aligned.m8n8.x2.shared.b16 {%0,%1},[%2];"
                 : "=r"(r0), "=r"(r1) : "r"(addr));
}
__device__ __forceinline__ void mma_bf16(float* c, const uint32_t* a, const uint32_t* b) {
    asm volatile("mma.sync.aligned.m16n8k16.row.col.f32.bf16.bf16.f32 "
                 "{%0,%1,%2,%3},{%4,%5,%6,%7},{%8,%9},{%0,%1,%2,%3};"
                 : "+f"(c[0]), "+f"(c[1]), "+f"(c[2]), "+f"(c[3])
                 : "r"(a[0]), "r"(a[1]), "r"(a[2]), "r"(a[3]), "r"(b[0]), "r"(b[1]));
}
__device__ __forceinline__ void cp16(uint32_t saddr, const void* gaddr, int sz) {
    asm volatile("cp.async.cg.shared.global [%0],[%1],16,%2;"
                 :: "r"(saddr), "l"(gaddr), "r"(sz));
}
__device__ __forceinline__ void cp_commit() {
    asm volatile("cp.async.commit_group;");
}
template <int N>
__device__ __forceinline__ void cp_wait() {
    asm volatile("cp.async.wait_group %0;" :: "n"(N));
}
__device__ __forceinline__ void cp_wait_all() {
    asm volatile("cp.async.commit_group;");
    asm volatile("cp.async.wait_group 0;");
}

// hi/lo bf16 split of 4 floats
__device__ __forceinline__ void split4(__nv_bfloat16* hi, __nv_bfloat16* lo, float4 v) {
    __nv_bfloat162 h0 = __floats2bfloat162_rn(v.x, v.y);
    __nv_bfloat162 h1 = __floats2bfloat162_rn(v.z, v.w);
    float lx = v.x - __bfloat162float(h0.x);
    float ly = v.y - __bfloat162float(h0.y);
    float lz = v.z - __bfloat162float(h1.x);
    float lw = v.w - __bfloat162float(h1.y);
    *reinterpret_cast<__nv_bfloat162*>(hi)     = h0;
    *reinterpret_cast<__nv_bfloat162*>(hi + 2) = h1;
    *reinterpret_cast<__nv_bfloat162*>(lo)     = __floats2bfloat162_rn(lx, ly);
    *reinterpret_cast<__nv_bfloat162*>(lo + 2) = __floats2bfloat162_rn(lz, lw);
}

__device__ __forceinline__ int edge_at(const void* edges, size_t idx) {
    if (g_is64) return (int)((const long long*)edges)[idx];
    return ((const int*)edges)[idx];
}

// ---------------- init: zero counters + scan state + dtype probe ------------
__global__ void init_kernel(const int* __restrict__ v, int n) {
    int i = blockIdx.x * blockDim.x + threadIdx.x;
    if (i < n) { g_deg[i] = 0; g_cursor[i] = 0; }
    if (blockIdx.x == 0) {
        if (threadIdx.x < NBLK_MAX) g_scan_state[threadIdx.x] = 0ULL;
        __shared__ int any_nonzero;
        if (threadIdx.x == 0) { any_nonzero = 0; g_scan_ticket = 0; }
        __syncthreads();
        if (v[2 * threadIdx.x + 1] != 0) atomicOr(&any_nonzero, 1);
        __syncthreads();
        if (threadIdx.x == 0) g_is64 = (any_nonzero == 0) ? 1 : 0;
    }
}

// ---------------- CSR build ------------------------------------------------
__global__ void degree_kernel(const void* __restrict__ edges, int E) {
    int e = blockIdx.x * blockDim.x + threadIdx.x;
    if (e < E) atomicAdd(&g_deg[edge_at(edges, (size_t)E + e)], 1);
}
__device__ __forceinline__ int block_incl_scan(int d, int* total) {
    __shared__ int wsum[32];
    int lane = threadIdx.x & 31, wid = threadIdx.x >> 5;
    int v = d;
#pragma unroll
    for (int o = 1; o < 32; o <<= 1) {
        int t = __shfl_up_sync(0xffffffffu, v, o);
        if (lane >= o) v += t;
    }
    if (lane == 31) wsum[wid] = v;
    __syncthreads();
    if (wid == 0) {
        int w = wsum[lane];
#pragma unroll
        for (int o = 1; o < 32; o <<= 1) {
            int t = __shfl_up_sync(0xffffffffu, w, o);
            if (lane >= o) w += t;
        }
        wsum[lane] = w;
    }
    __syncthreads();
    int incl = v + (wid > 0 ? wsum[wid - 1] : 0);
    *total = wsum[31];
    __syncthreads();
    return incl;
}

// single-pass decoupled-lookback scan: g_deg -> g_rowptr (+invdeg, rowptr[n])
__global__ void scan_lookback_kernel(int n, int E) {
    __shared__ int s_bid;
    __shared__ int s_prefix;
    if (threadIdx.x == 0) s_bid = atomicAdd(&g_scan_ticket, 1);
    __syncthreads();
    int bid = s_bid;
    int i = bid * SCAN_TILE + threadIdx.x;
    int d = (i < n) ? g_deg[i] : 0;
    int total;
    int incl = block_incl_scan(d, &total);
    if (threadIdx.x == 0) {
        if (bid == 0) {
            atomicExch(&g_scan_state[0], (2ULL << 62) | (unsigned)total);
            s_prefix = 0;
        } else {
            atomicExch(&g_scan_state[bid], (1ULL << 62) | (unsigned)total);
            int prefix = 0;
            int j = bid - 1;
            while (j >= 0) {
                unsigned long long st = atomicAdd(&g_scan_state[j], 0ULL);
                unsigned long long flag = st >> 62;
                if (flag == 2) { prefix += (int)(st & 0xFFFFFFFFu); break; }
                if (flag == 1) { prefix += (int)(st & 0xFFFFFFFFu); j--; }
            }
            atomicExch(&g_scan_state[bid], (2ULL << 62) | (unsigned)(prefix + total));
            s_prefix = prefix;
        }
    }
    __syncthreads();
    if (i < n) {
        g_rowptr[i] = s_prefix + incl - d;
        g_invdeg[i] = 1.0f / (float)(d > 0 ? d : 1);
        if (i == n - 1) g_rowptr[n] = E;
    }
}

__global__ void scatter_kernel(const void* __restrict__ edges, int E) {
    int e = blockIdx.x * blockDim.x + threadIdx.x;
    if (e < E) {
        int srcv = edge_at(edges, e);
        int d    = edge_at(edges, (size_t)E + e);
        int p = atomicAdd(&g_cursor[d], 1);
        g_col[g_rowptr[d] + p] = srcv;
    }
}

// ---------------- merged weight conversions ---------------------------------
#define W1_Q (F * (F / 4))          // 16384 float4s
#define W2_Q (N2 * (F / 4))         // 5120 float4s
__global__ void convert_weights_kernel(const float* __restrict__ w1_l,
                                       const float* __restrict__ w1_r,
                                       const float* __restrict__ w2_l,
                                       const float* __restrict__ w2_r) {
    int idx = blockIdx.x * blockDim.x + threadIdx.x;
    if (idx < W1_Q) {
        int row = idx / (F / 4), c4 = idx % (F / 4);
        float4 vl = *(const float4*)&w1_l[(size_t)row * F + c4 * 4];
        float4 vr = *(const float4*)&w1_r[(size_t)row * F + c4 * 4];
        size_t ol = (size_t)row * AK + c4 * 4;
        split4(&g_Bhi[ol], &g_Blo[ol], vl);
        split4(&g_Bhi[ol + F], &g_Blo[ol + F], vr);
    } else if (idx < W1_Q + W2_Q) {
        int j = idx - W1_Q;
        int row = j / (F / 4), c4 = j % (F / 4);
        const float* src = (row < NCLS) ? &w2_l[(size_t)row * F + c4 * 4]
                                        : &w2_r[(size_t)(row - NCLS) * F + c4 * 4];
        float4 v = *(const float4*)src;
        size_t o = (size_t)row * F + c4 * 4;
        split4(&g_B2hi[o], &g_B2lo[o], v);
    }
}

// ---------------- x conversion: fp16 copy + bf16 self-split (cols [256,512))
__global__ void convert_xh_kernel(const float* __restrict__ x, int n) {
    int idx = blockIdx.x * blockDim.x + threadIdx.x;
    if (idx >= n * (F / 4)) return;
    int row = idx / (F / 4), c4 = idx % (F / 4);
    float4 v = *(const float4*)&x[(size_t)row * F + c4 * 4];
    // fp16 copy (for aggregation gather)
    __half2 h0 = __floats2half2_rn(v.x, v.y);
    __half2 h1 = __floats2half2_rn(v.z, v.w);
    *(uint2*)&g_Xh[(size_t)row * F + c4 * 4] =
        make_uint2(*(const uint32_t*)&h0, *(const uint32_t*)&h1);
    // bf16 hi/lo self-split into A cols [256,512)
    size_t o = (size_t)row * AK + F + c4 * 4;
    split4(&g_Ahi[o], &g_Alo[o], v);
}

// ---------------- mean aggregation (256-dim) from fp16 x --------------------
// one warp per node; lane covers feats [lane*8, lane*8+8) = one uint4 per row
__global__ void aggregate_kernel(int n) {
    int node = blockIdx.x * blockDim.y + threadIdx.y;
    if (node >= n) return;
    int lane = threadIdx.x;
    int beg = g_rowptr[node], end = g_rowptr[node + 1];
    const uint4* xh = (const uint4*)g_Xh;   // row stride = 32 uint4
    float acc[8];
#pragma unroll
    for (int i = 0; i < 8; i++) acc[i] = 0.f;
    int e = beg;
    for (; e + 2 <= end; e += 2) {
        uint4 p0 = xh[(size_t)g_col[e] * 32 + lane];
        uint4 p1 = xh[(size_t)g_col[e + 1] * 32 + lane];
        const __half2* q0 = (const __half2*)&p0;
        const __half2* q1 = (const __half2*)&p1;
#pragma unroll
        for (int j = 0; j < 4; j++) {
            float2 f0 = __half22float2(q0[j]);
            float2 f1 = __half22float2(q1[j]);
            acc[j * 2]     += f0.x + f1.x;
            acc[j * 2 + 1] += f0.y + f1.y;
        }
    }
    if (e < end) {
        uint4 p0 = xh[(size_t)g_col[e] * 32 + lane];
        const __half2* q0 = (const __half2*)&p0;
#pragma unroll
        for (int j = 0; j < 4; j++) {
            float2 f0 = __half22float2(q0[j]);
            acc[j * 2]     += f0.x;
            acc[j * 2 + 1] += f0.y;
        }
    }
    float s = g_invdeg[node];
#pragma unroll
    for (int i = 0; i < 8; i++) acc[i] *= s;
    size_t base = (size_t)node * AK + lane * 8;
    split4(&g_Ahi[base],     &g_Alo[base],     make_float4(acc[0], acc[1], acc[2], acc[3]));
    split4(&g_Ahi[base + 4], &g_Alo[base + 4], make_float4(acc[4], acc[5], acc[6], acc[7]));
}

// ---------------- GEMM1 (tensor cores, fused split-3, 2-stage pipeline) -----
#define TSTRIDE 40
#define TILE_B  (128 * TSTRIDE * 2)
#define STAGE_B (4 * TILE_B)
extern __shared__ __align__(16) __nv_bfloat16 g1_smem[];
__global__ __launch_bounds__(256) void gemm1_tc_kernel(const float* __restrict__ bias0,
                                                       const float* __restrict__ bias1,
                                                       int M) {
    const uint32_t sb0 = (uint32_t)__cvta_generic_to_shared(g1_smem);
    int bm = blockIdx.x * 128, bn = blockIdx.y * 128;
    int tid = threadIdx.x, wid = tid >> 5, lane = tid & 31;
    int wm = (wid >> 2) * 64, wn = (wid & 3) * 32;

    float acc[4][4][4];
#pragma unroll
    for (int mf = 0; mf < 4; mf++)
#pragma unroll
        for (int nf = 0; nf < 4; nf++)
#pragma unroll
            for (int r = 0; r < 4; r++) acc[mf][nf][r] = 0.f;

    auto load_chunk = [&](int kc, int stage) {
        int k0 = kc * 32;
        uint32_t sbase = sb0 + stage * STAGE_B;
#pragma unroll
        for (int i = 0; i < 8; i++) {
            int idx = tid + i * 256;
            int t   = idx >> 9;
            int rem = idx & 511;
            int row = rem >> 2, ch = rem & 3;
            uint32_t sa = sbase + t * TILE_B + row * 80 + ch * 16;
            if (t < 2) {
                const __nv_bfloat16* Ag = t ? (const __nv_bfloat16*)g_Alo
                                            : (const __nv_bfloat16*)g_Ahi;
                int grow = bm + row;
                int gr = grow < M ? grow : (M - 1);
                cp16(sa, Ag + (size_t)gr * AK + k0 + ch * 8, grow < M ? 16 : 0);
            } else {
                const __nv_bfloat16* Bg = (t == 3) ? (const __nv_bfloat16*)g_Blo
                                                   : (const __nv_bfloat16*)g_Bhi;
                cp16(sa, Bg + (size_t)(bn + row) * AK + k0 + ch * 8, 16);
            }
        }
        cp_commit();
    };

    load_chunk(0, 0);
#pragma unroll 1
    for (int kc = 0; kc < 16; kc++) {
        int stage = kc & 1;
        if (kc + 1 < 16) {
            load_chunk(kc + 1, stage ^ 1);
            cp_wait<1>();
        } else {
            cp_wait<0>();
        }
        __syncthreads();
        uint32_t sb = sb0 + stage * STAGE_B;
#pragma unroll
        for (int ks = 0; ks < 32; ks += 16) {
            uint32_t ah[4][4], al[4][4], bh[4][2], bl[4][2];
            int akb = (ks + ((lane >> 4) << 3)) * 2;
#pragma unroll
            for (int mf = 0; mf < 4; mf++) {
                int row = wm + mf * 16 + (lane & 15);
                ldsm_x4(ah[mf][0], ah[mf][1], ah[mf][2], ah[mf][3],
                        sb + 0 * TILE_B + row * 80 + akb);
                ldsm_x4(al[mf][0], al[mf][1], al[mf][2], al[mf][3],
                        sb + 1 * TILE_B + row * 80 + akb);
            }
            int brow0 = wn + ((lane >> 4) << 3) + (lane & 7);
            int bkb = (ks + (((lane >> 3) & 1) << 3)) * 2;
#pragma unroll
            for (int nf2 = 0; nf2 < 2; nf2++) {
                int row = brow0 + nf2 * 16;
                uint32_t r0, r1, r2, r3;
                ldsm_x4(r0, r1, r2, r3, sb + 2 * TILE_B + row * 80 + bkb);
                bh[nf2 * 2][0] = r0; bh[nf2 * 2][1] = r1;
                bh[nf2 * 2 + 1][0] = r2; bh[nf2 * 2 + 1][1] = r3;
                ldsm_x4(r0, r1, r2, r3, sb + 3 * TILE_B + row * 80 + bkb);
                bl[nf2 * 2][0] = r0; bl[nf2 * 2][1] = r1;
                bl[nf2 * 2 + 1][0] = r2; bl[nf2 * 2 + 1][1] = r3;
            }
#pragma unroll
            for (int mf = 0; mf < 4; mf++)
#pragma unroll
                for (int nf = 0; nf < 4; nf++) {
                    mma_bf16(acc[mf][nf], ah[mf], bh[nf]);
                    mma_bf16(acc[mf][nf], ah[mf], bl[nf]);
                    mma_bf16(acc[mf][nf], al[mf], bh[nf]);
                }
        }
        __syncthreads();
    }
#pragma unroll
    for (int nf = 0; nf < 4; nf++) {
        int c = bn + wn + nf * 8 + 2 * (lane & 3);
        float bb0 = bias0[c] + bias1[c];
        float bb1 = bias0[c + 1] + bias1[c + 1];
#pragma unroll
        for (int mf = 0; mf < 4; mf++) {
            int r0 = bm + wm + mf * 16 + (lane >> 2);
            int r1 = r0 + 8;
            if (r0 < M) {
                float v0 = fmaxf(acc[mf][nf][0] + bb0, 0.f);
                float v1 = fmaxf(acc[mf][nf][1] + bb1, 0.f);
                __nv_bfloat162 h = __floats2bfloat162_rn(v0, v1);
                *(__nv_bfloat162*)&g_Hhi[(size_t)r0 * F + c] = h;
                *(__nv_bfloat162*)&g_Hlo[(size_t)r0 * F + c] =
                    __floats2bfloat162_rn(v0 - __bfloat162float(h.x),
                                          v1 - __bfloat162float(h.y));
            }
            if (r1 < M) {
                float v0 = fmaxf(acc[mf][nf][2] + bb0, 0.f);
                float v1 = fmaxf(acc[mf][nf][3] + bb1, 0.f);
                __nv_bfloat162 h = __floats2bfloat162_rn(v0, v1);
                *(__nv_bfloat162*)&g_Hhi[(size_t)r1 * F + c] = h;
                *(__nv_bfloat162*)&g_Hlo[(size_t)r1 * F + c] =
                    __floats2bfloat162_rn(v0 - __bfloat162float(h.x),
                                          v1 - __bfloat162float(h.y));
            }
        }
    }
}

// ---------------- GEMM40 (tensor cores, split-3): g_t|g_u = h @ [w2_l|w2_r]^T
#define A2_B (128 * 80)
#define B2_B (80 * 80)
__global__ __launch_bounds__(256) void gemm40_tc_kernel(int M) {
    __shared__ __align__(16) __nv_bfloat16 smem[(2 * A2_B + 2 * B2_B) / 2];
    const uint32_t sb = (uint32_t)__cvta_generic_to_shared(smem);
    int bm = blockIdx.x * 128;
    int tid = threadIdx.x, wid = tid >> 5, lane = tid & 31;
    int wm = (wid & 3) * 32, wn = (wid >> 2) * 40;

    float acc[2][5][4];
#pragma unroll
    for (int mf = 0; mf < 2; mf++)
#pragma unroll
        for (int nf = 0; nf < 5; nf++)
#pragma unroll
            for (int r = 0; r < 4; r++) acc[mf][nf][r] = 0.f;

#pragma unroll 1
    for (int kc = 0; kc < 8; kc++) {
        int k0 = kc * 32;
        for (int idx = tid; idx < 1664; idx += 256) {
            if (idx < 1024) {
                int t = idx >> 9, rem = idx & 511;
                int row = rem >> 2, ch = rem & 3;
                const __nv_bfloat16* Ag = t ? (const __nv_bfloat16*)g_Hlo
                                            : (const __nv_bfloat16*)g_Hhi;
                int grow = bm + row;
                int gr = grow < M ? grow : (M - 1);
                cp16(sb + t * A2_B + row * 80 + ch * 16,
                     Ag + (size_t)gr * F + k0 + ch * 8, grow < M ? 16 : 0);
            } else {
                int j = idx - 1024;
                int t = (j >= 320), r2 = j - t * 320;
                int row = r2 >> 2, ch = r2 & 3;
                const __nv_bfloat16* Bg = t ? (const __nv_bfloat16*)g_B2lo
                                            : (const __nv_bfloat16*)g_B2hi;
                cp16(sb + 2 * A2_B + t * B2_B + row * 80 + ch * 16,
                     Bg + (size_t)row * F + k0 + ch * 8, 16);
            }
        }
        cp_wait_all();
        __syncthreads();
#pragma unroll
        for (int ks = 0; ks < 32; ks += 16) {
            uint32_t ah[2][4], al[2][4], bh[5][2], bl[5][2];
            int akb = (ks + ((lane >> 4) << 3)) * 2;
#pragma unroll
            for (int mf = 0; mf < 2; mf++) {
                int row = wm + mf * 16 + (lane & 15);
                ldsm_x4(ah[mf][0], ah[mf][1], ah[mf][2], ah[mf][3],
                        sb + 0 * A2_B + row * 80 + akb);
                ldsm_x4(al[mf][0], al[mf][1], al[mf][2], al[mf][3],
                        sb + 1 * A2_B + row * 80 + akb);
            }
            int bkb = (ks + (((lane >> 3) & 1) << 3)) * 2;
            int brow0 = wn + ((lane >> 4) << 3) + (lane & 7);
#pragma unroll
            for (int nf2 = 0; nf2 < 2; nf2++) {
                int row = brow0 + nf2 * 16;
                uint32_t r0, r1, r2, r3;
                ldsm_x4(r0, r1, r2, r3, sb + 2 * A2_B + 0 * B2_B + row * 80 + bkb);
                bh[nf2 * 2][0] = r0; bh[nf2 * 2][1] = r1;
                bh[nf2 * 2 + 1][0] = r2; bh[nf2 * 2 + 1][1] = r3;
                ldsm_x4(r0, r1, r2, r3, sb + 2 * A2_B + 1 * B2_B + row * 80 + bkb);
                bl[nf2 * 2][0] = r0; bl[nf2 * 2][1] = r1;
                bl[nf2 * 2 + 1][0] = r2; bl[nf2 * 2 + 1][1] = r3;
            }
            {
                int row = wn + 32 + (lane & 7);
                ldsm_x2(bh[4][0], bh[4][1], sb + 2 * A2_B + 0 * B2_B + row * 80 + bkb);
                ldsm_x2(bl[4][0], bl[4][1], sb + 2 * A2_B + 1 * B2_B + row * 80 + bkb);
            }
#pragma unroll
            for (int mf = 0; mf < 2; mf++)
#pragma unroll
                for (int nf = 0; nf < 5; nf++) {
                    mma_bf16(acc[mf][nf], ah[mf], bh[nf]);
                    mma_bf16(acc[mf][nf], ah[mf], bl[nf]);
                    mma_bf16(acc[mf][nf], al[mf], bh[nf]);
                }
        }
        __syncthreads();
    }
    float* dst = (wid >> 2) ? (float*)g_u : (float*)g_t;
#pragma unroll
    for (int nf = 0; nf < 5; nf++) {
        int c = (wn % 40) + nf * 8 + 2 * (lane & 3);
#pragma unroll
        for (int mf = 0; mf < 2; mf++) {
            int r0 = bm + wm + mf * 16 + (lane >> 2);
            int r1 = r0 + 8;
            if (r0 < M) {
                dst[(size_t)r0 * NCLS + c]     = acc[mf][nf][0];
                dst[(size_t)r0 * NCLS + c + 1] = acc[mf][nf][1];
            }
            if (r1 < M) {
                dst[(size_t)r1 * NCLS + c]     = acc[mf][nf][2];
                dst[(size_t)r1 * NCLS + c + 1] = acc[mf][nf][3];
            }
        }
    }
}

// ---------------- mean aggregation (40-dim) on g_t, fused final, 4-unrolled -
__global__ void aggregate40_final_kernel(const float* __restrict__ b0,
                                         const float* __restrict__ b1,
                                         float* __restrict__ out, int n) {
    int tid = threadIdx.x;
    int node = blockIdx.x * 32 + tid / 10;
    int c4 = tid % 10;
    if (node >= n) return;
    int beg = g_rowptr[node], end = g_rowptr[node + 1];
    float4 acc = make_float4(0.f, 0.f, 0.f, 0.f);
    int e = beg;
    for (; e + 4 <= end; e += 4) {
        int c0 = g_col[e], c1 = g_col[e + 1], c2 = g_col[e + 2], c3 = g_col[e + 3];
        float4 v0 = *(const float4*)&g_t[(size_t)c0 * NCLS + c4 * 4];
        float4 v1 = *(const float4*)&g_t[(size_t)c1 * NCLS + c4 * 4];
        float4 v2 = *(const float4*)&g_t[(size_t)c2 * NCLS + c4 * 4];
        float4 v3 = *(const float4*)&g_t[(size_t)c3 * NCLS + c4 * 4];
        acc.x += (v0.x + v1.x) + (v2.x + v3.x);
        acc.y += (v0.y + v1.y) + (v2.y + v3.y);
        acc.z += (v0.z + v1.z) + (v2.z + v3.z);
        acc.w += (v0.w + v1.w) + (v2.w + v3.w);
    }
    for (; e < end; e++) {
        float4 v = *(const float4*)&g_t[(size_t)g_col[e] * NCLS + c4 * 4];
        acc.x += v.x; acc.y += v.y; acc.z += v.z; acc.w += v.w;
    }
    float s = g_invdeg[node];
    float4 u  = *(const float4*)&g_u[(size_t)node * NCLS + c4 * 4];
    float4 v0 = *(const float4*)&b0[c4 * 4];
    float4 v1 = *(const float4*)&b1[c4 * 4];
    *(float4*)&out[(size_t)node * NCLS + c4 * 4] =
        make_float4(acc.x * s + u.x + v0.x + v1.x,
                    acc.y * s + u.y + v0.y + v1.y,
                    acc.z * s + u.z + v0.z + v1.z,
                    acc.w * s + u.w + v0.w + v1.w);
}

// ---------------- launch --------------------------------------------------
extern "C" void kernel_launch(void* const* d_in, const int* in_sizes, int n_in,
                              void* d_out, int out_size) {
    const float* x     = (const float*)d_in[0];
    const void*  edges = (const void*)d_in[1];
    const float* w1_l = (const float*)d_in[2];
    const float* b1_l = (const float*)d_in[3];
    const float* w1_r = (const float*)d_in[4];
    const float* b1_r = (const float*)d_in[5];
    const float* w2_l = (const float*)d_in[6];
    const float* b2_l = (const float*)d_in[7];
    const float* w2_r = (const float*)d_in[8];
    const float* b2_r = (const float*)d_in[9];
    float* out = (float*)d_out;

    int N = in_sizes[0] / F;
    int E = in_sizes[1] / 2;
    int nb = (N + SCAN_TILE - 1) / SCAN_TILE;

    // one-time resources (created on the uncaptured correctness call)
    static cudaStream_t s2 = nullptr;
    static cudaEvent_t evFork = nullptr, evJoin = nullptr;
    static int once = 0;
    if (!once) {
        cudaStreamCreateWithFlags(&s2, cudaStreamNonBlocking);
        cudaEventCreateWithFlags(&evFork, cudaEventDisableTiming);
        cudaEventCreateWithFlags(&evJoin, cudaEventDisableTiming);
        cudaFuncSetAttribute(gemm1_tc_kernel,
                             cudaFuncAttributeMaxDynamicSharedMemorySize,
                             2 * STAGE_B);
        once = 1;
    }

    // fork: converts on s2, CSR chain on main stream
    cudaEventRecord(evFork, 0);
    cudaStreamWaitEvent(s2, evFork, 0);
    convert_weights_kernel<<<(W1_Q + W2_Q + 255) / 256, 256, 0, s2>>>(w1_l, w1_r,
                                                                     w2_l, w2_r);
    convert_xh_kernel<<<(N * (F / 4) + 255) / 256, 256, 0, s2>>>(x, N);
    cudaEventRecord(evJoin, s2);

    init_kernel<<<(N + 255) / 256, 256>>>((const int*)edges, N);
    degree_kernel<<<(E + 255) / 256, 256>>>(edges, E);
    scan_lookback_kernel<<<nb, SCAN_TILE>>>(N, E);
    scatter_kernel<<<(E + 255) / 256, 256>>>(edges, E);

    // join before aggregate (needs g_Xh) and gemm1 (needs weights)
    cudaStreamWaitEvent(0, evJoin, 0);

    // Layer 1: agg(fp16 x) -> tensor-core GEMM + bias + relu (h bf16)
    dim3 aggBlock(32, 8);
    aggregate_kernel<<<(N + 7) / 8, aggBlock>>>(N);
    {
        dim3 grid((N + 127) / 128, F / 128);
        gemm1_tc_kernel<<<grid, 256, 2 * STAGE_B>>>(b1_l, b1_r, N);
    }

    // Layer 2: TC dual projection, fused aggregate+final
    gemm40_tc_kernel<<<(N + 127) / 128, 256>>>(N);
    aggregate40_final_kernel<<<(N + 31) / 32, 320>>>(b2_l, b2_r, out, N);
}

// round 14
// speedup vs baseline: 3.9638x; 1.5491x over previous
#include <cuda_runtime.h>
#include <cuda_fp16.h>
#include <cstdint>

// Problem constants (fixed by reference_code)
#define NMAX 50000
#define EMAX 800000
#define F    256
#define AK   512          // concat K for layer-1 GEMM (agg | x)
#define NCLS 40
#define N2   80           // combined layer-2 output width [w2_l | w2_r]
#define SCAN_TILE 1024
#define NBLK_MAX  64

// ---------------- scratch (static device globals; no runtime allocation) ----
__device__ int   g_is64;
__device__ int   g_deg[NMAX];
__device__ int   g_cursor[NMAX];
__device__ int   g_rowptr[NMAX + 1];
__device__ int   g_col[EMAX];
__device__ unsigned long long g_scan_state[NBLK_MAX];  // (flag<<62)|value
__device__ int   g_scan_ticket;
__device__ float g_invdeg[NMAX];
__device__ __align__(16) __half g_Ah[(size_t)NMAX * AK];   // [agg | x] fp16
__device__ __align__(16) __half g_Bh[(size_t)F * AK];      // [w1_l | w1_r] fp16
__device__ __align__(16) __half g_Hh[(size_t)NMAX * F];    // relu(h) fp16
__device__ __align__(16) __half g_B2h[(size_t)N2 * F];     // [w2_l | w2_r] fp16
__device__ __align__(16) float g_t[(size_t)NMAX * NCLS];   // h @ w2_l^T
__device__ __align__(16) float g_u[(size_t)NMAX * NCLS];   // h @ w2_r^T

// ---------------- PTX helpers ----------------------------------------------
__device__ __forceinline__ void ldsm_x4(uint32_t& r0, uint32_t& r1,
                                        uint32_t& r2, uint32_t& r3, uint32_t addr) {
    asm volatile("ldmatrix.sync.aligned.m8n8.x4.shared.b16 {%0,%1,%2,%3},[%4];"
                 : "=r"(r0), "=r"(r1), "=r"(r2), "=r"(r3) : "r"(addr));
}
__device__ __forceinline__ void ldsm_x2(uint32_t& r0, uint32_t& r1, uint32_t addr) {
    asm volatile("ldmatrix.sync.aligned.m8n8.x2.shared.b16 {%0,%1},[%2];"
                 : "=r"(r0), "=r"(r1) : "r"(addr));
}
__device__ __forceinline__ void mma_f16(float* c, const uint32_t* a, const uint32_t* b) {
    asm volatile("mma.sync.aligned.m16n8k16.row.col.f32.f16.f16.f32 "
                 "{%0,%1,%2,%3},{%4,%5,%6,%7},{%8,%9},{%0,%1,%2,%3};"
                 : "+f"(c[0]), "+f"(c[1]), "+f"(c[2]), "+f"(c[3])
                 : "r"(a[0]), "r"(a[1]), "r"(a[2]), "r"(a[3]), "r"(b[0]), "r"(b[1]));
}
__device__ __forceinline__ void cp16(uint32_t saddr, const void* gaddr, int sz) {
    asm volatile("cp.async.cg.shared.global [%0],[%1],16,%2;"
                 :: "r"(saddr), "l"(gaddr), "r"(sz));
}
__device__ __forceinline__ void cp_commit() {
    asm volatile("cp.async.commit_group;");
}
template <int N>
__device__ __forceinline__ void cp_wait() {
    asm volatile("cp.async.wait_group %0;" :: "n"(N));
}
__device__ __forceinline__ void cp_wait_all() {
    asm volatile("cp.async.commit_group;");
    asm volatile("cp.async.wait_group 0;");
}

__device__ __forceinline__ int edge_at(const void* edges, size_t idx) {
    if (g_is64) return (int)((const long long*)edges)[idx];
    return ((const int*)edges)[idx];
}

// ---------------- init: zero counters + scan state + dtype probe ------------
__global__ void init_kernel(const int* __restrict__ v, int n) {
    int i = blockIdx.x * blockDim.x + threadIdx.x;
    if (i < n) { g_deg[i] = 0; g_cursor[i] = 0; }
    if (blockIdx.x == 0) {
        if (threadIdx.x < NBLK_MAX) g_scan_state[threadIdx.x] = 0ULL;
        __shared__ int any_nonzero;
        if (threadIdx.x == 0) { any_nonzero = 0; g_scan_ticket = 0; }
        __syncthreads();
        if (v[2 * threadIdx.x + 1] != 0) atomicOr(&any_nonzero, 1);
        __syncthreads();
        if (threadIdx.x == 0) g_is64 = (any_nonzero == 0) ? 1 : 0;
    }
}

// ---------------- CSR build ------------------------------------------------
__global__ void degree_kernel(const void* __restrict__ edges, int E) {
    int e = blockIdx.x * blockDim.x + threadIdx.x;
    if (e < E) atomicAdd(&g_deg[edge_at(edges, (size_t)E + e)], 1);
}
__device__ __forceinline__ int block_incl_scan(int d, int* total) {
    __shared__ int wsum[32];
    int lane = threadIdx.x & 31, wid = threadIdx.x >> 5;
    int v = d;
#pragma unroll
    for (int o = 1; o < 32; o <<= 1) {
        int t = __shfl_up_sync(0xffffffffu, v, o);
        if (lane >= o) v += t;
    }
    if (lane == 31) wsum[wid] = v;
    __syncthreads();
    if (wid == 0) {
        int w = wsum[lane];
#pragma unroll
        for (int o = 1; o < 32; o <<= 1) {
            int t = __shfl_up_sync(0xffffffffu, w, o);
            if (lane >= o) w += t;
        }
        wsum[lane] = w;
    }
    __syncthreads();
    int incl = v + (wid > 0 ? wsum[wid - 1] : 0);
    *total = wsum[31];
    __syncthreads();
    return incl;
}

// single-pass decoupled-lookback scan: g_deg -> g_rowptr (+invdeg, rowptr[n])
__global__ void scan_lookback_kernel(int n, int E) {
    __shared__ int s_bid;
    __shared__ int s_prefix;
    if (threadIdx.x == 0) s_bid = atomicAdd(&g_scan_ticket, 1);
    __syncthreads();
    int bid = s_bid;
    int i = bid * SCAN_TILE + threadIdx.x;
    int d = (i < n) ? g_deg[i] : 0;
    int total;
    int incl = block_incl_scan(d, &total);
    if (threadIdx.x == 0) {
        if (bid == 0) {
            atomicExch(&g_scan_state[0], (2ULL << 62) | (unsigned)total);
            s_prefix = 0;
        } else {
            atomicExch(&g_scan_state[bid], (1ULL << 62) | (unsigned)total);
            int prefix = 0;
            int j = bid - 1;
            while (j >= 0) {
                unsigned long long st = atomicAdd(&g_scan_state[j], 0ULL);
                unsigned long long flag = st >> 62;
                if (flag == 2) { prefix += (int)(st & 0xFFFFFFFFu); break; }
                if (flag == 1) { prefix += (int)(st & 0xFFFFFFFFu); j--; }
            }
            atomicExch(&g_scan_state[bid], (2ULL << 62) | (unsigned)(prefix + total));
            s_prefix = prefix;
        }
    }
    __syncthreads();
    if (i < n) {
        g_rowptr[i] = s_prefix + incl - d;
        g_invdeg[i] = 1.0f / (float)(d > 0 ? d : 1);
        if (i == n - 1) g_rowptr[n] = E;
    }
}

__global__ void scatter_kernel(const void* __restrict__ edges, int E) {
    int e = blockIdx.x * blockDim.x + threadIdx.x;
    if (e < E) {
        int srcv = edge_at(edges, e);
        int d    = edge_at(edges, (size_t)E + e);
        int p = atomicAdd(&g_cursor[d], 1);
        g_col[g_rowptr[d] + p] = srcv;
    }
}

// ---------------- merged weight conversions (fp16) ---------------------------
#define W1_Q (F * (F / 4))          // 16384 float4s
#define W2_Q (N2 * (F / 4))         // 5120 float4s
__device__ __forceinline__ uint2 to_h4(float4 v) {
    __half2 h0 = __floats2half2_rn(v.x, v.y);
    __half2 h1 = __floats2half2_rn(v.z, v.w);
    return make_uint2(*(const uint32_t*)&h0, *(const uint32_t*)&h1);
}
__global__ void convert_weights_kernel(const float* __restrict__ w1_l,
                                       const float* __restrict__ w1_r,
                                       const float* __restrict__ w2_l,
                                       const float* __restrict__ w2_r) {
    int idx = blockIdx.x * blockDim.x + threadIdx.x;
    if (idx < W1_Q) {
        int row = idx / (F / 4), c4 = idx % (F / 4);
        float4 vl = *(const float4*)&w1_l[(size_t)row * F + c4 * 4];
        float4 vr = *(const float4*)&w1_r[(size_t)row * F + c4 * 4];
        size_t o = (size_t)row * AK + c4 * 4;
        *(uint2*)&g_Bh[o]     = to_h4(vl);
        *(uint2*)&g_Bh[o + F] = to_h4(vr);
    } else if (idx < W1_Q + W2_Q) {
        int j = idx - W1_Q;
        int row = j / (F / 4), c4 = j % (F / 4);
        const float* src = (row < NCLS) ? &w2_l[(size_t)row * F + c4 * 4]
                                        : &w2_r[(size_t)(row - NCLS) * F + c4 * 4];
        *(uint2*)&g_B2h[(size_t)row * F + c4 * 4] = to_h4(*(const float4*)src);
    }
}

// ---------------- x conversion: fp16 into A cols [256,512) ------------------
__global__ void convert_x_kernel(const float* __restrict__ x, int n) {
    int idx = blockIdx.x * blockDim.x + threadIdx.x;
    if (idx >= n * (F / 4)) return;
    int row = idx / (F / 4), c4 = idx % (F / 4);
    float4 v = *(const float4*)&x[(size_t)row * F + c4 * 4];
    *(uint2*)&g_Ah[(size_t)row * AK + F + c4 * 4] = to_h4(v);
}

// ---------------- mean aggregation (256-dim) from fp16 x-part ---------------
// gather source: g_Ah cols [256,512); write agg fp16 to cols [0,256)
// one warp per node; lane covers 8 feats = one uint4
__global__ void aggregate_kernel(int n) {
    int node = blockIdx.x * blockDim.y + threadIdx.y;
    if (node >= n) return;
    int lane = threadIdx.x;
    int beg = g_rowptr[node], end = g_rowptr[node + 1];
    const uint4* xh = (const uint4*)g_Ah;   // row stride = 64 uint4; x-part +32
    float acc[8];
#pragma unroll
    for (int i = 0; i < 8; i++) acc[i] = 0.f;
    int e = beg;
    for (; e + 2 <= end; e += 2) {
        uint4 p0 = xh[(size_t)g_col[e] * 64 + 32 + lane];
        uint4 p1 = xh[(size_t)g_col[e + 1] * 64 + 32 + lane];
        const __half2* q0 = (const __half2*)&p0;
        const __half2* q1 = (const __half2*)&p1;
#pragma unroll
        for (int j = 0; j < 4; j++) {
            float2 f0 = __half22float2(q0[j]);
            float2 f1 = __half22float2(q1[j]);
            acc[j * 2]     += f0.x + f1.x;
            acc[j * 2 + 1] += f0.y + f1.y;
        }
    }
    if (e < end) {
        uint4 p0 = xh[(size_t)g_col[e] * 64 + 32 + lane];
        const __half2* q0 = (const __half2*)&p0;
#pragma unroll
        for (int j = 0; j < 4; j++) {
            float2 f0 = __half22float2(q0[j]);
            acc[j * 2]     += f0.x;
            acc[j * 2 + 1] += f0.y;
        }
    }
    float s = g_invdeg[node];
    uint4 o;
    __half2 h0 = __floats2half2_rn(acc[0] * s, acc[1] * s);
    __half2 h1 = __floats2half2_rn(acc[2] * s, acc[3] * s);
    __half2 h2 = __floats2half2_rn(acc[4] * s, acc[5] * s);
    __half2 h3 = __floats2half2_rn(acc[6] * s, acc[7] * s);
    o.x = *(const uint32_t*)&h0; o.y = *(const uint32_t*)&h1;
    o.z = *(const uint32_t*)&h2; o.w = *(const uint32_t*)&h3;
    *(uint4*)&g_Ah[(size_t)node * AK + lane * 8] = o;
}

// ---------------- GEMM1 (fp16 tensor cores, single pass, 2-stage pipeline) --
// g_Hh = relu(A*B^T + bias) fp16; A=[M,512] fp16, B=[256,512] fp16, fp32 accum
// BM=128, BN=128, BK=32; 8 warps 2(m)x4(n); 16 K-chunks, 32 mma/warp/chunk.
#define TSTRIDE 40      // halfs per smem row (80B) -> conflict-free ldsm
#define TILE_B  (128 * TSTRIDE * 2)   // bytes per tile = 10240
#define STAGE_B (2 * TILE_B)          // A + B tiles = 20480
extern __shared__ __align__(16) __half g1_smem[];
__global__ __launch_bounds__(256) void gemm1_tc_kernel(const float* __restrict__ bias0,
                                                       const float* __restrict__ bias1,
                                                       int M) {
    const uint32_t sb0 = (uint32_t)__cvta_generic_to_shared(g1_smem);
    int bm = blockIdx.x * 128, bn = blockIdx.y * 128;
    int tid = threadIdx.x, wid = tid >> 5, lane = tid & 31;
    int wm = (wid >> 2) * 64, wn = (wid & 3) * 32;

    float acc[4][4][4];
#pragma unroll
    for (int mf = 0; mf < 4; mf++)
#pragma unroll
        for (int nf = 0; nf < 4; nf++)
#pragma unroll
            for (int r = 0; r < 4; r++) acc[mf][nf][r] = 0.f;

    auto load_chunk = [&](int kc, int stage) {
        int k0 = kc * 32;
        uint32_t sbase = sb0 + stage * STAGE_B;
        // A tile 128x4ch + B tile 128x4ch = 1024 cp16, 4 per thread
#pragma unroll
        for (int i = 0; i < 4; i++) {
            int idx = tid + i * 256;
            int t   = idx >> 9;          // 0 = A, 1 = B
            int rem = idx & 511;
            int row = rem >> 2, ch = rem & 3;
            uint32_t sa = sbase + t * TILE_B + row * 80 + ch * 16;
            if (t == 0) {
                int grow = bm + row;
                int gr = grow < M ? grow : (M - 1);
                cp16(sa, g_Ah + (size_t)gr * AK + k0 + ch * 8, grow < M ? 16 : 0);
            } else {
                cp16(sa, g_Bh + (size_t)(bn + row) * AK + k0 + ch * 8, 16);
            }
        }
        cp_commit();
    };

    load_chunk(0, 0);
#pragma unroll 1
    for (int kc = 0; kc < 16; kc++) {
        int stage = kc & 1;
        if (kc + 1 < 16) {
            load_chunk(kc + 1, stage ^ 1);
            cp_wait<1>();
        } else {
            cp_wait<0>();
        }
        __syncthreads();
        uint32_t sb = sb0 + stage * STAGE_B;
#pragma unroll
        for (int ks = 0; ks < 32; ks += 16) {
            uint32_t a[4][4], b[4][2];
            int akb = (ks + ((lane >> 4) << 3)) * 2;
#pragma unroll
            for (int mf = 0; mf < 4; mf++) {
                int row = wm + mf * 16 + (lane & 15);
                ldsm_x4(a[mf][0], a[mf][1], a[mf][2], a[mf][3],
                        sb + row * 80 + akb);
            }
            int brow0 = wn + ((lane >> 4) << 3) + (lane & 7);
            int bkb = (ks + (((lane >> 3) & 1) << 3)) * 2;
#pragma unroll
            for (int nf2 = 0; nf2 < 2; nf2++) {
                int row = brow0 + nf2 * 16;
                uint32_t r0, r1, r2, r3;
                ldsm_x4(r0, r1, r2, r3, sb + TILE_B + row * 80 + bkb);
                b[nf2 * 2][0] = r0; b[nf2 * 2][1] = r1;
                b[nf2 * 2 + 1][0] = r2; b[nf2 * 2 + 1][1] = r3;
            }
#pragma unroll
            for (int mf = 0; mf < 4; mf++)
#pragma unroll
                for (int nf = 0; nf < 4; nf++)
                    mma_f16(acc[mf][nf], a[mf], b[nf]);
        }
        __syncthreads();
    }
    // epilogue: bias + relu -> fp16 h
#pragma unroll
    for (int nf = 0; nf < 4; nf++) {
        int c = bn + wn + nf * 8 + 2 * (lane & 3);
        float bb0 = bias0[c] + bias1[c];
        float bb1 = bias0[c + 1] + bias1[c + 1];
#pragma unroll
        for (int mf = 0; mf < 4; mf++) {
            int r0 = bm + wm + mf * 16 + (lane >> 2);
            int r1 = r0 + 8;
            if (r0 < M) {
                *(__half2*)&g_Hh[(size_t)r0 * F + c] =
                    __floats2half2_rn(fmaxf(acc[mf][nf][0] + bb0, 0.f),
                                      fmaxf(acc[mf][nf][1] + bb1, 0.f));
            }
            if (r1 < M) {
                *(__half2*)&g_Hh[(size_t)r1 * F + c] =
                    __floats2half2_rn(fmaxf(acc[mf][nf][2] + bb0, 0.f),
                                      fmaxf(acc[mf][nf][3] + bb1, 0.f));
            }
        }
    }
}

// ---------------- GEMM40 (fp16 TC, single pass): g_t|g_u = h @ [w2_l|w2_r]^T
#define A2_B (128 * 80)     // bytes per A tile
#define B2_B (80 * 80)      // bytes per B tile
__global__ __launch_bounds__(256) void gemm40_tc_kernel(int M) {
    __shared__ __align__(16) __half smem[(A2_B + B2_B) / 2];
    const uint32_t sb = (uint32_t)__cvta_generic_to_shared(smem);
    int bm = blockIdx.x * 128;
    int tid = threadIdx.x, wid = tid >> 5, lane = tid & 31;
    int wm = (wid & 3) * 32, wn = (wid >> 2) * 40;

    float acc[2][5][4];
#pragma unroll
    for (int mf = 0; mf < 2; mf++)
#pragma unroll
        for (int nf = 0; nf < 5; nf++)
#pragma unroll
            for (int r = 0; r < 4; r++) acc[mf][nf][r] = 0.f;

#pragma unroll 1
    for (int kc = 0; kc < 8; kc++) {
        int k0 = kc * 32;
        // A: 512 cp16; B: 320 cp16
        for (int idx = tid; idx < 832; idx += 256) {
            if (idx < 512) {
                int row = idx >> 2, ch = idx & 3;
                int grow = bm + row;
                int gr = grow < M ? grow : (M - 1);
                cp16(sb + row * 80 + ch * 16,
                     g_Hh + (size_t)gr * F + k0 + ch * 8, grow < M ? 16 : 0);
            } else {
                int j = idx - 512;
                int row = j >> 2, ch = j & 3;
                cp16(sb + A2_B + row * 80 + ch * 16,
                     g_B2h + (size_t)row * F + k0 + ch * 8, 16);
            }
        }
        cp_wait_all();
        __syncthreads();
#pragma unroll
        for (int ks = 0; ks < 32; ks += 16) {
            uint32_t a[2][4], b[5][2];
            int akb = (ks + ((lane >> 4) << 3)) * 2;
#pragma unroll
            for (int mf = 0; mf < 2; mf++) {
                int row = wm + mf * 16 + (lane & 15);
                ldsm_x4(a[mf][0], a[mf][1], a[mf][2], a[mf][3],
                        sb + row * 80 + akb);
            }
            int bkb = (ks + (((lane >> 3) & 1) << 3)) * 2;
            int brow0 = wn + ((lane >> 4) << 3) + (lane & 7);
#pragma unroll
            for (int nf2 = 0; nf2 < 2; nf2++) {
                int row = brow0 + nf2 * 16;
                uint32_t r0, r1, r2, r3;
                ldsm_x4(r0, r1, r2, r3, sb + A2_B + row * 80 + bkb);
                b[nf2 * 2][0] = r0; b[nf2 * 2][1] = r1;
                b[nf2 * 2 + 1][0] = r2; b[nf2 * 2 + 1][1] = r3;
            }
            {
                int row = wn + 32 + (lane & 7);
                ldsm_x2(b[4][0], b[4][1], sb + A2_B + row * 80 + bkb);
            }
#pragma unroll
            for (int mf = 0; mf < 2; mf++)
#pragma unroll
                for (int nf = 0; nf < 5; nf++)
                    mma_f16(acc[mf][nf], a[mf], b[nf]);
        }
        __syncthreads();
    }
    float* dst = (wid >> 2) ? (float*)g_u : (float*)g_t;
#pragma unroll
    for (int nf = 0; nf < 5; nf++) {
        int c = (wn % 40) + nf * 8 + 2 * (lane & 3);
#pragma unroll
        for (int mf = 0; mf < 2; mf++) {
            int r0 = bm + wm + mf * 16 + (lane >> 2);
            int r1 = r0 + 8;
            if (r0 < M) {
                dst[(size_t)r0 * NCLS + c]     = acc[mf][nf][0];
                dst[(size_t)r0 * NCLS + c + 1] = acc[mf][nf][1];
            }
            if (r1 < M) {
                dst[(size_t)r1 * NCLS + c]     = acc[mf][nf][2];
                dst[(size_t)r1 * NCLS + c + 1] = acc[mf][nf][3];
            }
        }
    }
}

// ---------------- mean aggregation (40-dim) on g_t, fused final, 4-unrolled -
__global__ void aggregate40_final_kernel(const float* __restrict__ b0,
                                         const float* __restrict__ b1,
                                         float* __restrict__ out, int n) {
    int tid = threadIdx.x;
    int node = blockIdx.x * 32 + tid / 10;
    int c4 = tid % 10;
    if (node >= n) return;
    int beg = g_rowptr[node], end = g_rowptr[node + 1];
    float4 acc = make_float4(0.f, 0.f, 0.f, 0.f);
    int e = beg;
    for (; e + 4 <= end; e += 4) {
        int c0 = g_col[e], c1 = g_col[e + 1], c2 = g_col[e + 2], c3 = g_col[e + 3];
        float4 v0 = *(const float4*)&g_t[(size_t)c0 * NCLS + c4 * 4];
        float4 v1 = *(const float4*)&g_t[(size_t)c1 * NCLS + c4 * 4];
        float4 v2 = *(const float4*)&g_t[(size_t)c2 * NCLS + c4 * 4];
        float4 v3 = *(const float4*)&g_t[(size_t)c3 * NCLS + c4 * 4];
        acc.x += (v0.x + v1.x) + (v2.x + v3.x);
        acc.y += (v0.y + v1.y) + (v2.y + v3.y);
        acc.z += (v0.z + v1.z) + (v2.z + v3.z);
        acc.w += (v0.w + v1.w) + (v2.w + v3.w);
    }
    for (; e < end; e++) {
        float4 v = *(const float4*)&g_t[(size_t)g_col[e] * NCLS + c4 * 4];
        acc.x += v.x; acc.y += v.y; acc.z += v.z; acc.w += v.w;
    }
    float s = g_invdeg[node];
    float4 u  = *(const float4*)&g_u[(size_t)node * NCLS + c4 * 4];
    float4 v0 = *(const float4*)&b0[c4 * 4];
    float4 v1 = *(const float4*)&b1[c4 * 4];
    *(float4*)&out[(size_t)node * NCLS + c4 * 4] =
        make_float4(acc.x * s + u.x + v0.x + v1.x,
                    acc.y * s + u.y + v0.y + v1.y,
                    acc.z * s + u.z + v0.z + v1.z,
                    acc.w * s + u.w + v0.w + v1.w);
}

// ---------------- launch --------------------------------------------------
extern "C" void kernel_launch(void* const* d_in, const int* in_sizes, int n_in,
                              void* d_out, int out_size) {
    const float* x     = (const float*)d_in[0];
    const void*  edges = (const void*)d_in[1];
    const float* w1_l = (const float*)d_in[2];
    const float* b1_l = (const float*)d_in[3];
    const float* w1_r = (const float*)d_in[4];
    const float* b1_r = (const float*)d_in[5];
    const float* w2_l = (const float*)d_in[6];
    const float* b2_l = (const float*)d_in[7];
    const float* w2_r = (const float*)d_in[8];
    const float* b2_r = (const float*)d_in[9];
    float* out = (float*)d_out;

    int N = in_sizes[0] / F;
    int E = in_sizes[1] / 2;
    int nb = (N + SCAN_TILE - 1) / SCAN_TILE;

    // one-time resources (created on the uncaptured correctness call)
    static cudaStream_t s2 = nullptr;
    static cudaEvent_t evFork = nullptr, evJoin = nullptr;
    static int once = 0;
    if (!once) {
        cudaStreamCreateWithFlags(&s2, cudaStreamNonBlocking);
        cudaEventCreateWithFlags(&evFork, cudaEventDisableTiming);
        cudaEventCreateWithFlags(&evJoin, cudaEventDisableTiming);
        cudaFuncSetAttribute(gemm1_tc_kernel,
                             cudaFuncAttributeMaxDynamicSharedMemorySize,
                             2 * STAGE_B);
        once = 1;
    }

    // fork: converts on s2, CSR chain on main stream
    cudaEventRecord(evFork, 0);
    cudaStreamWaitEvent(s2, evFork, 0);
    convert_weights_kernel<<<(W1_Q + W2_Q + 255) / 256, 256, 0, s2>>>(w1_l, w1_r,
                                                                     w2_l, w2_r);
    convert_x_kernel<<<(N * (F / 4) + 255) / 256, 256, 0, s2>>>(x, N);
    cudaEventRecord(evJoin, s2);

    init_kernel<<<(N + 255) / 256, 256>>>((const int*)edges, N);
    degree_kernel<<<(E + 255) / 256, 256>>>(edges, E);
    scan_lookback_kernel<<<nb, SCAN_TILE>>>(N, E);
    scatter_kernel<<<(E + 255) / 256, 256>>>(edges, E);

    // join before aggregate (needs g_Ah x-part) and gemm1 (needs weights)
    cudaStreamWaitEvent(0, evJoin, 0);

    // Layer 1: agg(fp16) -> fp16 tensor-core GEMM + bias + relu (h fp16)
    dim3 aggBlock(32, 8);
    aggregate_kernel<<<(N + 7) / 8, aggBlock>>>(N);
    {
        dim3 grid((N + 127) / 128, F / 128);
        gemm1_tc_kernel<<<grid, 256, 2 * STAGE_B>>>(b1_l, b1_r, N);
    }

    // Layer 2: fp16 TC dual projection, fused aggregate+final
    gemm40_tc_kernel<<<(N + 127) / 128, 256>>>(N);
    aggregate40_final_kernel<<<(N + 31) / 32, 320>>>(b2_l, b2_r, out, N);
}

// round 15
// speedup vs baseline: 4.1103x; 1.0369x over previous
#include <cuda_runtime.h>
#include <cuda_fp16.h>
#include <cstdint>

// Problem constants (fixed by reference_code)
#define NMAX 50000
#define EMAX 800000
#define F    256
#define AK   512          // concat K for layer-1 GEMM (agg | x)
#define NCLS 40
#define N2   80           // combined layer-2 output width [w2_l | w2_r]
#define SCAN_TILE 1024
#define NBLK_MAX  64

// ---------------- scratch (static device globals; no runtime allocation) ----
__device__ int   g_is64;
__device__ int   g_deg[NMAX];
__device__ int   g_rowptr[NMAX + 1];
__device__ int   g_col[EMAX];
__device__ int   g_pos[EMAX];            // per-edge slot within dst bucket
__device__ unsigned long long g_scan_state[NBLK_MAX];  // (flag<<62)|value
__device__ int   g_scan_ticket;
__device__ float g_invdeg[NMAX];
__device__ __align__(16) __half g_Ah[(size_t)NMAX * AK];   // [agg | x] fp16
__device__ __align__(16) __half g_Bh[(size_t)F * AK];      // [w1_l | w1_r] fp16
__device__ __align__(16) __half g_Hh[(size_t)NMAX * F];    // relu(h) fp16
__device__ __align__(16) __half g_B2h[(size_t)N2 * F];     // [w2_l | w2_r] fp16
__device__ __align__(16) __half g_t[(size_t)NMAX * NCLS];  // h @ w2_l^T (fp16)
__device__ __align__(16) float g_u[(size_t)NMAX * NCLS];   // h @ w2_r^T (fp32)

// ---------------- PTX helpers ----------------------------------------------
__device__ __forceinline__ void ldsm_x4(uint32_t& r0, uint32_t& r1,
                                        uint32_t& r2, uint32_t& r3, uint32_t addr) {
    asm volatile("ldmatrix.sync.aligned.m8n8.x4.shared.b16 {%0,%1,%2,%3},[%4];"
                 : "=r"(r0), "=r"(r1), "=r"(r2), "=r"(r3) : "r"(addr));
}
__device__ __forceinline__ void ldsm_x2(uint32_t& r0, uint32_t& r1, uint32_t addr) {
    asm volatile("ldmatrix.sync.aligned.m8n8.x2.shared.b16 {%0,%1},[%2];"
                 : "=r"(r0), "=r"(r1) : "r"(addr));
}
__device__ __forceinline__ void mma_f16(float* c, const uint32_t* a, const uint32_t* b) {
    asm volatile("mma.sync.aligned.m16n8k16.row.col.f32.f16.f16.f32 "
                 "{%0,%1,%2,%3},{%4,%5,%6,%7},{%8,%9},{%0,%1,%2,%3};"
                 : "+f"(c[0]), "+f"(c[1]), "+f"(c[2]), "+f"(c[3])
                 : "r"(a[0]), "r"(a[1]), "r"(a[2]), "r"(a[3]), "r"(b[0]), "r"(b[1]));
}
__device__ __forceinline__ void cp16(uint32_t saddr, const void* gaddr, int sz) {
    asm volatile("cp.async.cg.shared.global [%0],[%1],16,%2;"
                 :: "r"(saddr), "l"(gaddr), "r"(sz));
}
__device__ __forceinline__ void cp_commit() {
    asm volatile("cp.async.commit_group;");
}
template <int N>
__device__ __forceinline__ void cp_wait() {
    asm volatile("cp.async.wait_group %0;" :: "n"(N));
}
__device__ __forceinline__ void cp_wait_all() {
    asm volatile("cp.async.commit_group;");
    asm volatile("cp.async.wait_group 0;");
}

__device__ __forceinline__ int edge_at(const void* edges, size_t idx) {
    if (g_is64) return (int)((const long long*)edges)[idx];
    return ((const int*)edges)[idx];
}

// ---------------- init: zero counters + scan state + dtype probe ------------
__global__ void init_kernel(const int* __restrict__ v, int n) {
    int i = blockIdx.x * blockDim.x + threadIdx.x;
    if (i < n) g_deg[i] = 0;
    if (blockIdx.x == 0) {
        if (threadIdx.x < NBLK_MAX) g_scan_state[threadIdx.x] = 0ULL;
        __shared__ int any_nonzero;
        if (threadIdx.x == 0) { any_nonzero = 0; g_scan_ticket = 0; }
        __syncthreads();
        if (v[2 * threadIdx.x + 1] != 0) atomicOr(&any_nonzero, 1);
        __syncthreads();
        if (threadIdx.x == 0) g_is64 = (any_nonzero == 0) ? 1 : 0;
    }
}

// ---------------- CSR build ------------------------------------------------
// degree pass also records each edge's slot within its dst bucket
__global__ void degree_kernel(const void* __restrict__ edges, int E) {
    int e = blockIdx.x * blockDim.x + threadIdx.x;
    if (e < E) {
        int d = edge_at(edges, (size_t)E + e);
        g_pos[e] = atomicAdd(&g_deg[d], 1);
    }
}
__device__ __forceinline__ int block_incl_scan(int d, int* total) {
    __shared__ int wsum[32];
    int lane = threadIdx.x & 31, wid = threadIdx.x >> 5;
    int v = d;
#pragma unroll
    for (int o = 1; o < 32; o <<= 1) {
        int t = __shfl_up_sync(0xffffffffu, v, o);
        if (lane >= o) v += t;
    }
    if (lane == 31) wsum[wid] = v;
    __syncthreads();
    if (wid == 0) {
        int w = wsum[lane];
#pragma unroll
        for (int o = 1; o < 32; o <<= 1) {
            int t = __shfl_up_sync(0xffffffffu, w, o);
            if (lane >= o) w += t;
        }
        wsum[lane] = w;
    }
    __syncthreads();
    int incl = v + (wid > 0 ? wsum[wid - 1] : 0);
    *total = wsum[31];
    __syncthreads();
    return incl;
}

// single-pass decoupled-lookback scan: g_deg -> g_rowptr (+invdeg, rowptr[n])
__global__ void scan_lookback_kernel(int n, int E) {
    __shared__ int s_bid;
    __shared__ int s_prefix;
    if (threadIdx.x == 0) s_bid = atomicAdd(&g_scan_ticket, 1);
    __syncthreads();
    int bid = s_bid;
    int i = bid * SCAN_TILE + threadIdx.x;
    int d = (i < n) ? g_deg[i] : 0;
    int total;
    int incl = block_incl_scan(d, &total);
    if (threadIdx.x == 0) {
        if (bid == 0) {
            atomicExch(&g_scan_state[0], (2ULL << 62) | (unsigned)total);
            s_prefix = 0;
        } else {
            atomicExch(&g_scan_state[bid], (1ULL << 62) | (unsigned)total);
            int prefix = 0;
            int j = bid - 1;
            while (j >= 0) {
                unsigned long long st = atomicAdd(&g_scan_state[j], 0ULL);
                unsigned long long flag = st >> 62;
                if (flag == 2) { prefix += (int)(st & 0xFFFFFFFFu); break; }
                if (flag == 1) { prefix += (int)(st & 0xFFFFFFFFu); j--; }
            }
            atomicExch(&g_scan_state[bid], (2ULL << 62) | (unsigned)(prefix + total));
            s_prefix = prefix;
        }
    }
    __syncthreads();
    if (i < n) {
        g_rowptr[i] = s_prefix + incl - d;
        g_invdeg[i] = 1.0f / (float)(d > 0 ? d : 1);
        if (i == n - 1) g_rowptr[n] = E;
    }
}

// scatter without atomics: slot precomputed in degree pass
__global__ void scatter_kernel(const void* __restrict__ edges, int E) {
    int e = blockIdx.x * blockDim.x + threadIdx.x;
    if (e < E) {
        int srcv = edge_at(edges, e);
        int d    = edge_at(edges, (size_t)E + e);
        g_col[g_rowptr[d] + g_pos[e]] = srcv;
    }
}

// ---------------- merged weight conversions (fp16) ---------------------------
#define W1_Q (F * (F / 4))          // 16384 float4s
#define W2_Q (N2 * (F / 4))         // 5120 float4s
__device__ __forceinline__ uint2 to_h4(float4 v) {
    __half2 h0 = __floats2half2_rn(v.x, v.y);
    __half2 h1 = __floats2half2_rn(v.z, v.w);
    return make_uint2(*(const uint32_t*)&h0, *(const uint32_t*)&h1);
}
__global__ void convert_weights_kernel(const float* __restrict__ w1_l,
                                       const float* __restrict__ w1_r,
                                       const float* __restrict__ w2_l,
                                       const float* __restrict__ w2_r) {
    int idx = blockIdx.x * blockDim.x + threadIdx.x;
    if (idx < W1_Q) {
        int row = idx / (F / 4), c4 = idx % (F / 4);
        float4 vl = *(const float4*)&w1_l[(size_t)row * F + c4 * 4];
        float4 vr = *(const float4*)&w1_r[(size_t)row * F + c4 * 4];
        size_t o = (size_t)row * AK + c4 * 4;
        *(uint2*)&g_Bh[o]     = to_h4(vl);
        *(uint2*)&g_Bh[o + F] = to_h4(vr);
    } else if (idx < W1_Q + W2_Q) {
        int j = idx - W1_Q;
        int row = j / (F / 4), c4 = j % (F / 4);
        const float* src = (row < NCLS) ? &w2_l[(size_t)row * F + c4 * 4]
                                        : &w2_r[(size_t)(row - NCLS) * F + c4 * 4];
        *(uint2*)&g_B2h[(size_t)row * F + c4 * 4] = to_h4(*(const float4*)src);
    }
}

// ---------------- x conversion: fp16 into A cols [256,512) ------------------
__global__ void convert_x_kernel(const float* __restrict__ x, int n) {
    int idx = blockIdx.x * blockDim.x + threadIdx.x;
    if (idx >= n * (F / 4)) return;
    int row = idx / (F / 4), c4 = idx % (F / 4);
    float4 v = *(const float4*)&x[(size_t)row * F + c4 * 4];
    *(uint2*)&g_Ah[(size_t)row * AK + F + c4 * 4] = to_h4(v);
}

// ---------------- mean aggregation (256-dim) from fp16 x-part ---------------
__global__ void aggregate_kernel(int n) {
    int node = blockIdx.x * blockDim.y + threadIdx.y;
    if (node >= n) return;
    int lane = threadIdx.x;
    int beg = g_rowptr[node], end = g_rowptr[node + 1];
    const uint4* xh = (const uint4*)g_Ah;   // row stride = 64 uint4; x-part +32
    float acc[8];
#pragma unroll
    for (int i = 0; i < 8; i++) acc[i] = 0.f;
    int e = beg;
    for (; e + 2 <= end; e += 2) {
        uint4 p0 = xh[(size_t)g_col[e] * 64 + 32 + lane];
        uint4 p1 = xh[(size_t)g_col[e + 1] * 64 + 32 + lane];
        const __half2* q0 = (const __half2*)&p0;
        const __half2* q1 = (const __half2*)&p1;
#pragma unroll
        for (int j = 0; j < 4; j++) {
            float2 f0 = __half22float2(q0[j]);
            float2 f1 = __half22float2(q1[j]);
            acc[j * 2]     += f0.x + f1.x;
            acc[j * 2 + 1] += f0.y + f1.y;
        }
    }
    if (e < end) {
        uint4 p0 = xh[(size_t)g_col[e] * 64 + 32 + lane];
        const __half2* q0 = (const __half2*)&p0;
#pragma unroll
        for (int j = 0; j < 4; j++) {
            float2 f0 = __half22float2(q0[j]);
            acc[j * 2]     += f0.x;
            acc[j * 2 + 1] += f0.y;
        }
    }
    float s = g_invdeg[node];
    uint4 o;
    __half2 h0 = __floats2half2_rn(acc[0] * s, acc[1] * s);
    __half2 h1 = __floats2half2_rn(acc[2] * s, acc[3] * s);
    __half2 h2 = __floats2half2_rn(acc[4] * s, acc[5] * s);
    __half2 h3 = __floats2half2_rn(acc[6] * s, acc[7] * s);
    o.x = *(const uint32_t*)&h0; o.y = *(const uint32_t*)&h1;
    o.z = *(const uint32_t*)&h2; o.w = *(const uint32_t*)&h3;
    *(uint4*)&g_Ah[(size_t)node * AK + lane * 8] = o;
}

// ---------------- GEMM1 (fp16 tensor cores, single pass, 2-stage pipeline) --
#define TSTRIDE 40      // halfs per smem row (80B) -> conflict-free ldsm
#define TILE_B  (128 * TSTRIDE * 2)   // bytes per tile = 10240
#define STAGE_B (2 * TILE_B)          // A + B tiles = 20480
extern __shared__ __align__(16) __half g1_smem[];
__global__ __launch_bounds__(256) void gemm1_tc_kernel(const float* __restrict__ bias0,
                                                       const float* __restrict__ bias1,
                                                       int M) {
    const uint32_t sb0 = (uint32_t)__cvta_generic_to_shared(g1_smem);
    int bm = blockIdx.x * 128, bn = blockIdx.y * 128;
    int tid = threadIdx.x, wid = tid >> 5, lane = tid & 31;
    int wm = (wid >> 2) * 64, wn = (wid & 3) * 32;

    float acc[4][4][4];
#pragma unroll
    for (int mf = 0; mf < 4; mf++)
#pragma unroll
        for (int nf = 0; nf < 4; nf++)
#pragma unroll
            for (int r = 0; r < 4; r++) acc[mf][nf][r] = 0.f;

    auto load_chunk = [&](int kc, int stage) {
        int k0 = kc * 32;
        uint32_t sbase = sb0 + stage * STAGE_B;
#pragma unroll
        for (int i = 0; i < 4; i++) {
            int idx = tid + i * 256;
            int t   = idx >> 9;          // 0 = A, 1 = B
            int rem = idx & 511;
            int row = rem >> 2, ch = rem & 3;
            uint32_t sa = sbase + t * TILE_B + row * 80 + ch * 16;
            if (t == 0) {
                int grow = bm + row;
                int gr = grow < M ? grow : (M - 1);
                cp16(sa, g_Ah + (size_t)gr * AK + k0 + ch * 8, grow < M ? 16 : 0);
            } else {
                cp16(sa, g_Bh + (size_t)(bn + row) * AK + k0 + ch * 8, 16);
            }
        }
        cp_commit();
    };

    load_chunk(0, 0);
#pragma unroll 1
    for (int kc = 0; kc < 16; kc++) {
        int stage = kc & 1;
        if (kc + 1 < 16) {
            load_chunk(kc + 1, stage ^ 1);
            cp_wait<1>();
        } else {
            cp_wait<0>();
        }
        __syncthreads();
        uint32_t sb = sb0 + stage * STAGE_B;
#pragma unroll
        for (int ks = 0; ks < 32; ks += 16) {
            uint32_t a[4][4], b[4][2];
            int akb = (ks + ((lane >> 4) << 3)) * 2;
#pragma unroll
            for (int mf = 0; mf < 4; mf++) {
                int row = wm + mf * 16 + (lane & 15);
                ldsm_x4(a[mf][0], a[mf][1], a[mf][2], a[mf][3],
                        sb + row * 80 + akb);
            }
            int brow0 = wn + ((lane >> 4) << 3) + (lane & 7);
            int bkb = (ks + (((lane >> 3) & 1) << 3)) * 2;
#pragma unroll
            for (int nf2 = 0; nf2 < 2; nf2++) {
                int row = brow0 + nf2 * 16;
                uint32_t r0, r1, r2, r3;
                ldsm_x4(r0, r1, r2, r3, sb + TILE_B + row * 80 + bkb);
                b[nf2 * 2][0] = r0; b[nf2 * 2][1] = r1;
                b[nf2 * 2 + 1][0] = r2; b[nf2 * 2 + 1][1] = r3;
            }
#pragma unroll
            for (int mf = 0; mf < 4; mf++)
#pragma unroll
                for (int nf = 0; nf < 4; nf++)
                    mma_f16(acc[mf][nf], a[mf], b[nf]);
        }
        __syncthreads();
    }
#pragma unroll
    for (int nf = 0; nf < 4; nf++) {
        int c = bn + wn + nf * 8 + 2 * (lane & 3);
        float bb0 = bias0[c] + bias1[c];
        float bb1 = bias0[c + 1] + bias1[c + 1];
#pragma unroll
        for (int mf = 0; mf < 4; mf++) {
            int r0 = bm + wm + mf * 16 + (lane >> 2);
            int r1 = r0 + 8;
            if (r0 < M) {
                *(__half2*)&g_Hh[(size_t)r0 * F + c] =
                    __floats2half2_rn(fmaxf(acc[mf][nf][0] + bb0, 0.f),
                                      fmaxf(acc[mf][nf][1] + bb1, 0.f));
            }
            if (r1 < M) {
                *(__half2*)&g_Hh[(size_t)r1 * F + c] =
                    __floats2half2_rn(fmaxf(acc[mf][nf][2] + bb0, 0.f),
                                      fmaxf(acc[mf][nf][3] + bb1, 0.f));
            }
        }
    }
}

// ---------------- GEMM40 (fp16 TC): g_t (fp16) | g_u (fp32) = h @ B2^T ------
#define A2_B (128 * 80)
#define B2_B (80 * 80)
__global__ __launch_bounds__(256) void gemm40_tc_kernel(int M) {
    __shared__ __align__(16) __half smem[(A2_B + B2_B) / 2];
    const uint32_t sb = (uint32_t)__cvta_generic_to_shared(smem);
    int bm = blockIdx.x * 128;
    int tid = threadIdx.x, wid = tid >> 5, lane = tid & 31;
    int wm = (wid & 3) * 32, wn = (wid >> 2) * 40;

    float acc[2][5][4];
#pragma unroll
    for (int mf = 0; mf < 2; mf++)
#pragma unroll
        for (int nf = 0; nf < 5; nf++)
#pragma unroll
            for (int r = 0; r < 4; r++) acc[mf][nf][r] = 0.f;

#pragma unroll 1
    for (int kc = 0; kc < 8; kc++) {
        int k0 = kc * 32;
        for (int idx = tid; idx < 832; idx += 256) {
            if (idx < 512) {
                int row = idx >> 2, ch = idx & 3;
                int grow = bm + row;
                int gr = grow < M ? grow : (M - 1);
                cp16(sb + row * 80 + ch * 16,
                     g_Hh + (size_t)gr * F + k0 + ch * 8, grow < M ? 16 : 0);
            } else {
                int j = idx - 512;
                int row = j >> 2, ch = j & 3;
                cp16(sb + A2_B + row * 80 + ch * 16,
                     g_B2h + (size_t)row * F + k0 + ch * 8, 16);
            }
        }
        cp_wait_all();
        __syncthreads();
#pragma unroll
        for (int ks = 0; ks < 32; ks += 16) {
            uint32_t a[2][4], b[5][2];
            int akb = (ks + ((lane >> 4) << 3)) * 2;
#pragma unroll
            for (int mf = 0; mf < 2; mf++) {
                int row = wm + mf * 16 + (lane & 15);
                ldsm_x4(a[mf][0], a[mf][1], a[mf][2], a[mf][3],
                        sb + row * 80 + akb);
            }
            int bkb = (ks + (((lane >> 3) & 1) << 3)) * 2;
            int brow0 = wn + ((lane >> 4) << 3) + (lane & 7);
#pragma unroll
            for (int nf2 = 0; nf2 < 2; nf2++) {
                int row = brow0 + nf2 * 16;
                uint32_t r0, r1, r2, r3;
                ldsm_x4(r0, r1, r2, r3, sb + A2_B + row * 80 + bkb);
                b[nf2 * 2][0] = r0; b[nf2 * 2][1] = r1;
                b[nf2 * 2 + 1][0] = r2; b[nf2 * 2 + 1][1] = r3;
            }
            {
                int row = wn + 32 + (lane & 7);
                ldsm_x2(b[4][0], b[4][1], sb + A2_B + row * 80 + bkb);
            }
#pragma unroll
            for (int mf = 0; mf < 2; mf++)
#pragma unroll
                for (int nf = 0; nf < 5; nf++)
                    mma_f16(acc[mf][nf], a[mf], b[nf]);
        }
        __syncthreads();
    }
    bool is_u = (wid >> 2) != 0;
#pragma unroll
    for (int nf = 0; nf < 5; nf++) {
        int c = (wn % 40) + nf * 8 + 2 * (lane & 3);
#pragma unroll
        for (int mf = 0; mf < 2; mf++) {
            int r0 = bm + wm + mf * 16 + (lane >> 2);
            int r1 = r0 + 8;
            if (is_u) {
                if (r0 < M) {
                    g_u[(size_t)r0 * NCLS + c]     = acc[mf][nf][0];
                    g_u[(size_t)r0 * NCLS + c + 1] = acc[mf][nf][1];
                }
                if (r1 < M) {
                    g_u[(size_t)r1 * NCLS + c]     = acc[mf][nf][2];
                    g_u[(size_t)r1 * NCLS + c + 1] = acc[mf][nf][3];
                }
            } else {
                if (r0 < M)
                    *(__half2*)&g_t[(size_t)r0 * NCLS + c] =
                        __floats2half2_rn(acc[mf][nf][0], acc[mf][nf][1]);
                if (r1 < M)
                    *(__half2*)&g_t[(size_t)r1 * NCLS + c] =
                        __floats2half2_rn(acc[mf][nf][2], acc[mf][nf][3]);
            }
        }
    }
}

// ---------------- mean aggregation (40-dim, fp16 t) + fused final -----------
// 10 threads per node, each owns 4 cols (one uint2 = 4 halfs per edge)
__global__ void aggregate40_final_kernel(const float* __restrict__ b0,
                                         const float* __restrict__ b1,
                                         float* __restrict__ out, int n) {
    int tid = threadIdx.x;
    int node = blockIdx.x * 32 + tid / 10;
    int c4 = tid % 10;
    if (node >= n) return;
    int beg = g_rowptr[node], end = g_rowptr[node + 1];
    float4 acc = make_float4(0.f, 0.f, 0.f, 0.f);
    int e = beg;
    for (; e + 4 <= end; e += 4) {
        int c0 = g_col[e], c1 = g_col[e + 1], c2 = g_col[e + 2], c3 = g_col[e + 3];
        uint2 p0 = *(const uint2*)&g_t[(size_t)c0 * NCLS + c4 * 4];
        uint2 p1 = *(const uint2*)&g_t[(size_t)c1 * NCLS + c4 * 4];
        uint2 p2 = *(const uint2*)&g_t[(size_t)c2 * NCLS + c4 * 4];
        uint2 p3 = *(const uint2*)&g_t[(size_t)c3 * NCLS + c4 * 4];
        float2 a0 = __half22float2(*(const __half2*)&p0.x);
        float2 b0v = __half22float2(*(const __half2*)&p0.y);
        float2 a1 = __half22float2(*(const __half2*)&p1.x);
        float2 b1v = __half22float2(*(const __half2*)&p1.y);
        float2 a2 = __half22float2(*(const __half2*)&p2.x);
        float2 b2v = __half22float2(*(const __half2*)&p2.y);
        float2 a3 = __half22float2(*(const __half2*)&p3.x);
        float2 b3v = __half22float2(*(const __half2*)&p3.y);
        acc.x += (a0.x + a1.x) + (a2.x + a3.x);
        acc.y += (a0.y + a1.y) + (a2.y + a3.y);
        acc.z += (b0v.x + b1v.x) + (b2v.x + b3v.x);
        acc.w += (b0v.y + b1v.y) + (b2v.y + b3v.y);
    }
    for (; e < end; e++) {
        uint2 p = *(const uint2*)&g_t[(size_t)g_col[e] * NCLS + c4 * 4];
        float2 a = __half22float2(*(const __half2*)&p.x);
        float2 b = __half22float2(*(const __half2*)&p.y);
        acc.x += a.x; acc.y += a.y; acc.z += b.x; acc.w += b.y;
    }
    float s = g_invdeg[node];
    float4 u  = *(const float4*)&g_u[(size_t)node * NCLS + c4 * 4];
    float4 v0 = *(const float4*)&b0[c4 * 4];
    float4 v1 = *(const float4*)&b1[c4 * 4];
    *(float4*)&out[(size_t)node * NCLS + c4 * 4] =
        make_float4(acc.x * s + u.x + v0.x + v1.x,
                    acc.y * s + u.y + v0.y + v1.y,
                    acc.z * s + u.z + v0.z + v1.z,
                    acc.w * s + u.w + v0.w + v1.w);
}

// ---------------- launch --------------------------------------------------
extern "C" void kernel_launch(void* const* d_in, const int* in_sizes, int n_in,
                              void* d_out, int out_size) {
    const float* x     = (const float*)d_in[0];
    const void*  edges = (const void*)d_in[1];
    const float* w1_l = (const float*)d_in[2];
    const float* b1_l = (const float*)d_in[3];
    const float* w1_r = (const float*)d_in[4];
    const float* b1_r = (const float*)d_in[5];
    const float* w2_l = (const float*)d_in[6];
    const float* b2_l = (const float*)d_in[7];
    const float* w2_r = (const float*)d_in[8];
    const float* b2_r = (const float*)d_in[9];
    float* out = (float*)d_out;

    int N = in_sizes[0] / F;
    int E = in_sizes[1] / 2;
    int nb = (N + SCAN_TILE - 1) / SCAN_TILE;

    // one-time resources (created on the uncaptured correctness call)
    static cudaStream_t s2 = nullptr;
    static cudaEvent_t evFork = nullptr, evJoin = nullptr;
    static int once = 0;
    if (!once) {
        cudaStreamCreateWithFlags(&s2, cudaStreamNonBlocking);
        cudaEventCreateWithFlags(&evFork, cudaEventDisableTiming);
        cudaEventCreateWithFlags(&evJoin, cudaEventDisableTiming);
        cudaFuncSetAttribute(gemm1_tc_kernel,
                             cudaFuncAttributeMaxDynamicSharedMemorySize,
                             2 * STAGE_B);
        once = 1;
    }

    // fork: converts on s2, CSR chain on main stream
    cudaEventRecord(evFork, 0);
    cudaStreamWaitEvent(s2, evFork, 0);
    convert_weights_kernel<<<(W1_Q + W2_Q + 255) / 256, 256, 0, s2>>>(w1_l, w1_r,
                                                                     w2_l, w2_r);
    convert_x_kernel<<<(N * (F / 4) + 255) / 256, 256, 0, s2>>>(x, N);
    cudaEventRecord(evJoin, s2);

    init_kernel<<<(N + 255) / 256, 256>>>((const int*)edges, N);
    degree_kernel<<<(E + 255) / 256, 256>>>(edges, E);
    scan_lookback_kernel<<<nb, SCAN_TILE>>>(N, E);
    scatter_kernel<<<(E + 255) / 256, 256>>>(edges, E);

    // join before aggregate (needs g_Ah x-part) and gemm1 (needs weights)
    cudaStreamWaitEvent(0, evJoin, 0);

    // Layer 1: agg(fp16) -> fp16 tensor-core GEMM + bias + relu (h fp16)
    dim3 aggBlock(32, 8);
    aggregate_kernel<<<(N + 7) / 8, aggBlock>>>(N);
    {
        dim3 grid((N + 127) / 128, F / 128);
        gemm1_tc_kernel<<<grid, 256, 2 * STAGE_B>>>(b1_l, b1_r, N);
    }

    // Layer 2: fp16 TC dual projection, fused aggregate+final
    gemm40_tc_kernel<<<(N + 127) / 128, 256>>>(N);
    aggregate40_final_kernel<<<(N + 31) / 32, 320>>>(b2_l, b2_r, out, N);
}